// round 10
// baseline (speedup 1.0000x reference)
#include <cuda_runtime.h>
#include <cuda_bf16.h>
#include <math.h>
#include <stdint.h>

// ---------------- problem constants ----------------
#define TT    2080
#define DM    512
#define NH    8
#define DH    64
#define DI    2048
#define NLAY  4
#define NMTOK 16
#define QL    2048

// ---------------- fp32 scratch ----------------
__device__ float g_w[TT * DM];
__device__ float g_heads[TT * 3 * DM];
__device__ float g_r[TT * DM];
__device__ float g_tmp[TT * DM];
__device__ float g_tmp2[TT * DM];

// ---------------- bf16 hi/lo pair-plane scratch (word = bf16x2 {even k, odd k}) ----------------
__device__ uint32_t wPh[TT * 256],   wPl[TT * 256];      // w        [row][DM/2]
__device__ uint32_t posPh[TT * 256], posPl[TT * 256];    // pos_emb
__device__ uint32_t avPh[TT * 256],  avPl[TT * 256];     // attn out
__device__ uint32_t ff1Ph[TT * 1024], ff1Pl[TT * 1024];  // ffn hidden
// weights: [l][n][K/2]
__device__ uint32_t qkvPh[NLAY * 1536 * 256], qkvPl[NLAY * 1536 * 256];
__device__ uint32_t wrPh[NLAY * 512 * 256],   wrPl[NLAY * 512 * 256];
__device__ uint32_t woPh[NLAY * 512 * 256],   woPl[NLAY * 512 * 256];
__device__ uint32_t w1Ph[NLAY * 2048 * 256],  w1Pl[NLAY * 2048 * 256];
__device__ uint32_t w2Ph[NLAY * 512 * 1024],  w2Pl[NLAY * 512 * 1024];

// ---------------- bf16x3 helpers ----------------
__device__ __forceinline__ void split2(float x0, float x1, uint32_t& hw, uint32_t& lw) {
    __nv_bfloat162 h, l;
    h.x = __float2bfloat16(x0);
    h.y = __float2bfloat16(x1);
    l.x = __float2bfloat16(x0 - __bfloat162float(h.x));
    l.y = __float2bfloat16(x1 - __bfloat162float(h.y));
    hw = *reinterpret_cast<uint32_t*>(&h);
    lw = *reinterpret_cast<uint32_t*>(&l);
}

__device__ __forceinline__ void mma16(float (&c)[4], const uint32_t (&a)[4],
                                      uint32_t b0, uint32_t b1) {
    asm volatile(
        "mma.sync.aligned.m16n8k16.row.col.f32.bf16.bf16.f32 "
        "{%0,%1,%2,%3}, {%4,%5,%6,%7}, {%8,%9}, {%0,%1,%2,%3};"
        : "+f"(c[0]), "+f"(c[1]), "+f"(c[2]), "+f"(c[3])
        : "r"(a[0]), "r"(a[1]), "r"(a[2]), "r"(a[3]), "r"(b0), "r"(b1));
}

__device__ __forceinline__ uint32_t sm_u32(const void* p) {
    return (uint32_t)__cvta_generic_to_shared(p);
}

__device__ __forceinline__ void ldsm4(uint32_t (&r)[4], uint32_t a) {
    asm volatile("ldmatrix.sync.aligned.m8n8.x4.shared.b16 {%0,%1,%2,%3}, [%4];"
                 : "=r"(r[0]), "=r"(r[1]), "=r"(r[2]), "=r"(r[3]) : "r"(a));
}

// B-style pair-plane smem layout: word index for row n = n*36 + (n>>3)*4 (+ kpair)
__device__ __forceinline__ int boff(int n) { return n * 36 + ((n >> 3) << 2); }
#define BPLANE (64 * 36 + 32)

// ---------------- prep kernels (emit planes) ----------------
__global__ void build_w_kernel(const float* __restrict__ word_emb,
                               const float* __restrict__ mem) {
    int idx = blockIdx.x * blockDim.x + threadIdx.x;
    if (idx >= TT * 256) return;
    int row = idx >> 8, c2 = idx & 255;
    int c = 2 * c2;
    float v0, v1;
    if (row < NMTOK) {
        v0 = mem[row * DM + c]; v1 = mem[row * DM + c + 1];
    } else if (row < NMTOK + QL) {
        v0 = word_emb[(row - NMTOK) * DM + c]; v1 = word_emb[(row - NMTOK) * DM + c + 1];
    } else {
        v0 = mem[(row - NMTOK - QL) * DM + c]; v1 = mem[(row - NMTOK - QL) * DM + c + 1];
    }
    g_w[row * DM + c] = v0;
    g_w[row * DM + c + 1] = v1;
    uint32_t hw, lw;
    split2(v0, v1, hw, lw);
    wPh[idx] = hw; wPl[idx] = lw;
}

__global__ void build_pos_kernel() {
    int idx = blockIdx.x * blockDim.x + threadIdx.x;
    if (idx >= TT * 256) return;
    int row = idx >> 8, c2 = idx & 255;
    float v0, v1;
    #pragma unroll
    for (int u = 0; u < 2; u++) {
        int c = 2 * c2 + u;
        int f = (c < DM / 2) ? c : (c - DM / 2);
        double invf = exp(-((double)(2 * f) / (double)DM) * log(10000.0));
        double val = (double)(TT - 1 - row) * invf;
        float r = (float)((c < DM / 2) ? sin(val) : cos(val));
        if (u == 0) v0 = r; else v1 = r;
    }
    uint32_t hw, lw;
    split2(v0, v1, hw, lw);
    posPh[idx] = hw; posPl[idx] = lw;
}

// ---------------- weight convert: W[l][K][N] fp32 -> planes [l][N][K/2] ----------------
__global__ void convert_weight(const float* __restrict__ W,
                               uint32_t* __restrict__ Ph, uint32_t* __restrict__ Pl,
                               int K, int N) {
    __shared__ float S[64][33];
    const int l = blockIdx.z;
    const float* Wl = W + (size_t)l * K * N;
    const int Kw = K >> 1;
    uint32_t* PhL = Ph + (size_t)l * N * Kw;
    uint32_t* PlL = Pl + (size_t)l * N * Kw;
    const int n0 = blockIdx.x * 32, k0 = blockIdx.y * 64;
    const int t = threadIdx.x;
    {
        int n = t & 31, kk = t >> 5;
        #pragma unroll
        for (int i = 0; i < 8; i++)
            S[kk + 8 * i][n] = Wl[(size_t)(k0 + kk + 8 * i) * N + n0 + n];
    }
    __syncthreads();
    {
        int nn = t >> 3, kq = t & 7;
        uint32_t oh[4], ol[4];
        #pragma unroll
        for (int i = 0; i < 4; i++) {
            int kp = kq * 4 + i;
            split2(S[2 * kp][nn], S[2 * kp + 1][nn], oh[i], ol[i]);
        }
        size_t base = (size_t)(n0 + nn) * Kw + (k0 >> 1) + kq * 4;
        *reinterpret_cast<uint4*>(PhL + base) = *reinterpret_cast<uint4*>(oh);
        *reinterpret_cast<uint4*>(PlL + base) = *reinterpret_cast<uint4*>(ol);
    }
}

// ---------------- GEMM: planes in, fp32 or planes out ----------------
#define PPA 20
#define ABUF (128 * PPA)
#define GEMM_SMEM ((4 * ABUF + 4 * BPLANE) * 4)

__global__ __launch_bounds__(256, 2)
void mma_gemm(const uint32_t* __restrict__ Ahg, const uint32_t* __restrict__ Alg, int ldaw,
              const uint32_t* __restrict__ Bhg, const uint32_t* __restrict__ Blg, int ldbw,
              float* __restrict__ C, float* __restrict__ C2,
              uint32_t* __restrict__ OutH, uint32_t* __restrict__ OutL, int ldc,
              const float* __restrict__ cbias, int doRelu,
              int M, int N, int Ksub) {
    extern __shared__ uint32_t gsm[];
    uint32_t* Ah = gsm;
    uint32_t* Al = Ah + 2 * ABUF;
    uint32_t* Bh = Al + 2 * ABUF;
    uint32_t* Bl = Bh + 2 * BPLANE;

    const int bm = blockIdx.y * 128, bn = blockIdx.x * 64;
    const int kOffW = blockIdx.z * (Ksub >> 1);
    if (blockIdx.z == 1) C = C2;

    const int tid = threadIdx.x;
    const int lane = tid & 31, warp = tid >> 5;
    const int wm = warp & 3, wn = warp >> 2;
    const int g4 = lane >> 2, l4 = lane & 3;

    float acc[2][4][4] = {};
    uint4 pah[2], pal[2], pbh, pbl;

    const int arow = tid >> 2;     // 0..63 (A rows, also B n-rows)
    const int akq = tid & 3;       // uint4 group (4 kpairs)

    const int aRow = lane & 15;
    const uint32_t aHiB = ((lane >> 4) & 1) * 16;
    const uint32_t adAh = sm_u32(Ah) + (uint32_t)((wm * 32 + aRow) * PPA) * 4 + aHiB;
    const uint32_t adAl = sm_u32(Al) + (uint32_t)((wm * 32 + aRow) * PPA) * 4 + aHiB;
    const int bRowN = ((lane >> 4) & 1) * 8 + (lane & 7);
    const uint32_t bHiB = ((lane >> 3) & 1) * 16;
    const uint32_t adBh0 = sm_u32(Bh) + (uint32_t)boff(wn * 32 + bRowN) * 4 + bHiB;
    const uint32_t adBh1 = sm_u32(Bh) + (uint32_t)boff(wn * 32 + 16 + bRowN) * 4 + bHiB;
    const uint32_t adBl0 = sm_u32(Bl) + (uint32_t)boff(wn * 32 + bRowN) * 4 + bHiB;
    const uint32_t adBl1 = sm_u32(Bl) + (uint32_t)boff(wn * 32 + 16 + bRowN) * 4 + bHiB;

    auto loadAB = [&](int k0) {
        const int kw = kOffW + (k0 >> 1) + akq * 4;
        #pragma unroll
        for (int p = 0; p < 2; p++) {
            int row = bm + p * 64 + arow;
            if (row < M) {
                pah[p] = *reinterpret_cast<const uint4*>(Ahg + (size_t)row * ldaw + kw);
                pal[p] = *reinterpret_cast<const uint4*>(Alg + (size_t)row * ldaw + kw);
            } else {
                pah[p] = make_uint4(0, 0, 0, 0);
                pal[p] = make_uint4(0, 0, 0, 0);
            }
        }
        pbh = *reinterpret_cast<const uint4*>(Bhg + (size_t)(bn + arow) * ldbw + kw);
        pbl = *reinterpret_cast<const uint4*>(Blg + (size_t)(bn + arow) * ldbw + kw);
    };
    auto storeAB = [&](int s) {
        uint32_t* AhS = Ah + s * ABUF;
        uint32_t* AlS = Al + s * ABUF;
        uint32_t* BhS = Bh + s * BPLANE;
        uint32_t* BlS = Bl + s * BPLANE;
        #pragma unroll
        for (int p = 0; p < 2; p++) {
            int wi = (p * 64 + arow) * PPA + akq * 4;
            *reinterpret_cast<uint4*>(AhS + wi) = pah[p];
            *reinterpret_cast<uint4*>(AlS + wi) = pal[p];
        }
        int wi = boff(arow) + akq * 4;
        *reinterpret_cast<uint4*>(BhS + wi) = pbh;
        *reinterpret_cast<uint4*>(BlS + wi) = pbl;
    };

    loadAB(0);
    storeAB(0);
    __syncthreads();

    int s = 0;
    for (int k0 = 0; k0 < Ksub; k0 += 32) {
        const bool more = (k0 + 32 < Ksub);
        if (more) loadAB(k0 + 32);

        const uint32_t aOffB = (uint32_t)s * (ABUF * 4);
        const uint32_t bOffB = (uint32_t)s * (BPLANE * 4);
        #pragma unroll
        for (int ks = 0; ks < 2; ks++) {
            uint32_t ahh[2][4], alo[2][4];
            ldsm4(ahh[0], adAh + aOffB + ks * 32);
            ldsm4(ahh[1], adAh + aOffB + 16 * PPA * 4 + ks * 32);
            ldsm4(alo[0], adAl + aOffB + ks * 32);
            ldsm4(alo[1], adAl + aOffB + 16 * PPA * 4 + ks * 32);
            uint32_t bhh[2][4], blo[2][4];
            ldsm4(bhh[0], adBh0 + bOffB + ks * 32);
            ldsm4(bhh[1], adBh1 + bOffB + ks * 32);
            ldsm4(blo[0], adBl0 + bOffB + ks * 32);
            ldsm4(blo[1], adBl1 + bOffB + ks * 32);
            #pragma unroll
            for (int am = 0; am < 2; am++)
                #pragma unroll
                for (int an = 0; an < 4; an++) {
                    const int g = an >> 1, x = (an & 1) * 2;
                    mma16(acc[am][an], ahh[am], bhh[g][x], bhh[g][x + 1]);
                    mma16(acc[am][an], ahh[am], blo[g][x], blo[g][x + 1]);
                    mma16(acc[am][an], alo[am], bhh[g][x], bhh[g][x + 1]);
                }
        }
        if (more) storeAB(s ^ 1);
        __syncthreads();
        s ^= 1;
    }

    const bool planes = (OutH != nullptr);
    #pragma unroll
    for (int am = 0; am < 2; am++) {
        int row0 = bm + wm * 32 + am * 16 + g4;
        #pragma unroll
        for (int an = 0; an < 4; an++) {
            int col0 = bn + wn * 32 + an * 8 + 2 * l4;
            float v0 = acc[am][an][0], v1 = acc[am][an][1];
            float v2 = acc[am][an][2], v3 = acc[am][an][3];
            if (cbias && blockIdx.z == 0) {
                float b0 = cbias[col0], b1 = cbias[col0 + 1];
                v0 += b0; v1 += b1; v2 += b0; v3 += b1;
            }
            if (doRelu) {
                v0 = fmaxf(v0, 0.f); v1 = fmaxf(v1, 0.f);
                v2 = fmaxf(v2, 0.f); v3 = fmaxf(v3, 0.f);
            }
            if (planes) {
                uint32_t hw, lw;
                if (row0 < M) {
                    split2(v0, v1, hw, lw);
                    OutH[(size_t)row0 * ldc + (col0 >> 1)] = hw;
                    OutL[(size_t)row0 * ldc + (col0 >> 1)] = lw;
                }
                if (row0 + 8 < M) {
                    split2(v2, v3, hw, lw);
                    OutH[(size_t)(row0 + 8) * ldc + (col0 >> 1)] = hw;
                    OutL[(size_t)(row0 + 8) * ldc + (col0 >> 1)] = lw;
                }
            } else {
                if (row0 < M) {
                    C[(size_t)row0 * ldc + col0]     = v0;
                    C[(size_t)row0 * ldc + col0 + 1] = v1;
                }
                if (row0 + 8 < M) {
                    C[(size_t)(row0 + 8) * ldc + col0]     = v2;
                    C[(size_t)(row0 + 8) * ldc + col0 + 1] = v3;
                }
            }
        }
    }
}

// ---------------- fused flash-style relative attention (unchanged core; plane epilogue) ----------------
#define RPAD 68
#define RSLOT (64 * RPAD)
#define ATTN_WORDS (12 * BPLANE + 3 * RSLOT + 256)
#define ATTN_SMEM (ATTN_WORDS * 4)

__global__ __launch_bounds__(256, 1)
void fused_attn_kernel(const float* __restrict__ heads,
                       const float* __restrict__ rbuf,
                       const float* __restrict__ rwb,
                       const float* __restrict__ rrb) {
    extern __shared__ uint32_t smu[];
    uint32_t* Qwh = smu;
    uint32_t* Qwl = Qwh + BPLANE;
    uint32_t* Qrh = Qwl + BPLANE;
    uint32_t* Qrl = Qrh + BPLANE;
    uint32_t* Kh  = Qrl + BPLANE;
    uint32_t* Kl  = Kh  + BPLANE;
    uint32_t* Rh  = Kl  + BPLANE;
    uint32_t* Rl  = Rh  + BPLANE;
    uint32_t* Vth = Rl  + BPLANE;
    uint32_t* Vtl = Vth + BPLANE;
    uint32_t* Ph  = Vtl + BPLANE;
    uint32_t* Pl  = Ph  + BPLANE;
    float* Ring = (float*)(Pl + BPLANE);
    float* redm = Ring + 3 * RSLOT;
    float* reds = redm + 128;

    const int h = blockIdx.x;
    const int p = blockIdx.y;
    const int tid = threadIdx.x;
    const int lane = tid & 31, warp = tid >> 5;
    const int wm = warp & 3, wn = warp >> 2;
    const int g4 = lane >> 2, l4 = lane & 3;
    const int wr0 = wm * 16 + g4;
    const int colbase = wn * 32;

    const int aRow = lane & 15;
    const uint32_t aHiB = ((lane >> 4) & 1) * 16;
    const uint32_t aOff = (uint32_t)boff(wm * 16 + aRow) * 4 + aHiB;
    const uint32_t adQwh = sm_u32(Qwh) + aOff, adQwl = sm_u32(Qwl) + aOff;
    const uint32_t adQrh = sm_u32(Qrh) + aOff, adQrl = sm_u32(Qrl) + aOff;
    const uint32_t adPh  = sm_u32(Ph)  + aOff, adPl  = sm_u32(Pl)  + aOff;
    const int bRowN = ((lane >> 4) & 1) * 8 + (lane & 7);
    const uint32_t bHiB = ((lane >> 3) & 1) * 16;
    const uint32_t bO0 = (uint32_t)boff(colbase + bRowN) * 4 + bHiB;
    const uint32_t bO1 = (uint32_t)boff(colbase + 16 + bRowN) * 4 + bHiB;
    const uint32_t adKh0 = sm_u32(Kh) + bO0,  adKh1 = sm_u32(Kh) + bO1;
    const uint32_t adKl0 = sm_u32(Kl) + bO0,  adKl1 = sm_u32(Kl) + bO1;
    const uint32_t adRh0 = sm_u32(Rh) + bO0,  adRh1 = sm_u32(Rh) + bO1;
    const uint32_t adRl0 = sm_u32(Rl) + bO0,  adRl1 = sm_u32(Rl) + bO1;
    const uint32_t adVh0 = sm_u32(Vth) + bO0, adVh1 = sm_u32(Vth) + bO1;
    const uint32_t adVl0 = sm_u32(Vtl) + bO0, adVl1 = sm_u32(Vtl) + bO1;

    float4 kreg[4], vreg[4];
    const int kvr = tid >> 4, kvc4 = (tid & 15) * 4;
    const int vkp = tid >> 3, vfb = (tid & 7) * 8;
    auto prefetchKV = [&](int j0) {
        #pragma unroll
        for (int it = 0; it < 4; it++) {
            int grow = j0 + kvr + 16 * it;
            kreg[it] = make_float4(0.f, 0.f, 0.f, 0.f);
            if (grow < TT)
                kreg[it] = *(const float4*)(heads + (size_t)grow * (3 * DM) + DM + h * DH + kvc4);
        }
        int jA = j0 + 2 * vkp, jB = jA + 1;
        vreg[0] = vreg[1] = vreg[2] = vreg[3] = make_float4(0.f, 0.f, 0.f, 0.f);
        if (jA < TT) {
            vreg[0] = *(const float4*)(heads + (size_t)jA * (3 * DM) + 2 * DM + h * DH + vfb);
            vreg[1] = *(const float4*)(heads + (size_t)jA * (3 * DM) + 2 * DM + h * DH + vfb + 4);
        }
        if (jB < TT) {
            vreg[2] = *(const float4*)(heads + (size_t)jB * (3 * DM) + 2 * DM + h * DH + vfb);
            vreg[3] = *(const float4*)(heads + (size_t)jB * (3 * DM) + 2 * DM + h * DH + vfb + 4);
        }
    };
    auto storeKV = [&]() {
        #pragma unroll
        for (int it = 0; it < 4; it++) {
            int wi = boff(kvr + 16 * it) + (kvc4 >> 1);
            uint32_t hw, lw;
            split2(kreg[it].x, kreg[it].y, hw, lw); Kh[wi] = hw;     Kl[wi] = lw;
            split2(kreg[it].z, kreg[it].w, hw, lw); Kh[wi + 1] = hw; Kl[wi + 1] = lw;
        }
        const float* pa0 = &vreg[0].x; const float* pa1 = &vreg[1].x;
        const float* pb0 = &vreg[2].x; const float* pb1 = &vreg[3].x;
        #pragma unroll
        for (int i = 0; i < 4; i++) {
            uint32_t hw, lw;
            split2(pa0[i], pb0[i], hw, lw);
            Vth[boff(vfb + i) + vkp] = hw; Vtl[boff(vfb + i) + vkp] = lw;
            split2(pa1[i], pb1[i], hw, lw);
            Vth[boff(vfb + 4 + i) + vkp] = hw; Vtl[boff(vfb + 4 + i) + vkp] = lw;
        }
    };

    int blist[2]; int nblk;
    if (p < 16) { blist[0] = p; blist[1] = 31 - p; nblk = 2; }
    else        { blist[0] = 32; nblk = 1; }

    for (int bi = 0; bi < nblk; bi++) {
        const int b = blist[bi];
        const int i0 = b * 64;
        const int validRows = min(64, TT - i0);
        const int njt = (b < 32) ? (b + 1) : 33;

        __syncthreads();
        for (int t = tid; t < 64 * 16; t += 256) {
            int r = t >> 4, c4 = (t & 15) * 4;
            int grow = i0 + r;
            float4 q = make_float4(0.f, 0.f, 0.f, 0.f);
            if (grow < TT)
                q = *(const float4*)(heads + (size_t)grow * (3 * DM) + h * DH + c4);
            float4 bw = *(const float4*)(rwb + h * DH + c4);
            float4 br = *(const float4*)(rrb + h * DH + c4);
            int wi = boff(r) + (c4 >> 1);
            uint32_t hw, lw;
            split2(q.x + bw.x, q.y + bw.y, hw, lw); Qwh[wi] = hw;     Qwl[wi] = lw;
            split2(q.z + bw.z, q.w + bw.w, hw, lw); Qwh[wi + 1] = hw; Qwl[wi + 1] = lw;
            split2(q.x + br.x, q.y + br.y, hw, lw); Qrh[wi] = hw;     Qrl[wi] = lw;
            split2(q.z + br.z, q.w + br.w, hw, lw); Qrh[wi + 1] = hw; Qrl[wi + 1] = lw;
        }
        prefetchKV(0);

        float o[4][4];
        #pragma unroll
        for (int a = 0; a < 4; a++) { o[a][0] = o[a][1] = o[a][2] = o[a][3] = 0.f; }
        float mrow[2] = {-1e30f, -1e30f};
        float lrow[2] = {0.f, 0.f};

        int nextChunk = (2016 - i0) / 64;
        if (nextChunk < 0) nextChunk = 0;

        for (int jt = 0; jt < njt; jt++) {
            const int j0 = jt * 64;

            const int hiJr = min(TT - 1, TT - 1 - i0 + j0 + 63);
            const int chi = hiJr >> 6;
            while (nextChunk <= chi) {
                const int c = nextChunk;
                __syncthreads();
                for (int t = tid; t < 64 * 16; t += 256) {
                    int r = t >> 4, c4 = (t & 15) * 4;
                    int grow = c * 64 + r;
                    float4 v = make_float4(0.f, 0.f, 0.f, 0.f);
                    if (grow < TT)
                        v = *(const float4*)(rbuf + (size_t)grow * DM + h * DH + c4);
                    int wi = boff(r) + (c4 >> 1);
                    uint32_t hw, lw;
                    split2(v.x, v.y, hw, lw); Rh[wi] = hw;     Rl[wi] = lw;
                    split2(v.z, v.w, hw, lw); Rh[wi + 1] = hw; Rl[wi + 1] = lw;
                }
                __syncthreads();
                float cacc[4][4];
                #pragma unroll
                for (int a = 0; a < 4; a++)
                    cacc[a][0] = cacc[a][1] = cacc[a][2] = cacc[a][3] = 0.f;
                #pragma unroll
                for (int kc = 0; kc < 4; kc++) {
                    uint32_t ah[4], al[4];
                    ldsm4(ah, adQrh + kc * 32);
                    ldsm4(al, adQrl + kc * 32);
                    uint32_t bh[2][4], bl[2][4];
                    ldsm4(bh[0], adRh0 + kc * 32);
                    ldsm4(bh[1], adRh1 + kc * 32);
                    ldsm4(bl[0], adRl0 + kc * 32);
                    ldsm4(bl[1], adRl1 + kc * 32);
                    #pragma unroll
                    for (int an = 0; an < 4; an++) {
                        const int g = an >> 1, x = (an & 1) * 2;
                        mma16(cacc[an], ah, bh[g][x], bh[g][x + 1]);
                        mma16(cacc[an], ah, bl[g][x], bl[g][x + 1]);
                        mma16(cacc[an], al, bh[g][x], bh[g][x + 1]);
                    }
                }
                float* slot = Ring + (c % 3) * RSLOT;
                #pragma unroll
                for (int an = 0; an < 4; an++) {
                    int col = colbase + an * 8 + 2 * l4;
                    slot[wr0 * RPAD + col]           = cacc[an][0];
                    slot[wr0 * RPAD + col + 1]       = cacc[an][1];
                    slot[(wr0 + 8) * RPAD + col]     = cacc[an][2];
                    slot[(wr0 + 8) * RPAD + col + 1] = cacc[an][3];
                }
                nextChunk++;
            }

            __syncthreads();
            storeKV();
            __syncthreads();

            float s[4][4];
            #pragma unroll
            for (int a = 0; a < 4; a++)
                s[a][0] = s[a][1] = s[a][2] = s[a][3] = 0.f;
            #pragma unroll
            for (int kc = 0; kc < 4; kc++) {
                uint32_t ah[4], al[4];
                ldsm4(ah, adQwh + kc * 32);
                ldsm4(al, adQwl + kc * 32);
                uint32_t bh[2][4], bl[2][4];
                ldsm4(bh[0], adKh0 + kc * 32);
                ldsm4(bh[1], adKh1 + kc * 32);
                ldsm4(bl[0], adKl0 + kc * 32);
                ldsm4(bl[1], adKl1 + kc * 32);
                #pragma unroll
                for (int an = 0; an < 4; an++) {
                    const int g = an >> 1, x = (an & 1) * 2;
                    mma16(s[an], ah, bh[g][x], bh[g][x + 1]);
                    mma16(s[an], ah, bl[g][x], bl[g][x + 1]);
                    mma16(s[an], al, bh[g][x], bh[g][x + 1]);
                }
            }

            float tmax[2] = {-1e30f, -1e30f};
            #pragma unroll
            for (int an = 0; an < 4; an++) {
                #pragma unroll
                for (int e = 0; e < 4; e++) {
                    int rh = e >> 1;
                    int di = wr0 + rh * 8;
                    int dj = colbase + an * 8 + 2 * l4 + (e & 1);
                    int i = i0 + di, j = j0 + dj;
                    float v = -1e30f;
                    if (di < validRows && j < TT) {
                        int jmaxr = (i < NMTOK) ? (NMTOK - 1)
                                  : ((i >= TT - NMTOK) ? (TT - 1) : i);
                        if (j <= jmaxr) {
                            float bd;
                            if (j <= i) {
                                int jr = TT - 1 - i + j;
                                bd = Ring[((jr >> 6) % 3) * RSLOT + di * RPAD + (jr & 63)];
                            } else if (j == i + 1) {
                                bd = 0.f;
                            } else {
                                const float* rr = rbuf + (size_t)(j - i - 2) * DM + h * DH;
                                float accd = 0.f;
                                #pragma unroll 8
                                for (int d2 = 0; d2 < 32; d2++) {
                                    uint32_t wh = Qrh[boff(di + 1) + d2];
                                    uint32_t wl = Qrl[boff(di + 1) + d2];
                                    __nv_bfloat162 h2 = *reinterpret_cast<__nv_bfloat162*>(&wh);
                                    __nv_bfloat162 l2 = *reinterpret_cast<__nv_bfloat162*>(&wl);
                                    float q0 = __bfloat162float(h2.x) + __bfloat162float(l2.x);
                                    float q1 = __bfloat162float(h2.y) + __bfloat162float(l2.y);
                                    accd += q0 * rr[2 * d2] + q1 * rr[2 * d2 + 1];
                                }
                                bd = accd;
                            }
                            v = (s[an][e] + bd) * 0.125f;
                        }
                    }
                    s[an][e] = v;
                    tmax[rh] = fmaxf(tmax[rh], v);
                }
            }
            #pragma unroll
            for (int rh = 0; rh < 2; rh++) {
                tmax[rh] = fmaxf(tmax[rh], __shfl_xor_sync(0xffffffffu, tmax[rh], 1));
                tmax[rh] = fmaxf(tmax[rh], __shfl_xor_sync(0xffffffffu, tmax[rh], 2));
            }
            if (l4 == 0) {
                redm[wn * 64 + wm * 16 + g4]     = tmax[0];
                redm[wn * 64 + wm * 16 + g4 + 8] = tmax[1];
            }
            __syncthreads();

            float scl[2], lsum[2] = {0.f, 0.f};
            #pragma unroll
            for (int rh = 0; rh < 2; rh++) {
                int row = wm * 16 + g4 + rh * 8;
                float tm = fmaxf(redm[row], redm[64 + row]);
                float mnew = fmaxf(mrow[rh], tm);
                scl[rh] = expf(mrow[rh] - mnew);
                mrow[rh] = mnew;
            }
            #pragma unroll
            for (int an = 0; an < 4; an++) {
                #pragma unroll
                for (int e = 0; e < 4; e++) {
                    int rh = e >> 1;
                    float ev = expf(s[an][e] - mrow[rh]);
                    s[an][e] = ev;
                    lsum[rh] += ev;
                }
            }
            #pragma unroll
            for (int rh = 0; rh < 2; rh++) {
                lsum[rh] += __shfl_xor_sync(0xffffffffu, lsum[rh], 1);
                lsum[rh] += __shfl_xor_sync(0xffffffffu, lsum[rh], 2);
            }
            if (l4 == 0) {
                reds[wn * 64 + wm * 16 + g4]     = lsum[0];
                reds[wn * 64 + wm * 16 + g4 + 8] = lsum[1];
            }
            #pragma unroll
            for (int an = 0; an < 4; an++) {
                int cp = (colbase >> 1) + an * 4 + l4;
                uint32_t hw, lw;
                split2(s[an][0], s[an][1], hw, lw);
                Ph[boff(wr0) + cp] = hw; Pl[boff(wr0) + cp] = lw;
                split2(s[an][2], s[an][3], hw, lw);
                Ph[boff(wr0 + 8) + cp] = hw; Pl[boff(wr0 + 8) + cp] = lw;
            }
            __syncthreads();

            #pragma unroll
            for (int rh = 0; rh < 2; rh++) {
                int row = wm * 16 + g4 + rh * 8;
                lrow[rh] = lrow[rh] * scl[rh] + reds[row] + reds[64 + row];
            }
            #pragma unroll
            for (int an = 0; an < 4; an++) {
                o[an][0] *= scl[0]; o[an][1] *= scl[0];
                o[an][2] *= scl[1]; o[an][3] *= scl[1];
            }

            #pragma unroll
            for (int kc = 0; kc < 4; kc++) {
                uint32_t ah[4], al[4];
                ldsm4(ah, adPh + kc * 32);
                ldsm4(al, adPl + kc * 32);
                uint32_t bh[2][4], bl[2][4];
                ldsm4(bh[0], adVh0 + kc * 32);
                ldsm4(bh[1], adVh1 + kc * 32);
                ldsm4(bl[0], adVl0 + kc * 32);
                ldsm4(bl[1], adVl1 + kc * 32);
                #pragma unroll
                for (int an = 0; an < 4; an++) {
                    const int g = an >> 1, x = (an & 1) * 2;
                    mma16(o[an], ah, bh[g][x], bh[g][x + 1]);
                    mma16(o[an], ah, bl[g][x], bl[g][x + 1]);
                    mma16(o[an], al, bh[g][x], bh[g][x + 1]);
                }
            }

            if (jt + 1 < njt) prefetchKV((jt + 1) * 64);
        } // j-tiles

        // epilogue: write attention output directly as bf16 planes
        float inv0 = 1.f / lrow[0], inv1 = 1.f / lrow[1];
        #pragma unroll
        for (int an = 0; an < 4; an++) {
            int colw = (h * DH + colbase + an * 8 + 2 * l4) >> 1;
            int r0 = i0 + wr0;
            uint32_t hw, lw;
            if (wr0 < validRows) {
                split2(o[an][0] * inv0, o[an][1] * inv0, hw, lw);
                avPh[(size_t)r0 * 256 + colw] = hw;
                avPl[(size_t)r0 * 256 + colw] = lw;
            }
            if (wr0 + 8 < validRows) {
                split2(o[an][2] * inv1, o[an][3] * inv1, hw, lw);
                avPh[(size_t)(r0 + 8) * 256 + colw] = hw;
                avPl[(size_t)(r0 + 8) * 256 + colw] = lw;
            }
        }
    } // blocks
}

// ---------------- residual add + layernorm (pair threads; emits w planes) ----------------
__global__ void add_ln_kernel(float* __restrict__ w, const float* __restrict__ delta,
                              const float* __restrict__ delta2,
                              const float* __restrict__ gam, const float* __restrict__ bta) {
    int row = blockIdx.x;
    int tid = threadIdx.x;
    int c = 2 * tid;
    __shared__ float red[256];
    float x0 = w[row * DM + c]     + delta[row * DM + c];
    float x1 = w[row * DM + c + 1] + delta[row * DM + c + 1];
    if (delta2) {
        x0 += delta2[row * DM + c];
        x1 += delta2[row * DM + c + 1];
    }
    red[tid] = x0 + x1; __syncthreads();
    for (int s = 128; s > 0; s >>= 1) {
        if (tid < s) red[tid] += red[tid + s];
        __syncthreads();
    }
    float mean = red[0] * (1.f / DM);
    __syncthreads();
    float d0 = x0 - mean, d1 = x1 - mean;
    red[tid] = d0 * d0 + d1 * d1; __syncthreads();
    for (int s = 128; s > 0; s >>= 1) {
        if (tid < s) red[tid] += red[tid + s];
        __syncthreads();
    }
    float inv = 1.f / sqrtf(red[0] * (1.f / DM) + 1e-5f);
    float y0 = d0 * inv * gam[c]     + bta[c];
    float y1 = d1 * inv * gam[c + 1] + bta[c + 1];
    w[row * DM + c]     = y0;
    w[row * DM + c + 1] = y1;
    uint32_t hw, lw;
    split2(y0, y1, hw, lw);
    wPh[row * 256 + tid] = hw;
    wPl[row * 256 + tid] = lw;
}

__global__ void copy_out_kernel(float* __restrict__ out) {
    int idx = blockIdx.x * blockDim.x + threadIdx.x;
    if (idx < TT * DM) out[idx] = g_w[idx];
}

// ---------------- launcher ----------------
extern "C" void kernel_launch(void* const* d_in, const int* in_sizes, int n_in,
                              void* d_out, int out_size) {
    (void)in_sizes; (void)n_in; (void)out_size;
    const float* word_emb = (const float*)d_in[0];
    const float* mem_tok  = (const float*)d_in[1];
    const float* Wqkv     = (const float*)d_in[2];
    const float* Wr       = (const float*)d_in[3];
    const float* Wo       = (const float*)d_in[4];
    const float* ln1s     = (const float*)d_in[5];
    const float* ln1b     = (const float*)d_in[6];
    const float* W1       = (const float*)d_in[7];
    const float* b1       = (const float*)d_in[8];
    const float* W2       = (const float*)d_in[9];
    const float* b2       = (const float*)d_in[10];
    const float* ln2s     = (const float*)d_in[11];
    const float* ln2b     = (const float*)d_in[12];
    const float* rwb      = (const float*)d_in[13];
    const float* rrb      = (const float*)d_in[14];

    float *g_w_p, *g_hd_p, *g_r_p, *g_tmp_p, *g_tmp2_p;
    cudaGetSymbolAddress((void**)&g_w_p,    g_w);
    cudaGetSymbolAddress((void**)&g_hd_p,   g_heads);
    cudaGetSymbolAddress((void**)&g_r_p,    g_r);
    cudaGetSymbolAddress((void**)&g_tmp_p,  g_tmp);
    cudaGetSymbolAddress((void**)&g_tmp2_p, g_tmp2);
    uint32_t *wPh_p, *wPl_p, *posPh_p, *posPl_p, *avPh_p, *avPl_p, *ff1Ph_p, *ff1Pl_p;
    cudaGetSymbolAddress((void**)&wPh_p,   wPh);
    cudaGetSymbolAddress((void**)&wPl_p,   wPl);
    cudaGetSymbolAddress((void**)&posPh_p, posPh);
    cudaGetSymbolAddress((void**)&posPl_p, posPl);
    cudaGetSymbolAddress((void**)&avPh_p,  avPh);
    cudaGetSymbolAddress((void**)&avPl_p,  avPl);
    cudaGetSymbolAddress((void**)&ff1Ph_p, ff1Ph);
    cudaGetSymbolAddress((void**)&ff1Pl_p, ff1Pl);
    uint32_t *qkvPh_p, *qkvPl_p, *wrPh_p, *wrPl_p, *woPh_p, *woPl_p, *w1Ph_p, *w1Pl_p, *w2Ph_p, *w2Pl_p;
    cudaGetSymbolAddress((void**)&qkvPh_p, qkvPh);
    cudaGetSymbolAddress((void**)&qkvPl_p, qkvPl);
    cudaGetSymbolAddress((void**)&wrPh_p,  wrPh);
    cudaGetSymbolAddress((void**)&wrPl_p,  wrPl);
    cudaGetSymbolAddress((void**)&woPh_p,  woPh);
    cudaGetSymbolAddress((void**)&woPl_p,  woPl);
    cudaGetSymbolAddress((void**)&w1Ph_p,  w1Ph);
    cudaGetSymbolAddress((void**)&w1Pl_p,  w1Pl);
    cudaGetSymbolAddress((void**)&w2Ph_p,  w2Ph);
    cudaGetSymbolAddress((void**)&w2Pl_p,  w2Pl);

    cudaFuncSetAttribute(fused_attn_kernel,
                         cudaFuncAttributeMaxDynamicSharedMemorySize, ATTN_SMEM);
    cudaFuncSetAttribute(mma_gemm,
                         cudaFuncAttributeMaxDynamicSharedMemorySize, GEMM_SMEM);

    // one-time weight conversion to planes
    convert_weight<<<dim3(1536 / 32, 512 / 64, NLAY), 256>>>(Wqkv, qkvPh_p, qkvPl_p, 512, 1536);
    convert_weight<<<dim3(512 / 32, 512 / 64, NLAY), 256>>>(Wr, wrPh_p, wrPl_p, 512, 512);
    convert_weight<<<dim3(512 / 32, 512 / 64, NLAY), 256>>>(Wo, woPh_p, woPl_p, 512, 512);
    convert_weight<<<dim3(2048 / 32, 512 / 64, NLAY), 256>>>(W1, w1Ph_p, w1Pl_p, 512, 2048);
    convert_weight<<<dim3(512 / 32, 2048 / 64, NLAY), 256>>>(W2, w2Ph_p, w2Pl_p, 2048, 512);

    build_w_kernel<<<(TT * 256 + 255) / 256, 256>>>(word_emb, mem_tok);
    build_pos_kernel<<<(TT * 256 + 255) / 256, 256>>>();

    const int MB = (TT + 127) / 128;   // 17

    for (int l = 0; l < NLAY; l++) {
        // QKV: heads(fp32) = w @ Wqkv[l]
        mma_gemm<<<dim3(24, MB, 1), 256, GEMM_SMEM>>>(
            wPh_p, wPl_p, 256,
            qkvPh_p + (size_t)l * 1536 * 256, qkvPl_p + (size_t)l * 1536 * 256, 256,
            g_hd_p, g_hd_p, nullptr, nullptr, 3 * DM,
            nullptr, 0, TT, 3 * DM, DM);
        // Wr: r(fp32) = pos @ Wr[l]
        mma_gemm<<<dim3(8, MB, 1), 256, GEMM_SMEM>>>(
            posPh_p, posPl_p, 256,
            wrPh_p + (size_t)l * 512 * 256, wrPl_p + (size_t)l * 512 * 256, 256,
            g_r_p, g_r_p, nullptr, nullptr, DM,
            nullptr, 0, TT, DM, DM);

        fused_attn_kernel<<<dim3(NH, 17), 256, ATTN_SMEM>>>(g_hd_p, g_r_p, rwb, rrb);

        // Wo: K-split z=2, fp32 partials
        mma_gemm<<<dim3(8, MB, 2), 256, GEMM_SMEM>>>(
            avPh_p, avPl_p, 256,
            woPh_p + (size_t)l * 512 * 256, woPl_p + (size_t)l * 512 * 256, 256,
            g_tmp_p, g_tmp2_p, nullptr, nullptr, DM,
            nullptr, 0, TT, DM, DM / 2);
        add_ln_kernel<<<TT, 256>>>(g_w_p, g_tmp_p, g_tmp2_p, ln1s + l * DM, ln1b + l * DM);
        // FFN1: plane output (bias+relu fused)
        mma_gemm<<<dim3(32, MB, 1), 256, GEMM_SMEM>>>(
            wPh_p, wPl_p, 256,
            w1Ph_p + (size_t)l * 2048 * 256, w1Pl_p + (size_t)l * 2048 * 256, 256,
            nullptr, nullptr, ff1Ph_p, ff1Pl_p, DI / 2,
            b1 + (size_t)l * DI, 1, TT, DI, DM);
        // FFN2: K-split z=2, fp32 partials
        mma_gemm<<<dim3(8, MB, 2), 256, GEMM_SMEM>>>(
            ff1Ph_p, ff1Pl_p, 1024,
            w2Ph_p + (size_t)l * 512 * 1024, w2Pl_p + (size_t)l * 512 * 1024, 1024,
            g_tmp_p, g_tmp2_p, nullptr, nullptr, DM,
            b2 + (size_t)l * DM, 0, TT, DM, DI / 2);
        add_ln_kernel<<<TT, 256>>>(g_w_p, g_tmp_p, g_tmp2_p, ln2s + l * DM, ln2b + l * DM);
    }

    copy_out_kernel<<<(TT * DM + 255) / 256, 256>>>((float*)d_out);
}

// round 11
// speedup vs baseline: 1.0675x; 1.0675x over previous
#include <cuda_runtime.h>
#include <cuda_bf16.h>
#include <math.h>
#include <stdint.h>

// ---------------- problem constants ----------------
#define TT    2080
#define DM    512
#define NH    8
#define DH    64
#define DI    2048
#define NLAY  4
#define NMTOK 16
#define QL    2048

// ---------------- fp32 scratch ----------------
__device__ float g_w[TT * DM];
__device__ float g_heads[TT * 3 * DM];
__device__ float g_r[TT * DM];
__device__ float g_tmp[TT * DM];
__device__ float g_tmp2[TT * DM];

// ---------------- bf16 hi/lo pair-plane scratch (word = bf16x2 {even k, odd k}) ----------------
__device__ uint32_t wPh[TT * 256],   wPl[TT * 256];
__device__ uint32_t posPh[TT * 256], posPl[TT * 256];
__device__ uint32_t avPh[TT * 256],  avPl[TT * 256];
__device__ uint32_t ff1Ph[TT * 1024], ff1Pl[TT * 1024];
__device__ uint32_t qkvPh[NLAY * 1536 * 256], qkvPl[NLAY * 1536 * 256];
__device__ uint32_t wrPh[NLAY * 512 * 256],   wrPl[NLAY * 512 * 256];
__device__ uint32_t woPh[NLAY * 512 * 256],   woPl[NLAY * 512 * 256];
__device__ uint32_t w1Ph[NLAY * 2048 * 256],  w1Pl[NLAY * 2048 * 256];
__device__ uint32_t w2Ph[NLAY * 512 * 1024],  w2Pl[NLAY * 512 * 1024];

// ---------------- bf16x3 helpers ----------------
__device__ __forceinline__ void split2(float x0, float x1, uint32_t& hw, uint32_t& lw) {
    __nv_bfloat162 h, l;
    h.x = __float2bfloat16(x0);
    h.y = __float2bfloat16(x1);
    l.x = __float2bfloat16(x0 - __bfloat162float(h.x));
    l.y = __float2bfloat16(x1 - __bfloat162float(h.y));
    hw = *reinterpret_cast<uint32_t*>(&h);
    lw = *reinterpret_cast<uint32_t*>(&l);
}

__device__ __forceinline__ void mma16(float (&c)[4], const uint32_t (&a)[4],
                                      uint32_t b0, uint32_t b1) {
    asm volatile(
        "mma.sync.aligned.m16n8k16.row.col.f32.bf16.bf16.f32 "
        "{%0,%1,%2,%3}, {%4,%5,%6,%7}, {%8,%9}, {%0,%1,%2,%3};"
        : "+f"(c[0]), "+f"(c[1]), "+f"(c[2]), "+f"(c[3])
        : "r"(a[0]), "r"(a[1]), "r"(a[2]), "r"(a[3]), "r"(b0), "r"(b1));
}

__device__ __forceinline__ uint32_t sm_u32(const void* p) {
    return (uint32_t)__cvta_generic_to_shared(p);
}

__device__ __forceinline__ void ldsm4(uint32_t (&r)[4], uint32_t a) {
    asm volatile("ldmatrix.sync.aligned.m8n8.x4.shared.b16 {%0,%1,%2,%3}, [%4];"
                 : "=r"(r[0]), "=r"(r[1]), "=r"(r[2]), "=r"(r[3]) : "r"(a));
}

__device__ __forceinline__ void cpa16(uint32_t dst, const void* src, int szok) {
    asm volatile("cp.async.cg.shared.global [%0], [%1], 16, %2;"
                 :: "r"(dst), "l"(src), "r"(szok));
}

// attention B-style pair-plane smem layout (unchanged)
__device__ __forceinline__ int boff(int n) { return n * 36 + ((n >> 3) << 2); }
#define BPLANE (64 * 36 + 32)

// ---------------- prep kernels (emit planes) ----------------
__global__ void build_w_kernel(const float* __restrict__ word_emb,
                               const float* __restrict__ mem) {
    int idx = blockIdx.x * blockDim.x + threadIdx.x;
    if (idx >= TT * 256) return;
    int row = idx >> 8, c2 = idx & 255;
    int c = 2 * c2;
    float v0, v1;
    if (row < NMTOK) {
        v0 = mem[row * DM + c]; v1 = mem[row * DM + c + 1];
    } else if (row < NMTOK + QL) {
        v0 = word_emb[(row - NMTOK) * DM + c]; v1 = word_emb[(row - NMTOK) * DM + c + 1];
    } else {
        v0 = mem[(row - NMTOK - QL) * DM + c]; v1 = mem[(row - NMTOK - QL) * DM + c + 1];
    }
    g_w[row * DM + c] = v0;
    g_w[row * DM + c + 1] = v1;
    uint32_t hw, lw;
    split2(v0, v1, hw, lw);
    wPh[idx] = hw; wPl[idx] = lw;
}

__global__ void build_pos_kernel() {
    int idx = blockIdx.x * blockDim.x + threadIdx.x;
    if (idx >= TT * 256) return;
    int row = idx >> 8, c2 = idx & 255;
    float v0, v1;
    #pragma unroll
    for (int u = 0; u < 2; u++) {
        int c = 2 * c2 + u;
        int f = (c < DM / 2) ? c : (c - DM / 2);
        double invf = exp(-((double)(2 * f) / (double)DM) * log(10000.0));
        double val = (double)(TT - 1 - row) * invf;
        float r = (float)((c < DM / 2) ? sin(val) : cos(val));
        if (u == 0) v0 = r; else v1 = r;
    }
    uint32_t hw, lw;
    split2(v0, v1, hw, lw);
    posPh[idx] = hw; posPl[idx] = lw;
}

// ---------------- weight convert: W[l][K][N] fp32 -> planes [l][N][K/2] ----------------
__global__ void convert_weight(const float* __restrict__ W,
                               uint32_t* __restrict__ Ph, uint32_t* __restrict__ Pl,
                               int K, int N) {
    __shared__ float S[64][33];
    const int l = blockIdx.z;
    const float* Wl = W + (size_t)l * K * N;
    const int Kw = K >> 1;
    uint32_t* PhL = Ph + (size_t)l * N * Kw;
    uint32_t* PlL = Pl + (size_t)l * N * Kw;
    const int n0 = blockIdx.x * 32, k0 = blockIdx.y * 64;
    const int t = threadIdx.x;
    {
        int n = t & 31, kk = t >> 5;
        #pragma unroll
        for (int i = 0; i < 8; i++)
            S[kk + 8 * i][n] = Wl[(size_t)(k0 + kk + 8 * i) * N + n0 + n];
    }
    __syncthreads();
    {
        int nn = t >> 3, kq = t & 7;
        uint32_t oh[4], ol[4];
        #pragma unroll
        for (int i = 0; i < 4; i++) {
            int kp = kq * 4 + i;
            split2(S[2 * kp][nn], S[2 * kp + 1][nn], oh[i], ol[i]);
        }
        size_t base = (size_t)(n0 + nn) * Kw + (k0 >> 1) + kq * 4;
        *reinterpret_cast<uint4*>(PhL + base) = *reinterpret_cast<uint4*>(oh);
        *reinterpret_cast<uint4*>(PlL + base) = *reinterpret_cast<uint4*>(ol);
    }
}

// ---------------- GEMM: cp.async 3-stage pipeline, planes in, fp32 or planes out ----------------
#define PPA 20
#define PPB 20
#define ASTG (128 * PPA)                 // 2560 words per A plane per stage
#define BSTG (64 * PPB)                  // 1280 words per B plane per stage
#define STG_W (2 * ASTG + 2 * BSTG)      // 7680 words = 30720 B per stage
#define NSTG 3
#define GEMM_SMEM (NSTG * STG_W * 4)     // 92160 B

__global__ __launch_bounds__(256, 2)
void mma_gemm(const uint32_t* __restrict__ Ahg, const uint32_t* __restrict__ Alg, int ldaw,
              const uint32_t* __restrict__ Bhg, const uint32_t* __restrict__ Blg, int ldbw,
              float* __restrict__ C, float* __restrict__ C2,
              uint32_t* __restrict__ OutH, uint32_t* __restrict__ OutL, int ldc,
              const float* __restrict__ cbias, int doRelu,
              int M, int N, int Ksub) {
    extern __shared__ uint32_t gsm[];
    const uint32_t smBase = sm_u32(gsm);

    const int bm = blockIdx.y * 128, bn = blockIdx.x * 64;
    const int kOffW = blockIdx.z * (Ksub >> 1);
    if (blockIdx.z == 1) C = C2;

    const int tid = threadIdx.x;
    const int lane = tid & 31, warp = tid >> 5;
    const int wm = warp & 3, wn = warp >> 2;
    const int g4 = lane >> 2, l4 = lane & 3;

    float acc[2][4][4] = {};

    const int arow = tid >> 2;   // 0..63
    const int akq = tid & 3;     // uint4 group of kpairs

    // ldsm base addresses (stage byte-offset added in loop)
    const int aRow = lane & 15;
    const uint32_t aHiB = ((lane >> 4) & 1) * 16;
    const uint32_t adA = smBase + (uint32_t)((wm * 32 + aRow) * PPA) * 4 + aHiB;
    const int bRowN = ((lane >> 4) & 1) * 8 + (lane & 7);
    const uint32_t bHiB = ((lane >> 3) & 1) * 16;
    const uint32_t adB0 = smBase + (uint32_t)(2 * ASTG + (wn * 32 + bRowN) * PPB) * 4 + bHiB;
    const uint32_t adB1 = adB0 + 16 * PPB * 4;

    // cp.async dest offsets within stage (bytes)
    const uint32_t dA = (uint32_t)(arow * PPA + akq * 4) * 4;
    const uint32_t dB = (uint32_t)(2 * ASTG + arow * PPB + akq * 4) * 4;

    auto issueStage = [&](int iter, int st) {
        const int kw = kOffW + iter * 16 + akq * 4;
        const uint32_t base = smBase + (uint32_t)st * (STG_W * 4);
        #pragma unroll
        for (int p = 0; p < 2; p++) {
            int row = bm + p * 64 + arow;
            int ok = (row < M) ? 16 : 0;
            int rowc = (row < M) ? row : 0;
            cpa16(base + dA + p * 64 * PPA * 4, Ahg + (size_t)rowc * ldaw + kw, ok);
            cpa16(base + dA + p * 64 * PPA * 4 + ASTG * 4, Alg + (size_t)rowc * ldaw + kw, ok);
        }
        {
            int row = bn + arow;
            cpa16(base + dB, Bhg + (size_t)row * ldbw + kw, 16);
            cpa16(base + dB + BSTG * 4, Blg + (size_t)row * ldbw + kw, 16);
        }
    };

    const int niter = Ksub >> 5;
    issueStage(0, 0);
    asm volatile("cp.async.commit_group;" ::: "memory");
    issueStage(1, 1);
    asm volatile("cp.async.commit_group;" ::: "memory");

    int st = 0;
    for (int i = 0; i < niter; i++) {
        asm volatile("cp.async.wait_group 1;" ::: "memory");
        __syncthreads();
        const uint32_t so = (uint32_t)st * (STG_W * 4);
        #pragma unroll
        for (int ks = 0; ks < 2; ks++) {
            uint32_t ahh[2][4], alo[2][4];
            ldsm4(ahh[0], adA + so + ks * 32);
            ldsm4(ahh[1], adA + so + 16 * PPA * 4 + ks * 32);
            ldsm4(alo[0], adA + so + ASTG * 4 + ks * 32);
            ldsm4(alo[1], adA + so + ASTG * 4 + 16 * PPA * 4 + ks * 32);
            uint32_t bhh[2][4], blo[2][4];
            ldsm4(bhh[0], adB0 + so + ks * 32);
            ldsm4(bhh[1], adB1 + so + ks * 32);
            ldsm4(blo[0], adB0 + so + BSTG * 4 + ks * 32);
            ldsm4(blo[1], adB1 + so + BSTG * 4 + ks * 32);
            #pragma unroll
            for (int am = 0; am < 2; am++)
                #pragma unroll
                for (int an = 0; an < 4; an++) {
                    const int g = an >> 1, x = (an & 1) * 2;
                    mma16(acc[am][an], ahh[am], bhh[g][x], bhh[g][x + 1]);
                    mma16(acc[am][an], ahh[am], blo[g][x], blo[g][x + 1]);
                    mma16(acc[am][an], alo[am], bhh[g][x], bhh[g][x + 1]);
                }
        }
        if (i + 2 < niter) {
            int st2 = st + 2; if (st2 >= NSTG) st2 -= NSTG;
            issueStage(i + 2, st2);
        }
        asm volatile("cp.async.commit_group;" ::: "memory");
        st = (st + 1 == NSTG) ? 0 : st + 1;
    }

    const bool planes = (OutH != nullptr);
    #pragma unroll
    for (int am = 0; am < 2; am++) {
        int row0 = bm + wm * 32 + am * 16 + g4;
        #pragma unroll
        for (int an = 0; an < 4; an++) {
            int col0 = bn + wn * 32 + an * 8 + 2 * l4;
            float v0 = acc[am][an][0], v1 = acc[am][an][1];
            float v2 = acc[am][an][2], v3 = acc[am][an][3];
            if (cbias && blockIdx.z == 0) {
                float b0 = cbias[col0], b1 = cbias[col0 + 1];
                v0 += b0; v1 += b1; v2 += b0; v3 += b1;
            }
            if (doRelu) {
                v0 = fmaxf(v0, 0.f); v1 = fmaxf(v1, 0.f);
                v2 = fmaxf(v2, 0.f); v3 = fmaxf(v3, 0.f);
            }
            if (planes) {
                uint32_t hw, lw;
                if (row0 < M) {
                    split2(v0, v1, hw, lw);
                    OutH[(size_t)row0 * ldc + (col0 >> 1)] = hw;
                    OutL[(size_t)row0 * ldc + (col0 >> 1)] = lw;
                }
                if (row0 + 8 < M) {
                    split2(v2, v3, hw, lw);
                    OutH[(size_t)(row0 + 8) * ldc + (col0 >> 1)] = hw;
                    OutL[(size_t)(row0 + 8) * ldc + (col0 >> 1)] = lw;
                }
            } else {
                if (row0 < M) {
                    C[(size_t)row0 * ldc + col0]     = v0;
                    C[(size_t)row0 * ldc + col0 + 1] = v1;
                }
                if (row0 + 8 < M) {
                    C[(size_t)(row0 + 8) * ldc + col0]     = v2;
                    C[(size_t)(row0 + 8) * ldc + col0 + 1] = v3;
                }
            }
        }
    }
}

// ---------------- fused flash-style relative attention (unchanged core; plane epilogue) ----------------
#define RPAD 68
#define RSLOT (64 * RPAD)
#define ATTN_WORDS (12 * BPLANE + 3 * RSLOT + 256)
#define ATTN_SMEM (ATTN_WORDS * 4)

__global__ __launch_bounds__(256, 1)
void fused_attn_kernel(const float* __restrict__ heads,
                       const float* __restrict__ rbuf,
                       const float* __restrict__ rwb,
                       const float* __restrict__ rrb) {
    extern __shared__ uint32_t smu[];
    uint32_t* Qwh = smu;
    uint32_t* Qwl = Qwh + BPLANE;
    uint32_t* Qrh = Qwl + BPLANE;
    uint32_t* Qrl = Qrh + BPLANE;
    uint32_t* Kh  = Qrl + BPLANE;
    uint32_t* Kl  = Kh  + BPLANE;
    uint32_t* Rh  = Kl  + BPLANE;
    uint32_t* Rl  = Rh  + BPLANE;
    uint32_t* Vth = Rl  + BPLANE;
    uint32_t* Vtl = Vth + BPLANE;
    uint32_t* Ph  = Vtl + BPLANE;
    uint32_t* Pl  = Ph  + BPLANE;
    float* Ring = (float*)(Pl + BPLANE);
    float* redm = Ring + 3 * RSLOT;
    float* reds = redm + 128;

    const int h = blockIdx.x;
    const int p = blockIdx.y;
    const int tid = threadIdx.x;
    const int lane = tid & 31, warp = tid >> 5;
    const int wm = warp & 3, wn = warp >> 2;
    const int g4 = lane >> 2, l4 = lane & 3;
    const int wr0 = wm * 16 + g4;
    const int colbase = wn * 32;

    const int aRow = lane & 15;
    const uint32_t aHiB = ((lane >> 4) & 1) * 16;
    const uint32_t aOff = (uint32_t)boff(wm * 16 + aRow) * 4 + aHiB;
    const uint32_t adQwh = sm_u32(Qwh) + aOff, adQwl = sm_u32(Qwl) + aOff;
    const uint32_t adQrh = sm_u32(Qrh) + aOff, adQrl = sm_u32(Qrl) + aOff;
    const uint32_t adPh  = sm_u32(Ph)  + aOff, adPl  = sm_u32(Pl)  + aOff;
    const int bRowN = ((lane >> 4) & 1) * 8 + (lane & 7);
    const uint32_t bHiB = ((lane >> 3) & 1) * 16;
    const uint32_t bO0 = (uint32_t)boff(colbase + bRowN) * 4 + bHiB;
    const uint32_t bO1 = (uint32_t)boff(colbase + 16 + bRowN) * 4 + bHiB;
    const uint32_t adKh0 = sm_u32(Kh) + bO0,  adKh1 = sm_u32(Kh) + bO1;
    const uint32_t adKl0 = sm_u32(Kl) + bO0,  adKl1 = sm_u32(Kl) + bO1;
    const uint32_t adRh0 = sm_u32(Rh) + bO0,  adRh1 = sm_u32(Rh) + bO1;
    const uint32_t adRl0 = sm_u32(Rl) + bO0,  adRl1 = sm_u32(Rl) + bO1;
    const uint32_t adVh0 = sm_u32(Vth) + bO0, adVh1 = sm_u32(Vth) + bO1;
    const uint32_t adVl0 = sm_u32(Vtl) + bO0, adVl1 = sm_u32(Vtl) + bO1;

    float4 kreg[4], vreg[4];
    const int kvr = tid >> 4, kvc4 = (tid & 15) * 4;
    const int vkp = tid >> 3, vfb = (tid & 7) * 8;
    auto prefetchKV = [&](int j0) {
        #pragma unroll
        for (int it = 0; it < 4; it++) {
            int grow = j0 + kvr + 16 * it;
            kreg[it] = make_float4(0.f, 0.f, 0.f, 0.f);
            if (grow < TT)
                kreg[it] = *(const float4*)(heads + (size_t)grow * (3 * DM) + DM + h * DH + kvc4);
        }
        int jA = j0 + 2 * vkp, jB = jA + 1;
        vreg[0] = vreg[1] = vreg[2] = vreg[3] = make_float4(0.f, 0.f, 0.f, 0.f);
        if (jA < TT) {
            vreg[0] = *(const float4*)(heads + (size_t)jA * (3 * DM) + 2 * DM + h * DH + vfb);
            vreg[1] = *(const float4*)(heads + (size_t)jA * (3 * DM) + 2 * DM + h * DH + vfb + 4);
        }
        if (jB < TT) {
            vreg[2] = *(const float4*)(heads + (size_t)jB * (3 * DM) + 2 * DM + h * DH + vfb);
            vreg[3] = *(const float4*)(heads + (size_t)jB * (3 * DM) + 2 * DM + h * DH + vfb + 4);
        }
    };
    auto storeKV = [&]() {
        #pragma unroll
        for (int it = 0; it < 4; it++) {
            int wi = boff(kvr + 16 * it) + (kvc4 >> 1);
            uint32_t hw, lw;
            split2(kreg[it].x, kreg[it].y, hw, lw); Kh[wi] = hw;     Kl[wi] = lw;
            split2(kreg[it].z, kreg[it].w, hw, lw); Kh[wi + 1] = hw; Kl[wi + 1] = lw;
        }
        const float* pa0 = &vreg[0].x; const float* pa1 = &vreg[1].x;
        const float* pb0 = &vreg[2].x; const float* pb1 = &vreg[3].x;
        #pragma unroll
        for (int i = 0; i < 4; i++) {
            uint32_t hw, lw;
            split2(pa0[i], pb0[i], hw, lw);
            Vth[boff(vfb + i) + vkp] = hw; Vtl[boff(vfb + i) + vkp] = lw;
            split2(pa1[i], pb1[i], hw, lw);
            Vth[boff(vfb + 4 + i) + vkp] = hw; Vtl[boff(vfb + 4 + i) + vkp] = lw;
        }
    };

    int blist[2]; int nblk;
    if (p < 16) { blist[0] = p; blist[1] = 31 - p; nblk = 2; }
    else        { blist[0] = 32; nblk = 1; }

    for (int bi = 0; bi < nblk; bi++) {
        const int b = blist[bi];
        const int i0 = b * 64;
        const int validRows = min(64, TT - i0);
        const int njt = (b < 32) ? (b + 1) : 33;

        __syncthreads();
        for (int t = tid; t < 64 * 16; t += 256) {
            int r = t >> 4, c4 = (t & 15) * 4;
            int grow = i0 + r;
            float4 q = make_float4(0.f, 0.f, 0.f, 0.f);
            if (grow < TT)
                q = *(const float4*)(heads + (size_t)grow * (3 * DM) + h * DH + c4);
            float4 bw = *(const float4*)(rwb + h * DH + c4);
            float4 br = *(const float4*)(rrb + h * DH + c4);
            int wi = boff(r) + (c4 >> 1);
            uint32_t hw, lw;
            split2(q.x + bw.x, q.y + bw.y, hw, lw); Qwh[wi] = hw;     Qwl[wi] = lw;
            split2(q.z + bw.z, q.w + bw.w, hw, lw); Qwh[wi + 1] = hw; Qwl[wi + 1] = lw;
            split2(q.x + br.x, q.y + br.y, hw, lw); Qrh[wi] = hw;     Qrl[wi] = lw;
            split2(q.z + br.z, q.w + br.w, hw, lw); Qrh[wi + 1] = hw; Qrl[wi + 1] = lw;
        }
        prefetchKV(0);

        float o[4][4];
        #pragma unroll
        for (int a = 0; a < 4; a++) { o[a][0] = o[a][1] = o[a][2] = o[a][3] = 0.f; }
        float mrow[2] = {-1e30f, -1e30f};
        float lrow[2] = {0.f, 0.f};

        int nextChunk = (2016 - i0) / 64;
        if (nextChunk < 0) nextChunk = 0;

        for (int jt = 0; jt < njt; jt++) {
            const int j0 = jt * 64;

            const int hiJr = min(TT - 1, TT - 1 - i0 + j0 + 63);
            const int chi = hiJr >> 6;
            while (nextChunk <= chi) {
                const int c = nextChunk;
                __syncthreads();
                for (int t = tid; t < 64 * 16; t += 256) {
                    int r = t >> 4, c4 = (t & 15) * 4;
                    int grow = c * 64 + r;
                    float4 v = make_float4(0.f, 0.f, 0.f, 0.f);
                    if (grow < TT)
                        v = *(const float4*)(rbuf + (size_t)grow * DM + h * DH + c4);
                    int wi = boff(r) + (c4 >> 1);
                    uint32_t hw, lw;
                    split2(v.x, v.y, hw, lw); Rh[wi] = hw;     Rl[wi] = lw;
                    split2(v.z, v.w, hw, lw); Rh[wi + 1] = hw; Rl[wi + 1] = lw;
                }
                __syncthreads();
                float cacc[4][4];
                #pragma unroll
                for (int a = 0; a < 4; a++)
                    cacc[a][0] = cacc[a][1] = cacc[a][2] = cacc[a][3] = 0.f;
                #pragma unroll
                for (int kc = 0; kc < 4; kc++) {
                    uint32_t ah[4], al[4];
                    ldsm4(ah, adQrh + kc * 32);
                    ldsm4(al, adQrl + kc * 32);
                    uint32_t bh[2][4], bl[2][4];
                    ldsm4(bh[0], adRh0 + kc * 32);
                    ldsm4(bh[1], adRh1 + kc * 32);
                    ldsm4(bl[0], adRl0 + kc * 32);
                    ldsm4(bl[1], adRl1 + kc * 32);
                    #pragma unroll
                    for (int an = 0; an < 4; an++) {
                        const int g = an >> 1, x = (an & 1) * 2;
                        mma16(cacc[an], ah, bh[g][x], bh[g][x + 1]);
                        mma16(cacc[an], ah, bl[g][x], bl[g][x + 1]);
                        mma16(cacc[an], al, bh[g][x], bh[g][x + 1]);
                    }
                }
                float* slot = Ring + (c % 3) * RSLOT;
                #pragma unroll
                for (int an = 0; an < 4; an++) {
                    int col = colbase + an * 8 + 2 * l4;
                    slot[wr0 * RPAD + col]           = cacc[an][0];
                    slot[wr0 * RPAD + col + 1]       = cacc[an][1];
                    slot[(wr0 + 8) * RPAD + col]     = cacc[an][2];
                    slot[(wr0 + 8) * RPAD + col + 1] = cacc[an][3];
                }
                nextChunk++;
            }

            __syncthreads();
            storeKV();
            __syncthreads();

            float s[4][4];
            #pragma unroll
            for (int a = 0; a < 4; a++)
                s[a][0] = s[a][1] = s[a][2] = s[a][3] = 0.f;
            #pragma unroll
            for (int kc = 0; kc < 4; kc++) {
                uint32_t ah[4], al[4];
                ldsm4(ah, adQwh + kc * 32);
                ldsm4(al, adQwl + kc * 32);
                uint32_t bh[2][4], bl[2][4];
                ldsm4(bh[0], adKh0 + kc * 32);
                ldsm4(bh[1], adKh1 + kc * 32);
                ldsm4(bl[0], adKl0 + kc * 32);
                ldsm4(bl[1], adKl1 + kc * 32);
                #pragma unroll
                for (int an = 0; an < 4; an++) {
                    const int g = an >> 1, x = (an & 1) * 2;
                    mma16(s[an], ah, bh[g][x], bh[g][x + 1]);
                    mma16(s[an], ah, bl[g][x], bl[g][x + 1]);
                    mma16(s[an], al, bh[g][x], bh[g][x + 1]);
                }
            }

            float tmax[2] = {-1e30f, -1e30f};
            #pragma unroll
            for (int an = 0; an < 4; an++) {
                #pragma unroll
                for (int e = 0; e < 4; e++) {
                    int rh = e >> 1;
                    int di = wr0 + rh * 8;
                    int dj = colbase + an * 8 + 2 * l4 + (e & 1);
                    int i = i0 + di, j = j0 + dj;
                    float v = -1e30f;
                    if (di < validRows && j < TT) {
                        int jmaxr = (i < NMTOK) ? (NMTOK - 1)
                                  : ((i >= TT - NMTOK) ? (TT - 1) : i);
                        if (j <= jmaxr) {
                            float bd;
                            if (j <= i) {
                                int jr = TT - 1 - i + j;
                                bd = Ring[((jr >> 6) % 3) * RSLOT + di * RPAD + (jr & 63)];
                            } else if (j == i + 1) {
                                bd = 0.f;
                            } else {
                                const float* rr = rbuf + (size_t)(j - i - 2) * DM + h * DH;
                                float accd = 0.f;
                                #pragma unroll 8
                                for (int d2 = 0; d2 < 32; d2++) {
                                    uint32_t wh = Qrh[boff(di + 1) + d2];
                                    uint32_t wl = Qrl[boff(di + 1) + d2];
                                    __nv_bfloat162 h2 = *reinterpret_cast<__nv_bfloat162*>(&wh);
                                    __nv_bfloat162 l2 = *reinterpret_cast<__nv_bfloat162*>(&wl);
                                    float q0 = __bfloat162float(h2.x) + __bfloat162float(l2.x);
                                    float q1 = __bfloat162float(h2.y) + __bfloat162float(l2.y);
                                    accd += q0 * rr[2 * d2] + q1 * rr[2 * d2 + 1];
                                }
                                bd = accd;
                            }
                            v = (s[an][e] + bd) * 0.125f;
                        }
                    }
                    s[an][e] = v;
                    tmax[rh] = fmaxf(tmax[rh], v);
                }
            }
            #pragma unroll
            for (int rh = 0; rh < 2; rh++) {
                tmax[rh] = fmaxf(tmax[rh], __shfl_xor_sync(0xffffffffu, tmax[rh], 1));
                tmax[rh] = fmaxf(tmax[rh], __shfl_xor_sync(0xffffffffu, tmax[rh], 2));
            }
            if (l4 == 0) {
                redm[wn * 64 + wm * 16 + g4]     = tmax[0];
                redm[wn * 64 + wm * 16 + g4 + 8] = tmax[1];
            }
            __syncthreads();

            float scl[2], lsum[2] = {0.f, 0.f};
            #pragma unroll
            for (int rh = 0; rh < 2; rh++) {
                int row = wm * 16 + g4 + rh * 8;
                float tm = fmaxf(redm[row], redm[64 + row]);
                float mnew = fmaxf(mrow[rh], tm);
                scl[rh] = expf(mrow[rh] - mnew);
                mrow[rh] = mnew;
            }
            #pragma unroll
            for (int an = 0; an < 4; an++) {
                #pragma unroll
                for (int e = 0; e < 4; e++) {
                    int rh = e >> 1;
                    float ev = expf(s[an][e] - mrow[rh]);
                    s[an][e] = ev;
                    lsum[rh] += ev;
                }
            }
            #pragma unroll
            for (int rh = 0; rh < 2; rh++) {
                lsum[rh] += __shfl_xor_sync(0xffffffffu, lsum[rh], 1);
                lsum[rh] += __shfl_xor_sync(0xffffffffu, lsum[rh], 2);
            }
            if (l4 == 0) {
                reds[wn * 64 + wm * 16 + g4]     = lsum[0];
                reds[wn * 64 + wm * 16 + g4 + 8] = lsum[1];
            }
            #pragma unroll
            for (int an = 0; an < 4; an++) {
                int cp = (colbase >> 1) + an * 4 + l4;
                uint32_t hw, lw;
                split2(s[an][0], s[an][1], hw, lw);
                Ph[boff(wr0) + cp] = hw; Pl[boff(wr0) + cp] = lw;
                split2(s[an][2], s[an][3], hw, lw);
                Ph[boff(wr0 + 8) + cp] = hw; Pl[boff(wr0 + 8) + cp] = lw;
            }
            __syncthreads();

            #pragma unroll
            for (int rh = 0; rh < 2; rh++) {
                int row = wm * 16 + g4 + rh * 8;
                lrow[rh] = lrow[rh] * scl[rh] + reds[row] + reds[64 + row];
            }
            #pragma unroll
            for (int an = 0; an < 4; an++) {
                o[an][0] *= scl[0]; o[an][1] *= scl[0];
                o[an][2] *= scl[1]; o[an][3] *= scl[1];
            }

            #pragma unroll
            for (int kc = 0; kc < 4; kc++) {
                uint32_t ah[4], al[4];
                ldsm4(ah, adPh + kc * 32);
                ldsm4(al, adPl + kc * 32);
                uint32_t bh[2][4], bl[2][4];
                ldsm4(bh[0], adVh0 + kc * 32);
                ldsm4(bh[1], adVh1 + kc * 32);
                ldsm4(bl[0], adVl0 + kc * 32);
                ldsm4(bl[1], adVl1 + kc * 32);
                #pragma unroll
                for (int an = 0; an < 4; an++) {
                    const int g = an >> 1, x = (an & 1) * 2;
                    mma16(o[an], ah, bh[g][x], bh[g][x + 1]);
                    mma16(o[an], ah, bl[g][x], bl[g][x + 1]);
                    mma16(o[an], al, bh[g][x], bh[g][x + 1]);
                }
            }

            if (jt + 1 < njt) prefetchKV((jt + 1) * 64);
        } // j-tiles

        float inv0 = 1.f / lrow[0], inv1 = 1.f / lrow[1];
        #pragma unroll
        for (int an = 0; an < 4; an++) {
            int colw = (h * DH + colbase + an * 8 + 2 * l4) >> 1;
            int r0 = i0 + wr0;
            uint32_t hw, lw;
            if (wr0 < validRows) {
                split2(o[an][0] * inv0, o[an][1] * inv0, hw, lw);
                avPh[(size_t)r0 * 256 + colw] = hw;
                avPl[(size_t)r0 * 256 + colw] = lw;
            }
            if (wr0 + 8 < validRows) {
                split2(o[an][2] * inv1, o[an][3] * inv1, hw, lw);
                avPh[(size_t)(r0 + 8) * 256 + colw] = hw;
                avPl[(size_t)(r0 + 8) * 256 + colw] = lw;
            }
        }
    } // blocks
}

// ---------------- residual add + layernorm (pair threads; emits w planes) ----------------
__global__ void add_ln_kernel(float* __restrict__ w, const float* __restrict__ delta,
                              const float* __restrict__ delta2,
                              const float* __restrict__ gam, const float* __restrict__ bta) {
    int row = blockIdx.x;
    int tid = threadIdx.x;
    int c = 2 * tid;
    __shared__ float red[256];
    float x0 = w[row * DM + c]     + delta[row * DM + c];
    float x1 = w[row * DM + c + 1] + delta[row * DM + c + 1];
    if (delta2) {
        x0 += delta2[row * DM + c];
        x1 += delta2[row * DM + c + 1];
    }
    red[tid] = x0 + x1; __syncthreads();
    for (int s = 128; s > 0; s >>= 1) {
        if (tid < s) red[tid] += red[tid + s];
        __syncthreads();
    }
    float mean = red[0] * (1.f / DM);
    __syncthreads();
    float d0 = x0 - mean, d1 = x1 - mean;
    red[tid] = d0 * d0 + d1 * d1; __syncthreads();
    for (int s = 128; s > 0; s >>= 1) {
        if (tid < s) red[tid] += red[tid + s];
        __syncthreads();
    }
    float inv = 1.f / sqrtf(red[0] * (1.f / DM) + 1e-5f);
    float y0 = d0 * inv * gam[c]     + bta[c];
    float y1 = d1 * inv * gam[c + 1] + bta[c + 1];
    w[row * DM + c]     = y0;
    w[row * DM + c + 1] = y1;
    uint32_t hw, lw;
    split2(y0, y1, hw, lw);
    wPh[row * 256 + tid] = hw;
    wPl[row * 256 + tid] = lw;
}

__global__ void copy_out_kernel(float* __restrict__ out) {
    int idx = blockIdx.x * blockDim.x + threadIdx.x;
    if (idx < TT * DM) out[idx] = g_w[idx];
}

// ---------------- launcher ----------------
extern "C" void kernel_launch(void* const* d_in, const int* in_sizes, int n_in,
                              void* d_out, int out_size) {
    (void)in_sizes; (void)n_in; (void)out_size;
    const float* word_emb = (const float*)d_in[0];
    const float* mem_tok  = (const float*)d_in[1];
    const float* Wqkv     = (const float*)d_in[2];
    const float* Wr       = (const float*)d_in[3];
    const float* Wo       = (const float*)d_in[4];
    const float* ln1s     = (const float*)d_in[5];
    const float* ln1b     = (const float*)d_in[6];
    const float* W1       = (const float*)d_in[7];
    const float* b1       = (const float*)d_in[8];
    const float* W2       = (const float*)d_in[9];
    const float* b2       = (const float*)d_in[10];
    const float* ln2s     = (const float*)d_in[11];
    const float* ln2b     = (const float*)d_in[12];
    const float* rwb      = (const float*)d_in[13];
    const float* rrb      = (const float*)d_in[14];

    float *g_w_p, *g_hd_p, *g_r_p, *g_tmp_p, *g_tmp2_p;
    cudaGetSymbolAddress((void**)&g_w_p,    g_w);
    cudaGetSymbolAddress((void**)&g_hd_p,   g_heads);
    cudaGetSymbolAddress((void**)&g_r_p,    g_r);
    cudaGetSymbolAddress((void**)&g_tmp_p,  g_tmp);
    cudaGetSymbolAddress((void**)&g_tmp2_p, g_tmp2);
    uint32_t *wPh_p, *wPl_p, *posPh_p, *posPl_p, *avPh_p, *avPl_p, *ff1Ph_p, *ff1Pl_p;
    cudaGetSymbolAddress((void**)&wPh_p,   wPh);
    cudaGetSymbolAddress((void**)&wPl_p,   wPl);
    cudaGetSymbolAddress((void**)&posPh_p, posPh);
    cudaGetSymbolAddress((void**)&posPl_p, posPl);
    cudaGetSymbolAddress((void**)&avPh_p,  avPh);
    cudaGetSymbolAddress((void**)&avPl_p,  avPl);
    cudaGetSymbolAddress((void**)&ff1Ph_p, ff1Ph);
    cudaGetSymbolAddress((void**)&ff1Pl_p, ff1Pl);
    uint32_t *qkvPh_p, *qkvPl_p, *wrPh_p, *wrPl_p, *woPh_p, *woPl_p, *w1Ph_p, *w1Pl_p, *w2Ph_p, *w2Pl_p;
    cudaGetSymbolAddress((void**)&qkvPh_p, qkvPh);
    cudaGetSymbolAddress((void**)&qkvPl_p, qkvPl);
    cudaGetSymbolAddress((void**)&wrPh_p,  wrPh);
    cudaGetSymbolAddress((void**)&wrPl_p,  wrPl);
    cudaGetSymbolAddress((void**)&woPh_p,  woPh);
    cudaGetSymbolAddress((void**)&woPl_p,  woPl);
    cudaGetSymbolAddress((void**)&w1Ph_p,  w1Ph);
    cudaGetSymbolAddress((void**)&w1Pl_p,  w1Pl);
    cudaGetSymbolAddress((void**)&w2Ph_p,  w2Ph);
    cudaGetSymbolAddress((void**)&w2Pl_p,  w2Pl);

    cudaFuncSetAttribute(fused_attn_kernel,
                         cudaFuncAttributeMaxDynamicSharedMemorySize, ATTN_SMEM);
    cudaFuncSetAttribute(mma_gemm,
                         cudaFuncAttributeMaxDynamicSharedMemorySize, GEMM_SMEM);

    // one-time weight conversion to planes
    convert_weight<<<dim3(1536 / 32, 512 / 64, NLAY), 256>>>(Wqkv, qkvPh_p, qkvPl_p, 512, 1536);
    convert_weight<<<dim3(512 / 32, 512 / 64, NLAY), 256>>>(Wr, wrPh_p, wrPl_p, 512, 512);
    convert_weight<<<dim3(512 / 32, 512 / 64, NLAY), 256>>>(Wo, woPh_p, woPl_p, 512, 512);
    convert_weight<<<dim3(2048 / 32, 512 / 64, NLAY), 256>>>(W1, w1Ph_p, w1Pl_p, 512, 2048);
    convert_weight<<<dim3(512 / 32, 2048 / 64, NLAY), 256>>>(W2, w2Ph_p, w2Pl_p, 2048, 512);

    build_w_kernel<<<(TT * 256 + 255) / 256, 256>>>(word_emb, mem_tok);
    build_pos_kernel<<<(TT * 256 + 255) / 256, 256>>>();

    const int MB = (TT + 127) / 128;   // 17

    for (int l = 0; l < NLAY; l++) {
        // QKV: heads(fp32) = w @ Wqkv[l]
        mma_gemm<<<dim3(24, MB, 1), 256, GEMM_SMEM>>>(
            wPh_p, wPl_p, 256,
            qkvPh_p + (size_t)l * 1536 * 256, qkvPl_p + (size_t)l * 1536 * 256, 256,
            g_hd_p, g_hd_p, nullptr, nullptr, 3 * DM,
            nullptr, 0, TT, 3 * DM, DM);
        // Wr: r(fp32) = pos @ Wr[l]
        mma_gemm<<<dim3(8, MB, 1), 256, GEMM_SMEM>>>(
            posPh_p, posPl_p, 256,
            wrPh_p + (size_t)l * 512 * 256, wrPl_p + (size_t)l * 512 * 256, 256,
            g_r_p, g_r_p, nullptr, nullptr, DM,
            nullptr, 0, TT, DM, DM);

        fused_attn_kernel<<<dim3(NH, 17), 256, ATTN_SMEM>>>(g_hd_p, g_r_p, rwb, rrb);

        // Wo: K-split z=2, fp32 partials
        mma_gemm<<<dim3(8, MB, 2), 256, GEMM_SMEM>>>(
            avPh_p, avPl_p, 256,
            woPh_p + (size_t)l * 512 * 256, woPl_p + (size_t)l * 512 * 256, 256,
            g_tmp_p, g_tmp2_p, nullptr, nullptr, DM,
            nullptr, 0, TT, DM, DM / 2);
        add_ln_kernel<<<TT, 256>>>(g_w_p, g_tmp_p, g_tmp2_p, ln1s + l * DM, ln1b + l * DM);
        // FFN1: plane output (bias+relu fused)
        mma_gemm<<<dim3(32, MB, 1), 256, GEMM_SMEM>>>(
            wPh_p, wPl_p, 256,
            w1Ph_p + (size_t)l * 2048 * 256, w1Pl_p + (size_t)l * 2048 * 256, 256,
            nullptr, nullptr, ff1Ph_p, ff1Pl_p, DI / 2,
            b1 + (size_t)l * DI, 1, TT, DI, DM);
        // FFN2: K-split z=2, fp32 partials
        mma_gemm<<<dim3(8, MB, 2), 256, GEMM_SMEM>>>(
            ff1Ph_p, ff1Pl_p, 1024,
            w2Ph_p + (size_t)l * 512 * 1024, w2Pl_p + (size_t)l * 512 * 1024, 1024,
            g_tmp_p, g_tmp2_p, nullptr, nullptr, DM,
            b2 + (size_t)l * DM, 0, TT, DM, DI / 2);
        add_ln_kernel<<<TT, 256>>>(g_w_p, g_tmp_p, g_tmp2_p, ln2s + l * DM, ln2b + l * DM);
    }

    copy_out_kernel<<<(TT * DM + 255) / 256, 256>>>((float*)d_out);
}

// round 12
// speedup vs baseline: 1.1119x; 1.0416x over previous
#include <cuda_runtime.h>
#include <cuda_bf16.h>
#include <math.h>
#include <stdint.h>

// ---------------- problem constants ----------------
#define TT    2080
#define DM    512
#define NH    8
#define DH    64
#define DI    2048
#define NLAY  4
#define NMTOK 16
#define QL    2048
#define VTKP  1056    // padded key-pair dim for Vt planes (33 tiles * 32)

// ---------------- fp32 scratch ----------------
__device__ float g_w[TT * DM];
__device__ float g_heads[TT * 3 * DM];
__device__ float g_r[TT * DM];
__device__ float g_tmp[TT * DM];
__device__ float g_tmp2[TT * DM];

// ---------------- bf16 hi/lo pair-plane scratch ----------------
__device__ uint32_t wPh[TT * 256],   wPl[TT * 256];
__device__ uint32_t posPh[TT * 256], posPl[TT * 256];
__device__ uint32_t avPh[TT * 256],  avPl[TT * 256];
__device__ uint32_t ff1Ph[TT * 1024], ff1Pl[TT * 1024];
__device__ uint32_t kPh[TT * 256],   kPl[TT * 256];     // K planes (pairs over d)
__device__ uint32_t rPh[TT * 256],   rPl[TT * 256];     // r planes (pairs over d)
__device__ uint32_t vtPh[NH * 64 * VTKP], vtPl[NH * 64 * VTKP]; // V transposed planes
__device__ uint32_t qkvPh[NLAY * 1536 * 256], qkvPl[NLAY * 1536 * 256];
__device__ uint32_t wrPh[NLAY * 512 * 256],   wrPl[NLAY * 512 * 256];
__device__ uint32_t woPh[NLAY * 512 * 256],   woPl[NLAY * 512 * 256];
__device__ uint32_t w1Ph[NLAY * 2048 * 256],  w1Pl[NLAY * 2048 * 256];
__device__ uint32_t w2Ph[NLAY * 512 * 1024],  w2Pl[NLAY * 512 * 1024];

// ---------------- bf16x3 helpers ----------------
__device__ __forceinline__ void split2(float x0, float x1, uint32_t& hw, uint32_t& lw) {
    __nv_bfloat162 h, l;
    h.x = __float2bfloat16(x0);
    h.y = __float2bfloat16(x1);
    l.x = __float2bfloat16(x0 - __bfloat162float(h.x));
    l.y = __float2bfloat16(x1 - __bfloat162float(h.y));
    hw = *reinterpret_cast<uint32_t*>(&h);
    lw = *reinterpret_cast<uint32_t*>(&l);
}

__device__ __forceinline__ void mma16(float (&c)[4], const uint32_t (&a)[4],
                                      uint32_t b0, uint32_t b1) {
    asm volatile(
        "mma.sync.aligned.m16n8k16.row.col.f32.bf16.bf16.f32 "
        "{%0,%1,%2,%3}, {%4,%5,%6,%7}, {%8,%9}, {%0,%1,%2,%3};"
        : "+f"(c[0]), "+f"(c[1]), "+f"(c[2]), "+f"(c[3])
        : "r"(a[0]), "r"(a[1]), "r"(a[2]), "r"(a[3]), "r"(b0), "r"(b1));
}

__device__ __forceinline__ uint32_t sm_u32(const void* p) {
    return (uint32_t)__cvta_generic_to_shared(p);
}

__device__ __forceinline__ void ldsm4(uint32_t (&r)[4], uint32_t a) {
    asm volatile("ldmatrix.sync.aligned.m8n8.x4.shared.b16 {%0,%1,%2,%3}, [%4];"
                 : "=r"(r[0]), "=r"(r[1]), "=r"(r[2]), "=r"(r[3]) : "r"(a));
}

__device__ __forceinline__ void cpa16(uint32_t dst, const void* src, int szok) {
    asm volatile("cp.async.cg.shared.global [%0], [%1], 16, %2;"
                 :: "r"(dst), "l"(src), "r"(szok));
}

// attention B-style pair-plane smem layout
__device__ __forceinline__ int boff(int n) { return n * 36 + ((n >> 3) << 2); }
#define BPLANE (64 * 36 + 32)

// ---------------- prep kernels ----------------
__global__ void build_w_kernel(const float* __restrict__ word_emb,
                               const float* __restrict__ mem) {
    int idx = blockIdx.x * blockDim.x + threadIdx.x;
    if (idx >= TT * 256) return;
    int row = idx >> 8, c2 = idx & 255;
    int c = 2 * c2;
    float v0, v1;
    if (row < NMTOK) {
        v0 = mem[row * DM + c]; v1 = mem[row * DM + c + 1];
    } else if (row < NMTOK + QL) {
        v0 = word_emb[(row - NMTOK) * DM + c]; v1 = word_emb[(row - NMTOK) * DM + c + 1];
    } else {
        v0 = mem[(row - NMTOK - QL) * DM + c]; v1 = mem[(row - NMTOK - QL) * DM + c + 1];
    }
    g_w[row * DM + c] = v0;
    g_w[row * DM + c + 1] = v1;
    uint32_t hw, lw;
    split2(v0, v1, hw, lw);
    wPh[idx] = hw; wPl[idx] = lw;
}

__global__ void build_pos_kernel() {
    int idx = blockIdx.x * blockDim.x + threadIdx.x;
    if (idx >= TT * 256) return;
    int row = idx >> 8, c2 = idx & 255;
    float v0, v1;
    #pragma unroll
    for (int u = 0; u < 2; u++) {
        int c = 2 * c2 + u;
        int f = (c < DM / 2) ? c : (c - DM / 2);
        double invf = exp(-((double)(2 * f) / (double)DM) * log(10000.0));
        double val = (double)(TT - 1 - row) * invf;
        float r = (float)((c < DM / 2) ? sin(val) : cos(val));
        if (u == 0) v0 = r; else v1 = r;
    }
    uint32_t hw, lw;
    split2(v0, v1, hw, lw);
    posPh[idx] = hw; posPl[idx] = lw;
}

// ---------------- weight convert: W[l][K][N] fp32 -> planes [l][N][K/2] ----------------
__global__ void convert_weight(const float* __restrict__ W,
                               uint32_t* __restrict__ Ph, uint32_t* __restrict__ Pl,
                               int K, int N) {
    __shared__ float S[64][33];
    const int l = blockIdx.z;
    const float* Wl = W + (size_t)l * K * N;
    const int Kw = K >> 1;
    uint32_t* PhL = Ph + (size_t)l * N * Kw;
    uint32_t* PlL = Pl + (size_t)l * N * Kw;
    const int n0 = blockIdx.x * 32, k0 = blockIdx.y * 64;
    const int t = threadIdx.x;
    {
        int n = t & 31, kk = t >> 5;
        #pragma unroll
        for (int i = 0; i < 8; i++)
            S[kk + 8 * i][n] = Wl[(size_t)(k0 + kk + 8 * i) * N + n0 + n];
    }
    __syncthreads();
    {
        int nn = t >> 3, kq = t & 7;
        uint32_t oh[4], ol[4];
        #pragma unroll
        for (int i = 0; i < 4; i++) {
            int kp = kq * 4 + i;
            split2(S[2 * kp][nn], S[2 * kp + 1][nn], oh[i], ol[i]);
        }
        size_t base = (size_t)(n0 + nn) * Kw + (k0 >> 1) + kq * 4;
        *reinterpret_cast<uint4*>(PhL + base) = *reinterpret_cast<uint4*>(oh);
        *reinterpret_cast<uint4*>(PlL + base) = *reinterpret_cast<uint4*>(ol);
    }
}

// ---------------- V transpose-convert: heads v fp32 -> Vt planes [h][feat][kp] ----------------
__global__ void convert_vt(const float* __restrict__ heads,
                           uint32_t* __restrict__ Vh, uint32_t* __restrict__ Vl) {
    __shared__ float S[64][65];
    const int jt = blockIdx.x, h = blockIdx.y;
    const int j0 = jt * 64, tid = threadIdx.x;
    for (int t = tid; t < 64 * 16; t += 256) {
        int r = t >> 4, c4 = (t & 15) * 4;
        int gj = j0 + r;
        float4 v = make_float4(0.f, 0.f, 0.f, 0.f);
        if (gj < TT)
            v = *(const float4*)(heads + (size_t)gj * 1536 + 1024 + h * 64 + c4);
        S[r][c4] = v.x; S[r][c4 + 1] = v.y; S[r][c4 + 2] = v.z; S[r][c4 + 3] = v.w;
    }
    __syncthreads();
    const int f = tid >> 2, wq = (tid & 3) * 8;
    size_t base = ((size_t)h * 64 + f) * VTKP + (j0 >> 1) + wq;
    #pragma unroll
    for (int i = 0; i < 8; i++) {
        int kp = wq + i;
        uint32_t hw, lw;
        split2(S[2 * kp][f], S[2 * kp + 1][f], hw, lw);
        Vh[base + i] = hw; Vl[base + i] = lw;
    }
}

// ---------------- GEMM: cp.async 3-stage pipeline ----------------
#define PPA 20
#define PPB 20
#define ASTG (128 * PPA)
#define BSTG (64 * PPB)
#define STG_W (2 * ASTG + 2 * BSTG)
#define NSTG 3
#define GEMM_SMEM (NSTG * STG_W * 4)

// outMode: 0=fp32, 1=planes, 2=both, 3=QKV special (cols 512..1023 planes, else fp32)
__global__ __launch_bounds__(256, 2)
void mma_gemm(const uint32_t* __restrict__ Ahg, const uint32_t* __restrict__ Alg, int ldaw,
              const uint32_t* __restrict__ Bhg, const uint32_t* __restrict__ Blg, int ldbw,
              float* __restrict__ C, float* __restrict__ C2, int ldc,
              uint32_t* __restrict__ OutH, uint32_t* __restrict__ OutL, int ldcw,
              const float* __restrict__ cbias, int doRelu, int outMode,
              int M, int N, int Ksub) {
    extern __shared__ uint32_t gsm[];
    const uint32_t smBase = sm_u32(gsm);

    const int bm = blockIdx.y * 128, bn = blockIdx.x * 64;
    const int kOffW = blockIdx.z * (Ksub >> 1);
    if (blockIdx.z == 1) C = C2;

    const int tid = threadIdx.x;
    const int lane = tid & 31, warp = tid >> 5;
    const int wm = warp & 3, wn = warp >> 2;
    const int g4 = lane >> 2, l4 = lane & 3;

    float acc[2][4][4] = {};

    const int arow = tid >> 2;
    const int akq = tid & 3;

    const int aRow = lane & 15;
    const uint32_t aHiB = ((lane >> 4) & 1) * 16;
    const uint32_t adA = smBase + (uint32_t)((wm * 32 + aRow) * PPA) * 4 + aHiB;
    const int bRowN = ((lane >> 4) & 1) * 8 + (lane & 7);
    const uint32_t bHiB = ((lane >> 3) & 1) * 16;
    const uint32_t adB0 = smBase + (uint32_t)(2 * ASTG + (wn * 32 + bRowN) * PPB) * 4 + bHiB;
    const uint32_t adB1 = adB0 + 16 * PPB * 4;

    const uint32_t dA = (uint32_t)(arow * PPA + akq * 4) * 4;
    const uint32_t dB = (uint32_t)(2 * ASTG + arow * PPB + akq * 4) * 4;

    auto issueStage = [&](int iter, int st) {
        const int kw = kOffW + iter * 16 + akq * 4;
        const uint32_t base = smBase + (uint32_t)st * (STG_W * 4);
        #pragma unroll
        for (int p = 0; p < 2; p++) {
            int row = bm + p * 64 + arow;
            int ok = (row < M) ? 16 : 0;
            int rowc = (row < M) ? row : 0;
            cpa16(base + dA + p * 64 * PPA * 4, Ahg + (size_t)rowc * ldaw + kw, ok);
            cpa16(base + dA + p * 64 * PPA * 4 + ASTG * 4, Alg + (size_t)rowc * ldaw + kw, ok);
        }
        {
            int row = bn + arow;
            cpa16(base + dB, Bhg + (size_t)row * ldbw + kw, 16);
            cpa16(base + dB + BSTG * 4, Blg + (size_t)row * ldbw + kw, 16);
        }
    };

    const int niter = Ksub >> 5;
    issueStage(0, 0);
    asm volatile("cp.async.commit_group;" ::: "memory");
    issueStage(1, 1);
    asm volatile("cp.async.commit_group;" ::: "memory");

    int st = 0;
    for (int i = 0; i < niter; i++) {
        asm volatile("cp.async.wait_group 1;" ::: "memory");
        __syncthreads();
        const uint32_t so = (uint32_t)st * (STG_W * 4);
        #pragma unroll
        for (int ks = 0; ks < 2; ks++) {
            uint32_t ahh[2][4], alo[2][4];
            ldsm4(ahh[0], adA + so + ks * 32);
            ldsm4(ahh[1], adA + so + 16 * PPA * 4 + ks * 32);
            ldsm4(alo[0], adA + so + ASTG * 4 + ks * 32);
            ldsm4(alo[1], adA + so + ASTG * 4 + 16 * PPA * 4 + ks * 32);
            uint32_t bhh[2][4], blo[2][4];
            ldsm4(bhh[0], adB0 + so + ks * 32);
            ldsm4(bhh[1], adB1 + so + ks * 32);
            ldsm4(blo[0], adB0 + so + BSTG * 4 + ks * 32);
            ldsm4(blo[1], adB1 + so + BSTG * 4 + ks * 32);
            #pragma unroll
            for (int am = 0; am < 2; am++)
                #pragma unroll
                for (int an = 0; an < 4; an++) {
                    const int g = an >> 1, x = (an & 1) * 2;
                    mma16(acc[am][an], ahh[am], bhh[g][x], bhh[g][x + 1]);
                    mma16(acc[am][an], ahh[am], blo[g][x], blo[g][x + 1]);
                    mma16(acc[am][an], alo[am], bhh[g][x], bhh[g][x + 1]);
                }
        }
        if (i + 2 < niter) {
            int st2 = st + 2; if (st2 >= NSTG) st2 -= NSTG;
            issueStage(i + 2, st2);
        }
        asm volatile("cp.async.commit_group;" ::: "memory");
        st = (st + 1 == NSTG) ? 0 : st + 1;
    }

    bool wantPlane, wantF32;
    if (outMode == 0)      { wantPlane = false; wantF32 = true; }
    else if (outMode == 1) { wantPlane = true;  wantF32 = false; }
    else if (outMode == 2) { wantPlane = true;  wantF32 = true; }
    else {
        bool isk = (bn >= 512 && bn < 1024);
        wantPlane = isk; wantF32 = !isk;
    }
    const int pShift = (outMode == 3) ? 512 : 0;

    #pragma unroll
    for (int am = 0; am < 2; am++) {
        int row0 = bm + wm * 32 + am * 16 + g4;
        #pragma unroll
        for (int an = 0; an < 4; an++) {
            int col0 = bn + wn * 32 + an * 8 + 2 * l4;
            float v0 = acc[am][an][0], v1 = acc[am][an][1];
            float v2 = acc[am][an][2], v3 = acc[am][an][3];
            if (cbias && blockIdx.z == 0) {
                float b0 = cbias[col0], b1 = cbias[col0 + 1];
                v0 += b0; v1 += b1; v2 += b0; v3 += b1;
            }
            if (doRelu) {
                v0 = fmaxf(v0, 0.f); v1 = fmaxf(v1, 0.f);
                v2 = fmaxf(v2, 0.f); v3 = fmaxf(v3, 0.f);
            }
            if (wantPlane) {
                uint32_t hw, lw;
                int colP = (col0 - pShift) >> 1;
                if (row0 < M) {
                    split2(v0, v1, hw, lw);
                    OutH[(size_t)row0 * ldcw + colP] = hw;
                    OutL[(size_t)row0 * ldcw + colP] = lw;
                }
                if (row0 + 8 < M) {
                    split2(v2, v3, hw, lw);
                    OutH[(size_t)(row0 + 8) * ldcw + colP] = hw;
                    OutL[(size_t)(row0 + 8) * ldcw + colP] = lw;
                }
            }
            if (wantF32) {
                if (row0 < M) {
                    C[(size_t)row0 * ldc + col0]     = v0;
                    C[(size_t)row0 * ldc + col0 + 1] = v1;
                }
                if (row0 + 8 < M) {
                    C[(size_t)(row0 + 8) * ldc + col0]     = v2;
                    C[(size_t)(row0 + 8) * ldc + col0 + 1] = v3;
                }
            }
        }
    }
}

// ---------------- fused flash-style relative attention (plane inputs) ----------------
#define RPAD 68
#define RSLOT (64 * RPAD)
#define ATTN_WORDS (12 * BPLANE + 3 * RSLOT + 256)
#define ATTN_SMEM (ATTN_WORDS * 4)

__global__ __launch_bounds__(256, 1)
void fused_attn_kernel(const float* __restrict__ heads,
                       const float* __restrict__ rbuf,
                       const uint32_t* __restrict__ kGh, const uint32_t* __restrict__ kGl,
                       const uint32_t* __restrict__ vGh, const uint32_t* __restrict__ vGl,
                       const uint32_t* __restrict__ rGh, const uint32_t* __restrict__ rGl,
                       const float* __restrict__ rwb,
                       const float* __restrict__ rrb) {
    extern __shared__ uint32_t smu[];
    uint32_t* Qwh = smu;
    uint32_t* Qwl = Qwh + BPLANE;
    uint32_t* Qrh = Qwl + BPLANE;
    uint32_t* Qrl = Qrh + BPLANE;
    uint32_t* Kh  = Qrl + BPLANE;
    uint32_t* Kl  = Kh  + BPLANE;
    uint32_t* Rh  = Kl  + BPLANE;
    uint32_t* Rl  = Rh  + BPLANE;
    uint32_t* Vth = Rl  + BPLANE;
    uint32_t* Vtl = Vth + BPLANE;
    uint32_t* Ph  = Vtl + BPLANE;
    uint32_t* Pl  = Ph  + BPLANE;
    float* Ring = (float*)(Pl + BPLANE);
    float* redm = Ring + 3 * RSLOT;
    float* reds = redm + 128;

    const int h = blockIdx.x;
    const int p = blockIdx.y;
    const int tid = threadIdx.x;
    const int lane = tid & 31, warp = tid >> 5;
    const int wm = warp & 3, wn = warp >> 2;
    const int g4 = lane >> 2, l4 = lane & 3;
    const int wr0 = wm * 16 + g4;
    const int colbase = wn * 32;

    const int aRow = lane & 15;
    const uint32_t aHiB = ((lane >> 4) & 1) * 16;
    const uint32_t aOff = (uint32_t)boff(wm * 16 + aRow) * 4 + aHiB;
    const uint32_t adQwh = sm_u32(Qwh) + aOff, adQwl = sm_u32(Qwl) + aOff;
    const uint32_t adQrh = sm_u32(Qrh) + aOff, adQrl = sm_u32(Qrl) + aOff;
    const uint32_t adPh  = sm_u32(Ph)  + aOff, adPl  = sm_u32(Pl)  + aOff;
    const int bRowN = ((lane >> 4) & 1) * 8 + (lane & 7);
    const uint32_t bHiB = ((lane >> 3) & 1) * 16;
    const uint32_t bO0 = (uint32_t)boff(colbase + bRowN) * 4 + bHiB;
    const uint32_t bO1 = (uint32_t)boff(colbase + 16 + bRowN) * 4 + bHiB;
    const uint32_t adKh0 = sm_u32(Kh) + bO0,  adKh1 = sm_u32(Kh) + bO1;
    const uint32_t adKl0 = sm_u32(Kl) + bO0,  adKl1 = sm_u32(Kl) + bO1;
    const uint32_t adRh0 = sm_u32(Rh) + bO0,  adRh1 = sm_u32(Rh) + bO1;
    const uint32_t adRl0 = sm_u32(Rl) + bO0,  adRl1 = sm_u32(Rl) + bO1;
    const uint32_t adVh0 = sm_u32(Vth) + bO0, adVh1 = sm_u32(Vth) + bO1;
    const uint32_t adVl0 = sm_u32(Vtl) + bO0, adVl1 = sm_u32(Vtl) + bO1;

    // K/V prefetch (pure uint4; planes pre-converted)
    uint4 pk[4], pv[4];
    const int prow = tid >> 2, pwq = (tid & 3) * 8;
    const size_t vtBase = ((size_t)h * 64 + prow) * VTKP;
    auto prefetchKV = [&](int j0) {
        int gj = j0 + prow;
        if (gj < TT) {
            const uint32_t* bh = kGh + (size_t)gj * 256 + h * 32 + pwq;
            const uint32_t* bl = kGl + (size_t)gj * 256 + h * 32 + pwq;
            pk[0] = *(const uint4*)bh;       pk[1] = *(const uint4*)(bh + 4);
            pk[2] = *(const uint4*)bl;       pk[3] = *(const uint4*)(bl + 4);
        } else {
            pk[0] = pk[1] = pk[2] = pk[3] = make_uint4(0, 0, 0, 0);
        }
        const uint32_t* vh = vGh + vtBase + (j0 >> 1) + pwq;
        const uint32_t* vl = vGl + vtBase + (j0 >> 1) + pwq;
        pv[0] = *(const uint4*)vh;           pv[1] = *(const uint4*)(vh + 4);
        pv[2] = *(const uint4*)vl;           pv[3] = *(const uint4*)(vl + 4);
    };
    auto storeKV = [&]() {
        int wi = boff(prow) + pwq;
        *(uint4*)(Kh + wi) = pk[0];  *(uint4*)(Kh + wi + 4) = pk[1];
        *(uint4*)(Kl + wi) = pk[2];  *(uint4*)(Kl + wi + 4) = pk[3];
        *(uint4*)(Vth + wi) = pv[0]; *(uint4*)(Vth + wi + 4) = pv[1];
        *(uint4*)(Vtl + wi) = pv[2]; *(uint4*)(Vtl + wi + 4) = pv[3];
    };

    int blist[2]; int nblk;
    if (p < 16) { blist[0] = p; blist[1] = 31 - p; nblk = 2; }
    else        { blist[0] = 32; nblk = 1; }

    for (int bi = 0; bi < nblk; bi++) {
        const int b = blist[bi];
        const int i0 = b * 64;
        const int validRows = min(64, TT - i0);
        const int njt = (b < 32) ? (b + 1) : 33;

        __syncthreads();
        for (int t = tid; t < 64 * 16; t += 256) {
            int r = t >> 4, c4 = (t & 15) * 4;
            int grow = i0 + r;
            float4 q = make_float4(0.f, 0.f, 0.f, 0.f);
            if (grow < TT)
                q = *(const float4*)(heads + (size_t)grow * (3 * DM) + h * DH + c4);
            float4 bw = *(const float4*)(rwb + h * DH + c4);
            float4 br = *(const float4*)(rrb + h * DH + c4);
            int wi = boff(r) + (c4 >> 1);
            uint32_t hw, lw;
            split2(q.x + bw.x, q.y + bw.y, hw, lw); Qwh[wi] = hw;     Qwl[wi] = lw;
            split2(q.z + bw.z, q.w + bw.w, hw, lw); Qwh[wi + 1] = hw; Qwl[wi + 1] = lw;
            split2(q.x + br.x, q.y + br.y, hw, lw); Qrh[wi] = hw;     Qrl[wi] = lw;
            split2(q.z + br.z, q.w + br.w, hw, lw); Qrh[wi + 1] = hw; Qrl[wi + 1] = lw;
        }
        prefetchKV(0);

        float o[4][4];
        #pragma unroll
        for (int a = 0; a < 4; a++) { o[a][0] = o[a][1] = o[a][2] = o[a][3] = 0.f; }
        float mrow[2] = {-1e30f, -1e30f};
        float lrow[2] = {0.f, 0.f};

        int nextChunk = (2016 - i0) / 64;
        if (nextChunk < 0) nextChunk = 0;

        for (int jt = 0; jt < njt; jt++) {
            const int j0 = jt * 64;

            const int hiJr = min(TT - 1, TT - 1 - i0 + j0 + 63);
            const int chi = hiJr >> 6;
            while (nextChunk <= chi) {
                const int c = nextChunk;
                __syncthreads();
                {   // load r chunk from planes
                    int grow = c * 64 + prow;
                    uint4 r0 = make_uint4(0,0,0,0), r1 = r0, r2 = r0, r3 = r0;
                    if (grow < TT) {
                        const uint32_t* bh = rGh + (size_t)grow * 256 + h * 32 + pwq;
                        const uint32_t* bl = rGl + (size_t)grow * 256 + h * 32 + pwq;
                        r0 = *(const uint4*)bh; r1 = *(const uint4*)(bh + 4);
                        r2 = *(const uint4*)bl; r3 = *(const uint4*)(bl + 4);
                    }
                    int wi = boff(prow) + pwq;
                    *(uint4*)(Rh + wi) = r0; *(uint4*)(Rh + wi + 4) = r1;
                    *(uint4*)(Rl + wi) = r2; *(uint4*)(Rl + wi + 4) = r3;
                }
                __syncthreads();
                float cacc[4][4];
                #pragma unroll
                for (int a = 0; a < 4; a++)
                    cacc[a][0] = cacc[a][1] = cacc[a][2] = cacc[a][3] = 0.f;
                #pragma unroll
                for (int kc = 0; kc < 4; kc++) {
                    uint32_t ah[4], al[4];
                    ldsm4(ah, adQrh + kc * 32);
                    ldsm4(al, adQrl + kc * 32);
                    uint32_t bh[2][4], bl[2][4];
                    ldsm4(bh[0], adRh0 + kc * 32);
                    ldsm4(bh[1], adRh1 + kc * 32);
                    ldsm4(bl[0], adRl0 + kc * 32);
                    ldsm4(bl[1], adRl1 + kc * 32);
                    #pragma unroll
                    for (int an = 0; an < 4; an++) {
                        const int g = an >> 1, x = (an & 1) * 2;
                        mma16(cacc[an], ah, bh[g][x], bh[g][x + 1]);
                        mma16(cacc[an], ah, bl[g][x], bl[g][x + 1]);
                        mma16(cacc[an], al, bh[g][x], bh[g][x + 1]);
                    }
                }
                float* slot = Ring + (c % 3) * RSLOT;
                #pragma unroll
                for (int an = 0; an < 4; an++) {
                    int col = colbase + an * 8 + 2 * l4;
                    slot[wr0 * RPAD + col]           = cacc[an][0];
                    slot[wr0 * RPAD + col + 1]       = cacc[an][1];
                    slot[(wr0 + 8) * RPAD + col]     = cacc[an][2];
                    slot[(wr0 + 8) * RPAD + col + 1] = cacc[an][3];
                }
                nextChunk++;
            }

            __syncthreads();
            storeKV();
            __syncthreads();

            float s[4][4];
            #pragma unroll
            for (int a = 0; a < 4; a++)
                s[a][0] = s[a][1] = s[a][2] = s[a][3] = 0.f;
            #pragma unroll
            for (int kc = 0; kc < 4; kc++) {
                uint32_t ah[4], al[4];
                ldsm4(ah, adQwh + kc * 32);
                ldsm4(al, adQwl + kc * 32);
                uint32_t bh[2][4], bl[2][4];
                ldsm4(bh[0], adKh0 + kc * 32);
                ldsm4(bh[1], adKh1 + kc * 32);
                ldsm4(bl[0], adKl0 + kc * 32);
                ldsm4(bl[1], adKl1 + kc * 32);
                #pragma unroll
                for (int an = 0; an < 4; an++) {
                    const int g = an >> 1, x = (an & 1) * 2;
                    mma16(s[an], ah, bh[g][x], bh[g][x + 1]);
                    mma16(s[an], ah, bl[g][x], bl[g][x + 1]);
                    mma16(s[an], al, bh[g][x], bh[g][x + 1]);
                }
            }

            float tmax[2] = {-1e30f, -1e30f};
            #pragma unroll
            for (int an = 0; an < 4; an++) {
                #pragma unroll
                for (int e = 0; e < 4; e++) {
                    int rh = e >> 1;
                    int di = wr0 + rh * 8;
                    int dj = colbase + an * 8 + 2 * l4 + (e & 1);
                    int i = i0 + di, j = j0 + dj;
                    float v = -1e30f;
                    if (di < validRows && j < TT) {
                        int jmaxr = (i < NMTOK) ? (NMTOK - 1)
                                  : ((i >= TT - NMTOK) ? (TT - 1) : i);
                        if (j <= jmaxr) {
                            float bd;
                            if (j <= i) {
                                int jr = TT - 1 - i + j;
                                bd = Ring[((jr >> 6) % 3) * RSLOT + di * RPAD + (jr & 63)];
                            } else if (j == i + 1) {
                                bd = 0.f;
                            } else {
                                const float* rr = rbuf + (size_t)(j - i - 2) * DM + h * DH;
                                float accd = 0.f;
                                #pragma unroll 8
                                for (int d2 = 0; d2 < 32; d2++) {
                                    uint32_t wh = Qrh[boff(di + 1) + d2];
                                    uint32_t wl = Qrl[boff(di + 1) + d2];
                                    __nv_bfloat162 h2 = *reinterpret_cast<__nv_bfloat162*>(&wh);
                                    __nv_bfloat162 l2 = *reinterpret_cast<__nv_bfloat162*>(&wl);
                                    float q0 = __bfloat162float(h2.x) + __bfloat162float(l2.x);
                                    float q1 = __bfloat162float(h2.y) + __bfloat162float(l2.y);
                                    accd += q0 * rr[2 * d2] + q1 * rr[2 * d2 + 1];
                                }
                                bd = accd;
                            }
                            v = (s[an][e] + bd) * 0.125f;
                        }
                    }
                    s[an][e] = v;
                    tmax[rh] = fmaxf(tmax[rh], v);
                }
            }
            #pragma unroll
            for (int rh = 0; rh < 2; rh++) {
                tmax[rh] = fmaxf(tmax[rh], __shfl_xor_sync(0xffffffffu, tmax[rh], 1));
                tmax[rh] = fmaxf(tmax[rh], __shfl_xor_sync(0xffffffffu, tmax[rh], 2));
            }
            if (l4 == 0) {
                redm[wn * 64 + wm * 16 + g4]     = tmax[0];
                redm[wn * 64 + wm * 16 + g4 + 8] = tmax[1];
            }
            __syncthreads();

            float scl[2], lsum[2] = {0.f, 0.f};
            #pragma unroll
            for (int rh = 0; rh < 2; rh++) {
                int row = wm * 16 + g4 + rh * 8;
                float tm = fmaxf(redm[row], redm[64 + row]);
                float mnew = fmaxf(mrow[rh], tm);
                scl[rh] = expf(mrow[rh] - mnew);
                mrow[rh] = mnew;
            }
            #pragma unroll
            for (int an = 0; an < 4; an++) {
                #pragma unroll
                for (int e = 0; e < 4; e++) {
                    int rh = e >> 1;
                    float ev = expf(s[an][e] - mrow[rh]);
                    s[an][e] = ev;
                    lsum[rh] += ev;
                }
            }
            #pragma unroll
            for (int rh = 0; rh < 2; rh++) {
                lsum[rh] += __shfl_xor_sync(0xffffffffu, lsum[rh], 1);
                lsum[rh] += __shfl_xor_sync(0xffffffffu, lsum[rh], 2);
            }
            if (l4 == 0) {
                reds[wn * 64 + wm * 16 + g4]     = lsum[0];
                reds[wn * 64 + wm * 16 + g4 + 8] = lsum[1];
            }
            #pragma unroll
            for (int an = 0; an < 4; an++) {
                int cp = (colbase >> 1) + an * 4 + l4;
                uint32_t hw, lw;
                split2(s[an][0], s[an][1], hw, lw);
                Ph[boff(wr0) + cp] = hw; Pl[boff(wr0) + cp] = lw;
                split2(s[an][2], s[an][3], hw, lw);
                Ph[boff(wr0 + 8) + cp] = hw; Pl[boff(wr0 + 8) + cp] = lw;
            }
            __syncthreads();

            #pragma unroll
            for (int rh = 0; rh < 2; rh++) {
                int row = wm * 16 + g4 + rh * 8;
                lrow[rh] = lrow[rh] * scl[rh] + reds[row] + reds[64 + row];
            }
            #pragma unroll
            for (int an = 0; an < 4; an++) {
                o[an][0] *= scl[0]; o[an][1] *= scl[0];
                o[an][2] *= scl[1]; o[an][3] *= scl[1];
            }

            #pragma unroll
            for (int kc = 0; kc < 4; kc++) {
                uint32_t ah[4], al[4];
                ldsm4(ah, adPh + kc * 32);
                ldsm4(al, adPl + kc * 32);
                uint32_t bh[2][4], bl[2][4];
                ldsm4(bh[0], adVh0 + kc * 32);
                ldsm4(bh[1], adVh1 + kc * 32);
                ldsm4(bl[0], adVl0 + kc * 32);
                ldsm4(bl[1], adVl1 + kc * 32);
                #pragma unroll
                for (int an = 0; an < 4; an++) {
                    const int g = an >> 1, x = (an & 1) * 2;
                    mma16(o[an], ah, bh[g][x], bh[g][x + 1]);
                    mma16(o[an], ah, bl[g][x], bl[g][x + 1]);
                    mma16(o[an], al, bh[g][x], bh[g][x + 1]);
                }
            }

            if (jt + 1 < njt) prefetchKV((jt + 1) * 64);
        } // j-tiles

        float inv0 = 1.f / lrow[0], inv1 = 1.f / lrow[1];
        #pragma unroll
        for (int an = 0; an < 4; an++) {
            int colw = (h * DH + colbase + an * 8 + 2 * l4) >> 1;
            int r0 = i0 + wr0;
            uint32_t hw, lw;
            if (wr0 < validRows) {
                split2(o[an][0] * inv0, o[an][1] * inv0, hw, lw);
                avPh[(size_t)r0 * 256 + colw] = hw;
                avPl[(size_t)r0 * 256 + colw] = lw;
            }
            if (wr0 + 8 < validRows) {
                split2(o[an][2] * inv1, o[an][3] * inv1, hw, lw);
                avPh[(size_t)(r0 + 8) * 256 + colw] = hw;
                avPl[(size_t)(r0 + 8) * 256 + colw] = lw;
            }
        }
    } // blocks
}

// ---------------- residual add + layernorm (emits w planes) ----------------
__global__ void add_ln_kernel(float* __restrict__ w, const float* __restrict__ delta,
                              const float* __restrict__ delta2,
                              const float* __restrict__ gam, const float* __restrict__ bta) {
    int row = blockIdx.x;
    int tid = threadIdx.x;
    int c = 2 * tid;
    __shared__ float red[256];
    float x0 = w[row * DM + c]     + delta[row * DM + c];
    float x1 = w[row * DM + c + 1] + delta[row * DM + c + 1];
    if (delta2) {
        x0 += delta2[row * DM + c];
        x1 += delta2[row * DM + c + 1];
    }
    red[tid] = x0 + x1; __syncthreads();
    for (int s = 128; s > 0; s >>= 1) {
        if (tid < s) red[tid] += red[tid + s];
        __syncthreads();
    }
    float mean = red[0] * (1.f / DM);
    __syncthreads();
    float d0 = x0 - mean, d1 = x1 - mean;
    red[tid] = d0 * d0 + d1 * d1; __syncthreads();
    for (int s = 128; s > 0; s >>= 1) {
        if (tid < s) red[tid] += red[tid + s];
        __syncthreads();
    }
    float inv = 1.f / sqrtf(red[0] * (1.f / DM) + 1e-5f);
    float y0 = d0 * inv * gam[c]     + bta[c];
    float y1 = d1 * inv * gam[c + 1] + bta[c + 1];
    w[row * DM + c]     = y0;
    w[row * DM + c + 1] = y1;
    uint32_t hw, lw;
    split2(y0, y1, hw, lw);
    wPh[row * 256 + tid] = hw;
    wPl[row * 256 + tid] = lw;
}

__global__ void copy_out_kernel(float* __restrict__ out) {
    int idx = blockIdx.x * blockDim.x + threadIdx.x;
    if (idx < TT * DM) out[idx] = g_w[idx];
}

// ---------------- launcher ----------------
extern "C" void kernel_launch(void* const* d_in, const int* in_sizes, int n_in,
                              void* d_out, int out_size) {
    (void)in_sizes; (void)n_in; (void)out_size;
    const float* word_emb = (const float*)d_in[0];
    const float* mem_tok  = (const float*)d_in[1];
    const float* Wqkv     = (const float*)d_in[2];
    const float* Wr       = (const float*)d_in[3];
    const float* Wo       = (const float*)d_in[4];
    const float* ln1s     = (const float*)d_in[5];
    const float* ln1b     = (const float*)d_in[6];
    const float* W1       = (const float*)d_in[7];
    const float* b1       = (const float*)d_in[8];
    const float* W2       = (const float*)d_in[9];
    const float* b2       = (const float*)d_in[10];
    const float* ln2s     = (const float*)d_in[11];
    const float* ln2b     = (const float*)d_in[12];
    const float* rwb      = (const float*)d_in[13];
    const float* rrb      = (const float*)d_in[14];

    float *g_w_p, *g_hd_p, *g_r_p, *g_tmp_p, *g_tmp2_p;
    cudaGetSymbolAddress((void**)&g_w_p,    g_w);
    cudaGetSymbolAddress((void**)&g_hd_p,   g_heads);
    cudaGetSymbolAddress((void**)&g_r_p,    g_r);
    cudaGetSymbolAddress((void**)&g_tmp_p,  g_tmp);
    cudaGetSymbolAddress((void**)&g_tmp2_p, g_tmp2);
    uint32_t *wPh_p, *wPl_p, *posPh_p, *posPl_p, *avPh_p, *avPl_p, *ff1Ph_p, *ff1Pl_p;
    uint32_t *kPh_p, *kPl_p, *rPh_p, *rPl_p, *vtPh_p, *vtPl_p;
    cudaGetSymbolAddress((void**)&wPh_p,   wPh);
    cudaGetSymbolAddress((void**)&wPl_p,   wPl);
    cudaGetSymbolAddress((void**)&posPh_p, posPh);
    cudaGetSymbolAddress((void**)&posPl_p, posPl);
    cudaGetSymbolAddress((void**)&avPh_p,  avPh);
    cudaGetSymbolAddress((void**)&avPl_p,  avPl);
    cudaGetSymbolAddress((void**)&ff1Ph_p, ff1Ph);
    cudaGetSymbolAddress((void**)&ff1Pl_p, ff1Pl);
    cudaGetSymbolAddress((void**)&kPh_p,   kPh);
    cudaGetSymbolAddress((void**)&kPl_p,   kPl);
    cudaGetSymbolAddress((void**)&rPh_p,   rPh);
    cudaGetSymbolAddress((void**)&rPl_p,   rPl);
    cudaGetSymbolAddress((void**)&vtPh_p,  vtPh);
    cudaGetSymbolAddress((void**)&vtPl_p,  vtPl);
    uint32_t *qkvPh_p, *qkvPl_p, *wrPh_p, *wrPl_p, *woPh_p, *woPl_p, *w1Ph_p, *w1Pl_p, *w2Ph_p, *w2Pl_p;
    cudaGetSymbolAddress((void**)&qkvPh_p, qkvPh);
    cudaGetSymbolAddress((void**)&qkvPl_p, qkvPl);
    cudaGetSymbolAddress((void**)&wrPh_p,  wrPh);
    cudaGetSymbolAddress((void**)&wrPl_p,  wrPl);
    cudaGetSymbolAddress((void**)&woPh_p,  woPh);
    cudaGetSymbolAddress((void**)&woPl_p,  woPl);
    cudaGetSymbolAddress((void**)&w1Ph_p,  w1Ph);
    cudaGetSymbolAddress((void**)&w1Pl_p,  w1Pl);
    cudaGetSymbolAddress((void**)&w2Ph_p,  w2Ph);
    cudaGetSymbolAddress((void**)&w2Pl_p,  w2Pl);

    cudaFuncSetAttribute(fused_attn_kernel,
                         cudaFuncAttributeMaxDynamicSharedMemorySize, ATTN_SMEM);
    cudaFuncSetAttribute(mma_gemm,
                         cudaFuncAttributeMaxDynamicSharedMemorySize, GEMM_SMEM);

    convert_weight<<<dim3(1536 / 32, 512 / 64, NLAY), 256>>>(Wqkv, qkvPh_p, qkvPl_p, 512, 1536);
    convert_weight<<<dim3(512 / 32, 512 / 64, NLAY), 256>>>(Wr, wrPh_p, wrPl_p, 512, 512);
    convert_weight<<<dim3(512 / 32, 512 / 64, NLAY), 256>>>(Wo, woPh_p, woPl_p, 512, 512);
    convert_weight<<<dim3(2048 / 32, 512 / 64, NLAY), 256>>>(W1, w1Ph_p, w1Pl_p, 512, 2048);
    convert_weight<<<dim3(512 / 32, 2048 / 64, NLAY), 256>>>(W2, w2Ph_p, w2Pl_p, 2048, 512);

    build_w_kernel<<<(TT * 256 + 255) / 256, 256>>>(word_emb, mem_tok);
    build_pos_kernel<<<(TT * 256 + 255) / 256, 256>>>();

    const int MB = (TT + 127) / 128;   // 17

    for (int l = 0; l < NLAY; l++) {
        // QKV: q,v fp32; k region emitted as planes (outMode 3)
        mma_gemm<<<dim3(24, MB, 1), 256, GEMM_SMEM>>>(
            wPh_p, wPl_p, 256,
            qkvPh_p + (size_t)l * 1536 * 256, qkvPl_p + (size_t)l * 1536 * 256, 256,
            g_hd_p, g_hd_p, 3 * DM,
            kPh_p, kPl_p, 256,
            nullptr, 0, 3, TT, 3 * DM, DM);
        // Wr: fp32 + planes (outMode 2)
        mma_gemm<<<dim3(8, MB, 1), 256, GEMM_SMEM>>>(
            posPh_p, posPl_p, 256,
            wrPh_p + (size_t)l * 512 * 256, wrPl_p + (size_t)l * 512 * 256, 256,
            g_r_p, g_r_p, DM,
            rPh_p, rPl_p, 256,
            nullptr, 0, 2, TT, DM, DM);
        // V transpose-convert
        convert_vt<<<dim3(33, NH), 256>>>(g_hd_p, vtPh_p, vtPl_p);

        fused_attn_kernel<<<dim3(NH, 17), 256, ATTN_SMEM>>>(
            g_hd_p, g_r_p, kPh_p, kPl_p, vtPh_p, vtPl_p, rPh_p, rPl_p, rwb, rrb);

        // Wo: K-split z=2, fp32 partials
        mma_gemm<<<dim3(8, MB, 2), 256, GEMM_SMEM>>>(
            avPh_p, avPl_p, 256,
            woPh_p + (size_t)l * 512 * 256, woPl_p + (size_t)l * 512 * 256, 256,
            g_tmp_p, g_tmp2_p, DM,
            nullptr, nullptr, 0,
            nullptr, 0, 0, TT, DM, DM / 2);
        add_ln_kernel<<<TT, 256>>>(g_w_p, g_tmp_p, g_tmp2_p, ln1s + l * DM, ln1b + l * DM);
        // FFN1: plane output (bias+relu fused)
        mma_gemm<<<dim3(32, MB, 1), 256, GEMM_SMEM>>>(
            wPh_p, wPl_p, 256,
            w1Ph_p + (size_t)l * 2048 * 256, w1Pl_p + (size_t)l * 2048 * 256, 256,
            nullptr, nullptr, 0,
            ff1Ph_p, ff1Pl_p, DI / 2,
            b1 + (size_t)l * DI, 1, 1, TT, DI, DM);
        // FFN2: K-split z=2, fp32 partials
        mma_gemm<<<dim3(8, MB, 2), 256, GEMM_SMEM>>>(
            ff1Ph_p, ff1Pl_p, 1024,
            w2Ph_p + (size_t)l * 512 * 1024, w2Pl_p + (size_t)l * 512 * 1024, 1024,
            g_tmp_p, g_tmp2_p, DM,
            nullptr, nullptr, 0,
            b2 + (size_t)l * DM, 0, 0, TT, DM, DI / 2);
        add_ln_kernel<<<TT, 256>>>(g_w_p, g_tmp_p, g_tmp2_p, ln2s + l * DM, ln2b + l * DM);
    }

    copy_out_kernel<<<(TT * DM + 255) / 256, 256>>>((float*)d_out);
}

// round 13
// speedup vs baseline: 1.1330x; 1.0190x over previous
#include <cuda_runtime.h>
#include <cuda_bf16.h>
#include <math.h>
#include <stdint.h>

// ---------------- problem constants ----------------
#define TT    2080
#define DM    512
#define NH    8
#define DH    64
#define DI    2048
#define NLAY  4
#define NMTOK 16
#define QL    2048
#define VTKP  1056

// ---------------- fp32 scratch ----------------
__device__ float g_w[TT * DM];
__device__ float g_heads[TT * 3 * DM];
__device__ float g_r[TT * DM];
__device__ float g_tmp[TT * DM];
__device__ float g_tmp2[TT * DM];

// ---------------- bf16 hi/lo pair-plane scratch ----------------
__device__ uint32_t wPh[TT * 256],   wPl[TT * 256];
__device__ uint32_t posPh[TT * 256], posPl[TT * 256];
__device__ uint32_t avPh[TT * 256],  avPl[TT * 256];
__device__ uint32_t ff1Ph[TT * 1024], ff1Pl[TT * 1024];
__device__ uint32_t kPh[TT * 256],   kPl[TT * 256];
__device__ uint32_t rPh[TT * 256],   rPl[TT * 256];
__device__ uint32_t vtPh[NH * 64 * VTKP], vtPl[NH * 64 * VTKP];
__device__ uint32_t qkvPh[NLAY * 1536 * 256], qkvPl[NLAY * 1536 * 256];
__device__ uint32_t wrPh[NLAY * 512 * 256],   wrPl[NLAY * 512 * 256];
__device__ uint32_t woPh[NLAY * 512 * 256],   woPl[NLAY * 512 * 256];
__device__ uint32_t w1Ph[NLAY * 2048 * 256],  w1Pl[NLAY * 2048 * 256];
__device__ uint32_t w2Ph[NLAY * 512 * 1024],  w2Pl[NLAY * 512 * 1024];

// ---------------- bf16x3 helpers ----------------
__device__ __forceinline__ void split2(float x0, float x1, uint32_t& hw, uint32_t& lw) {
    __nv_bfloat162 h, l;
    h.x = __float2bfloat16(x0);
    h.y = __float2bfloat16(x1);
    l.x = __float2bfloat16(x0 - __bfloat162float(h.x));
    l.y = __float2bfloat16(x1 - __bfloat162float(h.y));
    hw = *reinterpret_cast<uint32_t*>(&h);
    lw = *reinterpret_cast<uint32_t*>(&l);
}

__device__ __forceinline__ void mma16(float (&c)[4], const uint32_t (&a)[4],
                                      uint32_t b0, uint32_t b1) {
    asm volatile(
        "mma.sync.aligned.m16n8k16.row.col.f32.bf16.bf16.f32 "
        "{%0,%1,%2,%3}, {%4,%5,%6,%7}, {%8,%9}, {%0,%1,%2,%3};"
        : "+f"(c[0]), "+f"(c[1]), "+f"(c[2]), "+f"(c[3])
        : "r"(a[0]), "r"(a[1]), "r"(a[2]), "r"(a[3]), "r"(b0), "r"(b1));
}

__device__ __forceinline__ uint32_t sm_u32(const void* p) {
    return (uint32_t)__cvta_generic_to_shared(p);
}

__device__ __forceinline__ void ldsm4(uint32_t (&r)[4], uint32_t a) {
    asm volatile("ldmatrix.sync.aligned.m8n8.x4.shared.b16 {%0,%1,%2,%3}, [%4];"
                 : "=r"(r[0]), "=r"(r[1]), "=r"(r[2]), "=r"(r[3]) : "r"(a));
}

__device__ __forceinline__ void cpa16(uint32_t dst, const void* src, int szok) {
    asm volatile("cp.async.cg.shared.global [%0], [%1], 16, %2;"
                 :: "r"(dst), "l"(src), "r"(szok));
}

__device__ __forceinline__ int boff(int n) { return n * 36 + ((n >> 3) << 2); }
#define BPLANE (64 * 36 + 32)

// ---------------- prep kernels ----------------
__global__ void build_w_kernel(const float* __restrict__ word_emb,
                               const float* __restrict__ mem) {
    int idx = blockIdx.x * blockDim.x + threadIdx.x;
    if (idx >= TT * 256) return;
    int row = idx >> 8, c2 = idx & 255;
    int c = 2 * c2;
    float v0, v1;
    if (row < NMTOK) {
        v0 = mem[row * DM + c]; v1 = mem[row * DM + c + 1];
    } else if (row < NMTOK + QL) {
        v0 = word_emb[(row - NMTOK) * DM + c]; v1 = word_emb[(row - NMTOK) * DM + c + 1];
    } else {
        v0 = mem[(row - NMTOK - QL) * DM + c]; v1 = mem[(row - NMTOK - QL) * DM + c + 1];
    }
    g_w[row * DM + c] = v0;
    g_w[row * DM + c + 1] = v1;
    uint32_t hw, lw;
    split2(v0, v1, hw, lw);
    wPh[idx] = hw; wPl[idx] = lw;
}

__global__ void build_pos_kernel() {
    int idx = blockIdx.x * blockDim.x + threadIdx.x;
    if (idx >= TT * 256) return;
    int row = idx >> 8, c2 = idx & 255;
    float v0, v1;
    #pragma unroll
    for (int u = 0; u < 2; u++) {
        int c = 2 * c2 + u;
        int f = (c < DM / 2) ? c : (c - DM / 2);
        double invf = exp(-((double)(2 * f) / (double)DM) * log(10000.0));
        double val = (double)(TT - 1 - row) * invf;
        float r = (float)((c < DM / 2) ? sin(val) : cos(val));
        if (u == 0) v0 = r; else v1 = r;
    }
    uint32_t hw, lw;
    split2(v0, v1, hw, lw);
    posPh[idx] = hw; posPl[idx] = lw;
}

// ---------------- weight convert ----------------
__global__ void convert_weight(const float* __restrict__ W,
                               uint32_t* __restrict__ Ph, uint32_t* __restrict__ Pl,
                               int K, int N) {
    __shared__ float S[64][33];
    const int l = blockIdx.z;
    const float* Wl = W + (size_t)l * K * N;
    const int Kw = K >> 1;
    uint32_t* PhL = Ph + (size_t)l * N * Kw;
    uint32_t* PlL = Pl + (size_t)l * N * Kw;
    const int n0 = blockIdx.x * 32, k0 = blockIdx.y * 64;
    const int t = threadIdx.x;
    {
        int n = t & 31, kk = t >> 5;
        #pragma unroll
        for (int i = 0; i < 8; i++)
            S[kk + 8 * i][n] = Wl[(size_t)(k0 + kk + 8 * i) * N + n0 + n];
    }
    __syncthreads();
    {
        int nn = t >> 3, kq = t & 7;
        uint32_t oh[4], ol[4];
        #pragma unroll
        for (int i = 0; i < 4; i++) {
            int kp = kq * 4 + i;
            split2(S[2 * kp][nn], S[2 * kp + 1][nn], oh[i], ol[i]);
        }
        size_t base = (size_t)(n0 + nn) * Kw + (k0 >> 1) + kq * 4;
        *reinterpret_cast<uint4*>(PhL + base) = *reinterpret_cast<uint4*>(oh);
        *reinterpret_cast<uint4*>(PlL + base) = *reinterpret_cast<uint4*>(ol);
    }
}

// ---------------- V transpose-convert ----------------
__global__ void convert_vt(const float* __restrict__ heads,
                           uint32_t* __restrict__ Vh, uint32_t* __restrict__ Vl) {
    __shared__ float S[64][65];
    const int jt = blockIdx.x, h = blockIdx.y;
    const int j0 = jt * 64, tid = threadIdx.x;
    for (int t = tid; t < 64 * 16; t += 256) {
        int r = t >> 4, c4 = (t & 15) * 4;
        int gj = j0 + r;
        float4 v = make_float4(0.f, 0.f, 0.f, 0.f);
        if (gj < TT)
            v = *(const float4*)(heads + (size_t)gj * 1536 + 1024 + h * 64 + c4);
        S[r][c4] = v.x; S[r][c4 + 1] = v.y; S[r][c4 + 2] = v.z; S[r][c4 + 3] = v.w;
    }
    __syncthreads();
    const int f = tid >> 2, wq = (tid & 3) * 8;
    size_t base = ((size_t)h * 64 + f) * VTKP + (j0 >> 1) + wq;
    #pragma unroll
    for (int i = 0; i < 8; i++) {
        int kp = wq + i;
        uint32_t hw, lw;
        split2(S[2 * kp][f], S[2 * kp + 1][f], hw, lw);
        Vh[base + i] = hw; Vl[base + i] = lw;
    }
}

// ---------------- GEMM: cp.async 3-stage pipeline ----------------
#define PPA 20
#define PPB 20
#define ASTG (128 * PPA)
#define BSTG (64 * PPB)
#define STG_W (2 * ASTG + 2 * BSTG)
#define NSTG 3
#define GEMM_SMEM (NSTG * STG_W * 4)

__global__ __launch_bounds__(256, 2)
void mma_gemm(const uint32_t* __restrict__ Ahg, const uint32_t* __restrict__ Alg, int ldaw,
              const uint32_t* __restrict__ Bhg, const uint32_t* __restrict__ Blg, int ldbw,
              float* __restrict__ C, float* __restrict__ C2, int ldc,
              uint32_t* __restrict__ OutH, uint32_t* __restrict__ OutL, int ldcw,
              const float* __restrict__ cbias, int doRelu, int outMode,
              int M, int N, int Ksub) {
    extern __shared__ uint32_t gsm[];
    const uint32_t smBase = sm_u32(gsm);

    const int bm = blockIdx.y * 128, bn = blockIdx.x * 64;
    const int kOffW = blockIdx.z * (Ksub >> 1);
    if (blockIdx.z == 1) C = C2;

    const int tid = threadIdx.x;
    const int lane = tid & 31, warp = tid >> 5;
    const int wm = warp & 3, wn = warp >> 2;
    const int g4 = lane >> 2, l4 = lane & 3;

    float acc[2][4][4] = {};

    const int arow = tid >> 2;
    const int akq = tid & 3;

    const int aRow = lane & 15;
    const uint32_t aHiB = ((lane >> 4) & 1) * 16;
    const uint32_t adA = smBase + (uint32_t)((wm * 32 + aRow) * PPA) * 4 + aHiB;
    const int bRowN = ((lane >> 4) & 1) * 8 + (lane & 7);
    const uint32_t bHiB = ((lane >> 3) & 1) * 16;
    const uint32_t adB0 = smBase + (uint32_t)(2 * ASTG + (wn * 32 + bRowN) * PPB) * 4 + bHiB;
    const uint32_t adB1 = adB0 + 16 * PPB * 4;

    const uint32_t dA = (uint32_t)(arow * PPA + akq * 4) * 4;
    const uint32_t dB = (uint32_t)(2 * ASTG + arow * PPB + akq * 4) * 4;

    auto issueStage = [&](int iter, int st) {
        const int kw = kOffW + iter * 16 + akq * 4;
        const uint32_t base = smBase + (uint32_t)st * (STG_W * 4);
        #pragma unroll
        for (int p = 0; p < 2; p++) {
            int row = bm + p * 64 + arow;
            int ok = (row < M) ? 16 : 0;
            int rowc = (row < M) ? row : 0;
            cpa16(base + dA + p * 64 * PPA * 4, Ahg + (size_t)rowc * ldaw + kw, ok);
            cpa16(base + dA + p * 64 * PPA * 4 + ASTG * 4, Alg + (size_t)rowc * ldaw + kw, ok);
        }
        {
            int row = bn + arow;
            cpa16(base + dB, Bhg + (size_t)row * ldbw + kw, 16);
            cpa16(base + dB + BSTG * 4, Blg + (size_t)row * ldbw + kw, 16);
        }
    };

    const int niter = Ksub >> 5;
    issueStage(0, 0);
    asm volatile("cp.async.commit_group;" ::: "memory");
    issueStage(1, 1);
    asm volatile("cp.async.commit_group;" ::: "memory");

    int st = 0;
    for (int i = 0; i < niter; i++) {
        asm volatile("cp.async.wait_group 1;" ::: "memory");
        __syncthreads();
        const uint32_t so = (uint32_t)st * (STG_W * 4);
        #pragma unroll
        for (int ks = 0; ks < 2; ks++) {
            uint32_t ahh[2][4], alo[2][4];
            ldsm4(ahh[0], adA + so + ks * 32);
            ldsm4(ahh[1], adA + so + 16 * PPA * 4 + ks * 32);
            ldsm4(alo[0], adA + so + ASTG * 4 + ks * 32);
            ldsm4(alo[1], adA + so + ASTG * 4 + 16 * PPA * 4 + ks * 32);
            uint32_t bhh[2][4], blo[2][4];
            ldsm4(bhh[0], adB0 + so + ks * 32);
            ldsm4(bhh[1], adB1 + so + ks * 32);
            ldsm4(blo[0], adB0 + so + BSTG * 4 + ks * 32);
            ldsm4(blo[1], adB1 + so + BSTG * 4 + ks * 32);
            #pragma unroll
            for (int am = 0; am < 2; am++)
                #pragma unroll
                for (int an = 0; an < 4; an++) {
                    const int g = an >> 1, x = (an & 1) * 2;
                    mma16(acc[am][an], ahh[am], bhh[g][x], bhh[g][x + 1]);
                    mma16(acc[am][an], ahh[am], blo[g][x], blo[g][x + 1]);
                    mma16(acc[am][an], alo[am], bhh[g][x], bhh[g][x + 1]);
                }
        }
        if (i + 2 < niter) {
            int st2 = st + 2; if (st2 >= NSTG) st2 -= NSTG;
            issueStage(i + 2, st2);
        }
        asm volatile("cp.async.commit_group;" ::: "memory");
        st = (st + 1 == NSTG) ? 0 : st + 1;
    }

    bool wantPlane, wantF32;
    if (outMode == 0)      { wantPlane = false; wantF32 = true; }
    else if (outMode == 1) { wantPlane = true;  wantF32 = false; }
    else if (outMode == 2) { wantPlane = true;  wantF32 = true; }
    else {
        bool isk = (bn >= 512 && bn < 1024);
        wantPlane = isk; wantF32 = !isk;
    }
    const int pShift = (outMode == 3) ? 512 : 0;

    #pragma unroll
    for (int am = 0; am < 2; am++) {
        int row0 = bm + wm * 32 + am * 16 + g4;
        #pragma unroll
        for (int an = 0; an < 4; an++) {
            int col0 = bn + wn * 32 + an * 8 + 2 * l4;
            float v0 = acc[am][an][0], v1 = acc[am][an][1];
            float v2 = acc[am][an][2], v3 = acc[am][an][3];
            if (cbias && blockIdx.z == 0) {
                float b0 = cbias[col0], b1 = cbias[col0 + 1];
                v0 += b0; v1 += b1; v2 += b0; v3 += b1;
            }
            if (doRelu) {
                v0 = fmaxf(v0, 0.f); v1 = fmaxf(v1, 0.f);
                v2 = fmaxf(v2, 0.f); v3 = fmaxf(v3, 0.f);
            }
            if (wantPlane) {
                uint32_t hw, lw;
                int colP = (col0 - pShift) >> 1;
                if (row0 < M) {
                    split2(v0, v1, hw, lw);
                    OutH[(size_t)row0 * ldcw + colP] = hw;
                    OutL[(size_t)row0 * ldcw + colP] = lw;
                }
                if (row0 + 8 < M) {
                    split2(v2, v3, hw, lw);
                    OutH[(size_t)(row0 + 8) * ldcw + colP] = hw;
                    OutL[(size_t)(row0 + 8) * ldcw + colP] = lw;
                }
            }
            if (wantF32) {
                if (row0 < M) {
                    C[(size_t)row0 * ldc + col0]     = v0;
                    C[(size_t)row0 * ldc + col0 + 1] = v1;
                }
                if (row0 + 8 < M) {
                    C[(size_t)(row0 + 8) * ldc + col0]     = v2;
                    C[(size_t)(row0 + 8) * ldc + col0 + 1] = v3;
                }
            }
        }
    }
}

// ---------------- fused flash-style relative attention (512 threads, 16 warps) ----------------
#define RPAD 68
#define RSLOT (64 * RPAD)
#define ATTN_WORDS (12 * BPLANE + 3 * RSLOT + 512)
#define ATTN_SMEM (ATTN_WORDS * 4)

__global__ __launch_bounds__(512, 1)
void fused_attn_kernel(const float* __restrict__ heads,
                       const float* __restrict__ rbuf,
                       const uint32_t* __restrict__ kGh, const uint32_t* __restrict__ kGl,
                       const uint32_t* __restrict__ vGh, const uint32_t* __restrict__ vGl,
                       const uint32_t* __restrict__ rGh, const uint32_t* __restrict__ rGl,
                       const float* __restrict__ rwb,
                       const float* __restrict__ rrb) {
    extern __shared__ uint32_t smu[];
    uint32_t* Qwh = smu;
    uint32_t* Qwl = Qwh + BPLANE;
    uint32_t* Qrh = Qwl + BPLANE;
    uint32_t* Qrl = Qrh + BPLANE;
    uint32_t* Kh  = Qrl + BPLANE;
    uint32_t* Kl  = Kh  + BPLANE;
    uint32_t* Rh  = Kl  + BPLANE;
    uint32_t* Rl  = Rh  + BPLANE;
    uint32_t* Vth = Rl  + BPLANE;
    uint32_t* Vtl = Vth + BPLANE;
    uint32_t* Ph  = Vtl + BPLANE;
    uint32_t* Pl  = Ph  + BPLANE;
    float* Ring = (float*)(Pl + BPLANE);
    float* redm = Ring + 3 * RSLOT;     // [4][64]
    float* reds = redm + 256;           // [4][64]

    const int h = blockIdx.x;
    const int p = blockIdx.y;
    const int tid = threadIdx.x;
    const int lane = tid & 31, warp = tid >> 5;
    const int wm = warp & 3, wn = warp >> 2;      // 4 x 4 warps
    const int g4 = lane >> 2, l4 = lane & 3;
    const int wr0 = wm * 16 + g4;
    const int colbase = wn * 16;

    const int aRow = lane & 15;
    const uint32_t aHiB = ((lane >> 4) & 1) * 16;
    const uint32_t aOff = (uint32_t)boff(wm * 16 + aRow) * 4 + aHiB;
    const uint32_t adQwh = sm_u32(Qwh) + aOff, adQwl = sm_u32(Qwl) + aOff;
    const uint32_t adQrh = sm_u32(Qrh) + aOff, adQrl = sm_u32(Qrl) + aOff;
    const uint32_t adPh  = sm_u32(Ph)  + aOff, adPl  = sm_u32(Pl)  + aOff;
    const int bRowN = ((lane >> 4) & 1) * 8 + (lane & 7);
    const uint32_t bHiB = ((lane >> 3) & 1) * 16;
    const uint32_t bO0 = (uint32_t)boff(colbase + bRowN) * 4 + bHiB;
    const uint32_t adKh0 = sm_u32(Kh) + bO0;
    const uint32_t adKl0 = sm_u32(Kl) + bO0;
    const uint32_t adRh0 = sm_u32(Rh) + bO0;
    const uint32_t adRl0 = sm_u32(Rl) + bO0;
    const uint32_t adVh0 = sm_u32(Vth) + bO0;
    const uint32_t adVl0 = sm_u32(Vtl) + bO0;

    // K/V prefetch: 512 threads, 1 uint4 per plane per thread
    uint4 pkh, pkl, pvh, pvl;
    const int prow = tid >> 3, pwq = (tid & 7) * 4;
    const size_t vtBase = ((size_t)h * 64 + prow) * VTKP;
    auto prefetchKV = [&](int j0) {
        int gj = j0 + prow;
        if (gj < TT) {
            pkh = *(const uint4*)(kGh + (size_t)gj * 256 + h * 32 + pwq);
            pkl = *(const uint4*)(kGl + (size_t)gj * 256 + h * 32 + pwq);
        } else {
            pkh = make_uint4(0, 0, 0, 0);
            pkl = make_uint4(0, 0, 0, 0);
        }
        pvh = *(const uint4*)(vGh + vtBase + (j0 >> 1) + pwq);
        pvl = *(const uint4*)(vGl + vtBase + (j0 >> 1) + pwq);
    };
    auto storeKV = [&]() {
        int wi = boff(prow) + pwq;
        *(uint4*)(Kh + wi) = pkh;
        *(uint4*)(Kl + wi) = pkl;
        *(uint4*)(Vth + wi) = pvh;
        *(uint4*)(Vtl + wi) = pvl;
    };

    int blist[2]; int nblk;
    if (p < 16) { blist[0] = p; blist[1] = 31 - p; nblk = 2; }
    else        { blist[0] = 32; nblk = 1; }

    for (int bi = 0; bi < nblk; bi++) {
        const int b = blist[bi];
        const int i0 = b * 64;
        const int validRows = min(64, TT - i0);
        const int njt = (b < 32) ? (b + 1) : 33;

        __syncthreads();
        for (int t = tid; t < 64 * 16; t += 512) {
            int r = t >> 4, c4 = (t & 15) * 4;
            int grow = i0 + r;
            float4 q = make_float4(0.f, 0.f, 0.f, 0.f);
            if (grow < TT)
                q = *(const float4*)(heads + (size_t)grow * (3 * DM) + h * DH + c4);
            float4 bw = *(const float4*)(rwb + h * DH + c4);
            float4 br = *(const float4*)(rrb + h * DH + c4);
            int wi = boff(r) + (c4 >> 1);
            uint32_t hw, lw;
            split2(q.x + bw.x, q.y + bw.y, hw, lw); Qwh[wi] = hw;     Qwl[wi] = lw;
            split2(q.z + bw.z, q.w + bw.w, hw, lw); Qwh[wi + 1] = hw; Qwl[wi + 1] = lw;
            split2(q.x + br.x, q.y + br.y, hw, lw); Qrh[wi] = hw;     Qrl[wi] = lw;
            split2(q.z + br.z, q.w + br.w, hw, lw); Qrh[wi + 1] = hw; Qrl[wi + 1] = lw;
        }
        prefetchKV(0);

        float o[2][4];
        #pragma unroll
        for (int a = 0; a < 2; a++) { o[a][0] = o[a][1] = o[a][2] = o[a][3] = 0.f; }
        float mrow[2] = {-1e30f, -1e30f};
        float lrow[2] = {0.f, 0.f};

        int nextChunk = (2016 - i0) / 64;
        if (nextChunk < 0) nextChunk = 0;

        for (int jt = 0; jt < njt; jt++) {
            const int j0 = jt * 64;

            const int hiJr = min(TT - 1, TT - 1 - i0 + j0 + 63);
            const int chi = hiJr >> 6;
            while (nextChunk <= chi) {
                const int c = nextChunk;
                __syncthreads();
                {
                    int grow = c * 64 + prow;
                    uint4 r0 = make_uint4(0, 0, 0, 0), r1 = r0;
                    if (grow < TT) {
                        r0 = *(const uint4*)(rGh + (size_t)grow * 256 + h * 32 + pwq);
                        r1 = *(const uint4*)(rGl + (size_t)grow * 256 + h * 32 + pwq);
                    }
                    int wi = boff(prow) + pwq;
                    *(uint4*)(Rh + wi) = r0;
                    *(uint4*)(Rl + wi) = r1;
                }
                __syncthreads();
                float cacc[2][4];
                #pragma unroll
                for (int a = 0; a < 2; a++)
                    cacc[a][0] = cacc[a][1] = cacc[a][2] = cacc[a][3] = 0.f;
                #pragma unroll
                for (int kc = 0; kc < 4; kc++) {
                    uint32_t ah[4], al[4];
                    ldsm4(ah, adQrh + kc * 32);
                    ldsm4(al, adQrl + kc * 32);
                    uint32_t bh[4], bl[4];
                    ldsm4(bh, adRh0 + kc * 32);
                    ldsm4(bl, adRl0 + kc * 32);
                    #pragma unroll
                    for (int an = 0; an < 2; an++) {
                        const int x = an * 2;
                        mma16(cacc[an], ah, bh[x], bh[x + 1]);
                        mma16(cacc[an], ah, bl[x], bl[x + 1]);
                        mma16(cacc[an], al, bh[x], bh[x + 1]);
                    }
                }
                float* slot = Ring + (c % 3) * RSLOT;
                #pragma unroll
                for (int an = 0; an < 2; an++) {
                    int col = colbase + an * 8 + 2 * l4;
                    slot[wr0 * RPAD + col]           = cacc[an][0];
                    slot[wr0 * RPAD + col + 1]       = cacc[an][1];
                    slot[(wr0 + 8) * RPAD + col]     = cacc[an][2];
                    slot[(wr0 + 8) * RPAD + col + 1] = cacc[an][3];
                }
                nextChunk++;
            }

            __syncthreads();
            storeKV();
            __syncthreads();

            float s[2][4];
            #pragma unroll
            for (int a = 0; a < 2; a++)
                s[a][0] = s[a][1] = s[a][2] = s[a][3] = 0.f;
            #pragma unroll
            for (int kc = 0; kc < 4; kc++) {
                uint32_t ah[4], al[4];
                ldsm4(ah, adQwh + kc * 32);
                ldsm4(al, adQwl + kc * 32);
                uint32_t bh[4], bl[4];
                ldsm4(bh, adKh0 + kc * 32);
                ldsm4(bl, adKl0 + kc * 32);
                #pragma unroll
                for (int an = 0; an < 2; an++) {
                    const int x = an * 2;
                    mma16(s[an], ah, bh[x], bh[x + 1]);
                    mma16(s[an], ah, bl[x], bl[x + 1]);
                    mma16(s[an], al, bh[x], bh[x + 1]);
                }
            }

            float tmax[2] = {-1e30f, -1e30f};
            #pragma unroll
            for (int an = 0; an < 2; an++) {
                #pragma unroll
                for (int e = 0; e < 4; e++) {
                    int rh = e >> 1;
                    int di = wr0 + rh * 8;
                    int dj = colbase + an * 8 + 2 * l4 + (e & 1);
                    int i = i0 + di, j = j0 + dj;
                    float v = -1e30f;
                    if (di < validRows && j < TT) {
                        int jmaxr = (i < NMTOK) ? (NMTOK - 1)
                                  : ((i >= TT - NMTOK) ? (TT - 1) : i);
                        if (j <= jmaxr) {
                            float bd;
                            if (j <= i) {
                                int jr = TT - 1 - i + j;
                                bd = Ring[((jr >> 6) % 3) * RSLOT + di * RPAD + (jr & 63)];
                            } else if (j == i + 1) {
                                bd = 0.f;
                            } else {
                                const float* rr = rbuf + (size_t)(j - i - 2) * DM + h * DH;
                                float accd = 0.f;
                                #pragma unroll 8
                                for (int d2 = 0; d2 < 32; d2++) {
                                    uint32_t wh = Qrh[boff(di + 1) + d2];
                                    uint32_t wl = Qrl[boff(di + 1) + d2];
                                    __nv_bfloat162 h2 = *reinterpret_cast<__nv_bfloat162*>(&wh);
                                    __nv_bfloat162 l2 = *reinterpret_cast<__nv_bfloat162*>(&wl);
                                    float q0 = __bfloat162float(h2.x) + __bfloat162float(l2.x);
                                    float q1 = __bfloat162float(h2.y) + __bfloat162float(l2.y);
                                    accd += q0 * rr[2 * d2] + q1 * rr[2 * d2 + 1];
                                }
                                bd = accd;
                            }
                            v = (s[an][e] + bd) * 0.125f;
                        }
                    }
                    s[an][e] = v;
                    tmax[rh] = fmaxf(tmax[rh], v);
                }
            }
            #pragma unroll
            for (int rh = 0; rh < 2; rh++) {
                tmax[rh] = fmaxf(tmax[rh], __shfl_xor_sync(0xffffffffu, tmax[rh], 1));
                tmax[rh] = fmaxf(tmax[rh], __shfl_xor_sync(0xffffffffu, tmax[rh], 2));
            }
            if (l4 == 0) {
                redm[wn * 64 + wm * 16 + g4]     = tmax[0];
                redm[wn * 64 + wm * 16 + g4 + 8] = tmax[1];
            }
            __syncthreads();

            float scl[2], lsum[2] = {0.f, 0.f};
            #pragma unroll
            for (int rh = 0; rh < 2; rh++) {
                int row = wm * 16 + g4 + rh * 8;
                float tm = fmaxf(fmaxf(redm[row], redm[64 + row]),
                                 fmaxf(redm[128 + row], redm[192 + row]));
                float mnew = fmaxf(mrow[rh], tm);
                scl[rh] = expf(mrow[rh] - mnew);
                mrow[rh] = mnew;
            }
            #pragma unroll
            for (int an = 0; an < 2; an++) {
                #pragma unroll
                for (int e = 0; e < 4; e++) {
                    int rh = e >> 1;
                    float ev = expf(s[an][e] - mrow[rh]);
                    s[an][e] = ev;
                    lsum[rh] += ev;
                }
            }
            #pragma unroll
            for (int rh = 0; rh < 2; rh++) {
                lsum[rh] += __shfl_xor_sync(0xffffffffu, lsum[rh], 1);
                lsum[rh] += __shfl_xor_sync(0xffffffffu, lsum[rh], 2);
            }
            if (l4 == 0) {
                reds[wn * 64 + wm * 16 + g4]     = lsum[0];
                reds[wn * 64 + wm * 16 + g4 + 8] = lsum[1];
            }
            #pragma unroll
            for (int an = 0; an < 2; an++) {
                int cp = (colbase >> 1) + an * 4 + l4;
                uint32_t hw, lw;
                split2(s[an][0], s[an][1], hw, lw);
                Ph[boff(wr0) + cp] = hw; Pl[boff(wr0) + cp] = lw;
                split2(s[an][2], s[an][3], hw, lw);
                Ph[boff(wr0 + 8) + cp] = hw; Pl[boff(wr0 + 8) + cp] = lw;
            }
            __syncthreads();

            #pragma unroll
            for (int rh = 0; rh < 2; rh++) {
                int row = wm * 16 + g4 + rh * 8;
                lrow[rh] = lrow[rh] * scl[rh] +
                           reds[row] + reds[64 + row] + reds[128 + row] + reds[192 + row];
            }
            #pragma unroll
            for (int an = 0; an < 2; an++) {
                o[an][0] *= scl[0]; o[an][1] *= scl[0];
                o[an][2] *= scl[1]; o[an][3] *= scl[1];
            }

            #pragma unroll
            for (int kc = 0; kc < 4; kc++) {
                uint32_t ah[4], al[4];
                ldsm4(ah, adPh + kc * 32);
                ldsm4(al, adPl + kc * 32);
                uint32_t bh[4], bl[4];
                ldsm4(bh, adVh0 + kc * 32);
                ldsm4(bl, adVl0 + kc * 32);
                #pragma unroll
                for (int an = 0; an < 2; an++) {
                    const int x = an * 2;
                    mma16(o[an], ah, bh[x], bh[x + 1]);
                    mma16(o[an], ah, bl[x], bl[x + 1]);
                    mma16(o[an], al, bh[x], bh[x + 1]);
                }
            }

            if (jt + 1 < njt) prefetchKV((jt + 1) * 64);
        } // j-tiles

        float inv0 = 1.f / lrow[0], inv1 = 1.f / lrow[1];
        #pragma unroll
        for (int an = 0; an < 2; an++) {
            int colw = (h * DH + colbase + an * 8 + 2 * l4) >> 1;
            int r0 = i0 + wr0;
            uint32_t hw, lw;
            if (wr0 < validRows) {
                split2(o[an][0] * inv0, o[an][1] * inv0, hw, lw);
                avPh[(size_t)r0 * 256 + colw] = hw;
                avPl[(size_t)r0 * 256 + colw] = lw;
            }
            if (wr0 + 8 < validRows) {
                split2(o[an][2] * inv1, o[an][3] * inv1, hw, lw);
                avPh[(size_t)(r0 + 8) * 256 + colw] = hw;
                avPl[(size_t)(r0 + 8) * 256 + colw] = lw;
            }
        }
    } // blocks
}

// ---------------- residual add + layernorm (emits w planes) ----------------
__global__ void add_ln_kernel(float* __restrict__ w, const float* __restrict__ delta,
                              const float* __restrict__ delta2,
                              const float* __restrict__ gam, const float* __restrict__ bta) {
    int row = blockIdx.x;
    int tid = threadIdx.x;
    int c = 2 * tid;
    __shared__ float red[256];
    float x0 = w[row * DM + c]     + delta[row * DM + c];
    float x1 = w[row * DM + c + 1] + delta[row * DM + c + 1];
    if (delta2) {
        x0 += delta2[row * DM + c];
        x1 += delta2[row * DM + c + 1];
    }
    red[tid] = x0 + x1; __syncthreads();
    for (int s = 128; s > 0; s >>= 1) {
        if (tid < s) red[tid] += red[tid + s];
        __syncthreads();
    }
    float mean = red[0] * (1.f / DM);
    __syncthreads();
    float d0 = x0 - mean, d1 = x1 - mean;
    red[tid] = d0 * d0 + d1 * d1; __syncthreads();
    for (int s = 128; s > 0; s >>= 1) {
        if (tid < s) red[tid] += red[tid + s];
        __syncthreads();
    }
    float inv = 1.f / sqrtf(red[0] * (1.f / DM) + 1e-5f);
    float y0 = d0 * inv * gam[c]     + bta[c];
    float y1 = d1 * inv * gam[c + 1] + bta[c + 1];
    w[row * DM + c]     = y0;
    w[row * DM + c + 1] = y1;
    uint32_t hw, lw;
    split2(y0, y1, hw, lw);
    wPh[row * 256 + tid] = hw;
    wPl[row * 256 + tid] = lw;
}

__global__ void copy_out_kernel(float* __restrict__ out) {
    int idx = blockIdx.x * blockDim.x + threadIdx.x;
    if (idx < TT * DM) out[idx] = g_w[idx];
}

// ---------------- launcher ----------------
extern "C" void kernel_launch(void* const* d_in, const int* in_sizes, int n_in,
                              void* d_out, int out_size) {
    (void)in_sizes; (void)n_in; (void)out_size;
    const float* word_emb = (const float*)d_in[0];
    const float* mem_tok  = (const float*)d_in[1];
    const float* Wqkv     = (const float*)d_in[2];
    const float* Wr       = (const float*)d_in[3];
    const float* Wo       = (const float*)d_in[4];
    const float* ln1s     = (const float*)d_in[5];
    const float* ln1b     = (const float*)d_in[6];
    const float* W1       = (const float*)d_in[7];
    const float* b1       = (const float*)d_in[8];
    const float* W2       = (const float*)d_in[9];
    const float* b2       = (const float*)d_in[10];
    const float* ln2s     = (const float*)d_in[11];
    const float* ln2b     = (const float*)d_in[12];
    const float* rwb      = (const float*)d_in[13];
    const float* rrb      = (const float*)d_in[14];

    float *g_w_p, *g_hd_p, *g_r_p, *g_tmp_p, *g_tmp2_p;
    cudaGetSymbolAddress((void**)&g_w_p,    g_w);
    cudaGetSymbolAddress((void**)&g_hd_p,   g_heads);
    cudaGetSymbolAddress((void**)&g_r_p,    g_r);
    cudaGetSymbolAddress((void**)&g_tmp_p,  g_tmp);
    cudaGetSymbolAddress((void**)&g_tmp2_p, g_tmp2);
    uint32_t *wPh_p, *wPl_p, *posPh_p, *posPl_p, *avPh_p, *avPl_p, *ff1Ph_p, *ff1Pl_p;
    uint32_t *kPh_p, *kPl_p, *rPh_p, *rPl_p, *vtPh_p, *vtPl_p;
    cudaGetSymbolAddress((void**)&wPh_p,   wPh);
    cudaGetSymbolAddress((void**)&wPl_p,   wPl);
    cudaGetSymbolAddress((void**)&posPh_p, posPh);
    cudaGetSymbolAddress((void**)&posPl_p, posPl);
    cudaGetSymbolAddress((void**)&avPh_p,  avPh);
    cudaGetSymbolAddress((void**)&avPl_p,  avPl);
    cudaGetSymbolAddress((void**)&ff1Ph_p, ff1Ph);
    cudaGetSymbolAddress((void**)&ff1Pl_p, ff1Pl);
    cudaGetSymbolAddress((void**)&kPh_p,   kPh);
    cudaGetSymbolAddress((void**)&kPl_p,   kPl);
    cudaGetSymbolAddress((void**)&rPh_p,   rPh);
    cudaGetSymbolAddress((void**)&rPl_p,   rPl);
    cudaGetSymbolAddress((void**)&vtPh_p,  vtPh);
    cudaGetSymbolAddress((void**)&vtPl_p,  vtPl);
    uint32_t *qkvPh_p, *qkvPl_p, *wrPh_p, *wrPl_p, *woPh_p, *woPl_p, *w1Ph_p, *w1Pl_p, *w2Ph_p, *w2Pl_p;
    cudaGetSymbolAddress((void**)&qkvPh_p, qkvPh);
    cudaGetSymbolAddress((void**)&qkvPl_p, qkvPl);
    cudaGetSymbolAddress((void**)&wrPh_p,  wrPh);
    cudaGetSymbolAddress((void**)&wrPl_p,  wrPl);
    cudaGetSymbolAddress((void**)&woPh_p,  woPh);
    cudaGetSymbolAddress((void**)&woPl_p,  woPl);
    cudaGetSymbolAddress((void**)&w1Ph_p,  w1Ph);
    cudaGetSymbolAddress((void**)&w1Pl_p,  w1Pl);
    cudaGetSymbolAddress((void**)&w2Ph_p,  w2Ph);
    cudaGetSymbolAddress((void**)&w2Pl_p,  w2Pl);

    cudaFuncSetAttribute(fused_attn_kernel,
                         cudaFuncAttributeMaxDynamicSharedMemorySize, ATTN_SMEM);
    cudaFuncSetAttribute(mma_gemm,
                         cudaFuncAttributeMaxDynamicSharedMemorySize, GEMM_SMEM);

    convert_weight<<<dim3(1536 / 32, 512 / 64, NLAY), 256>>>(Wqkv, qkvPh_p, qkvPl_p, 512, 1536);
    convert_weight<<<dim3(512 / 32, 512 / 64, NLAY), 256>>>(Wr, wrPh_p, wrPl_p, 512, 512);
    convert_weight<<<dim3(512 / 32, 512 / 64, NLAY), 256>>>(Wo, woPh_p, woPl_p, 512, 512);
    convert_weight<<<dim3(2048 / 32, 512 / 64, NLAY), 256>>>(W1, w1Ph_p, w1Pl_p, 512, 2048);
    convert_weight<<<dim3(512 / 32, 2048 / 64, NLAY), 256>>>(W2, w2Ph_p, w2Pl_p, 2048, 512);

    build_w_kernel<<<(TT * 256 + 255) / 256, 256>>>(word_emb, mem_tok);
    build_pos_kernel<<<(TT * 256 + 255) / 256, 256>>>();

    const int MB = (TT + 127) / 128;   // 17

    for (int l = 0; l < NLAY; l++) {
        mma_gemm<<<dim3(24, MB, 1), 256, GEMM_SMEM>>>(
            wPh_p, wPl_p, 256,
            qkvPh_p + (size_t)l * 1536 * 256, qkvPl_p + (size_t)l * 1536 * 256, 256,
            g_hd_p, g_hd_p, 3 * DM,
            kPh_p, kPl_p, 256,
            nullptr, 0, 3, TT, 3 * DM, DM);
        mma_gemm<<<dim3(8, MB, 1), 256, GEMM_SMEM>>>(
            posPh_p, posPl_p, 256,
            wrPh_p + (size_t)l * 512 * 256, wrPl_p + (size_t)l * 512 * 256, 256,
            g_r_p, g_r_p, DM,
            rPh_p, rPl_p, 256,
            nullptr, 0, 2, TT, DM, DM);
        convert_vt<<<dim3(33, NH), 256>>>(g_hd_p, vtPh_p, vtPl_p);

        fused_attn_kernel<<<dim3(NH, 17), 512, ATTN_SMEM>>>(
            g_hd_p, g_r_p, kPh_p, kPl_p, vtPh_p, vtPl_p, rPh_p, rPl_p, rwb, rrb);

        mma_gemm<<<dim3(8, MB, 2), 256, GEMM_SMEM>>>(
            avPh_p, avPl_p, 256,
            woPh_p + (size_t)l * 512 * 256, woPl_p + (size_t)l * 512 * 256, 256,
            g_tmp_p, g_tmp2_p, DM,
            nullptr, nullptr, 0,
            nullptr, 0, 0, TT, DM, DM / 2);
        add_ln_kernel<<<TT, 256>>>(g_w_p, g_tmp_p, g_tmp2_p, ln1s + l * DM, ln1b + l * DM);
        mma_gemm<<<dim3(32, MB, 1), 256, GEMM_SMEM>>>(
            wPh_p, wPl_p, 256,
            w1Ph_p + (size_t)l * 2048 * 256, w1Pl_p + (size_t)l * 2048 * 256, 256,
            nullptr, nullptr, 0,
            ff1Ph_p, ff1Pl_p, DI / 2,
            b1 + (size_t)l * DI, 1, 1, TT, DI, DM);
        mma_gemm<<<dim3(8, MB, 2), 256, GEMM_SMEM>>>(
            ff1Ph_p, ff1Pl_p, 1024,
            w2Ph_p + (size_t)l * 512 * 1024, w2Pl_p + (size_t)l * 512 * 1024, 1024,
            g_tmp_p, g_tmp2_p, DM,
            nullptr, nullptr, 0,
            b2 + (size_t)l * DM, 0, 0, TT, DM, DI / 2);
        add_ln_kernel<<<TT, 256>>>(g_w_p, g_tmp_p, g_tmp2_p, ln2s + l * DM, ln2b + l * DM);
    }

    copy_out_kernel<<<(TT * DM + 255) / 256, 256>>>((float*)d_out);
}

// round 14
// speedup vs baseline: 1.1858x; 1.0466x over previous
#include <cuda_runtime.h>
#include <cuda_bf16.h>
#include <math.h>
#include <stdint.h>

// ---------------- problem constants ----------------
#define TT    2080
#define DM    512
#define NH    8
#define DH    64
#define DI    2048
#define NLAY  4
#define NMTOK 16
#define QL    2048
#define VTKP  1056

// ---------------- fp32 scratch ----------------
__device__ float g_w[TT * DM];
__device__ float g_heads[TT * 3 * DM];
__device__ float g_r[TT * DM];
__device__ float g_tmp[TT * DM];
__device__ float g_tmp2[TT * DM];

// ---------------- bf16 hi/lo pair-plane scratch ----------------
__device__ uint32_t wPh[TT * 256],   wPl[TT * 256];
__device__ uint32_t posPh[TT * 256], posPl[TT * 256];
__device__ uint32_t avPh[TT * 256],  avPl[TT * 256];
__device__ uint32_t ff1Ph[TT * 1024], ff1Pl[TT * 1024];
__device__ uint32_t kPh[TT * 256],   kPl[TT * 256];
__device__ uint32_t rPh[TT * 256],   rPl[TT * 256];
__device__ uint32_t vtPh[NH * 64 * VTKP], vtPl[NH * 64 * VTKP];
__device__ uint32_t qkvPh[NLAY * 1536 * 256], qkvPl[NLAY * 1536 * 256];
__device__ uint32_t wrPh[NLAY * 512 * 256],   wrPl[NLAY * 512 * 256];
__device__ uint32_t woPh[NLAY * 512 * 256],   woPl[NLAY * 512 * 256];
__device__ uint32_t w1Ph[NLAY * 2048 * 256],  w1Pl[NLAY * 2048 * 256];
__device__ uint32_t w2Ph[NLAY * 512 * 1024],  w2Pl[NLAY * 512 * 1024];

// ---------------- bf16x3 helpers ----------------
__device__ __forceinline__ void split2(float x0, float x1, uint32_t& hw, uint32_t& lw) {
    __nv_bfloat162 h, l;
    h.x = __float2bfloat16(x0);
    h.y = __float2bfloat16(x1);
    l.x = __float2bfloat16(x0 - __bfloat162float(h.x));
    l.y = __float2bfloat16(x1 - __bfloat162float(h.y));
    hw = *reinterpret_cast<uint32_t*>(&h);
    lw = *reinterpret_cast<uint32_t*>(&l);
}

__device__ __forceinline__ void mma16(float (&c)[4], const uint32_t (&a)[4],
                                      uint32_t b0, uint32_t b1) {
    asm volatile(
        "mma.sync.aligned.m16n8k16.row.col.f32.bf16.bf16.f32 "
        "{%0,%1,%2,%3}, {%4,%5,%6,%7}, {%8,%9}, {%0,%1,%2,%3};"
        : "+f"(c[0]), "+f"(c[1]), "+f"(c[2]), "+f"(c[3])
        : "r"(a[0]), "r"(a[1]), "r"(a[2]), "r"(a[3]), "r"(b0), "r"(b1));
}

__device__ __forceinline__ uint32_t sm_u32(const void* p) {
    return (uint32_t)__cvta_generic_to_shared(p);
}

__device__ __forceinline__ void ldsm4(uint32_t (&r)[4], uint32_t a) {
    asm volatile("ldmatrix.sync.aligned.m8n8.x4.shared.b16 {%0,%1,%2,%3}, [%4];"
                 : "=r"(r[0]), "=r"(r[1]), "=r"(r[2]), "=r"(r[3]) : "r"(a));
}

__device__ __forceinline__ void cpa16(uint32_t dst, const void* src, int szok) {
    asm volatile("cp.async.cg.shared.global [%0], [%1], 16, %2;"
                 :: "r"(dst), "l"(src), "r"(szok));
}

__device__ __forceinline__ int boff(int n) { return n * 36 + ((n >> 3) << 2); }
#define BPLANE (64 * 36 + 32)

// ---------------- prep kernels ----------------
__global__ void build_w_kernel(const float* __restrict__ word_emb,
                               const float* __restrict__ mem) {
    int idx = blockIdx.x * blockDim.x + threadIdx.x;
    if (idx >= TT * 256) return;
    int row = idx >> 8, c2 = idx & 255;
    int c = 2 * c2;
    float v0, v1;
    if (row < NMTOK) {
        v0 = mem[row * DM + c]; v1 = mem[row * DM + c + 1];
    } else if (row < NMTOK + QL) {
        v0 = word_emb[(row - NMTOK) * DM + c]; v1 = word_emb[(row - NMTOK) * DM + c + 1];
    } else {
        v0 = mem[(row - NMTOK - QL) * DM + c]; v1 = mem[(row - NMTOK - QL) * DM + c + 1];
    }
    g_w[row * DM + c] = v0;
    g_w[row * DM + c + 1] = v1;
    uint32_t hw, lw;
    split2(v0, v1, hw, lw);
    wPh[idx] = hw; wPl[idx] = lw;
}

__global__ void build_pos_kernel() {
    int idx = blockIdx.x * blockDim.x + threadIdx.x;
    if (idx >= TT * 256) return;
    int row = idx >> 8, c2 = idx & 255;
    float v0, v1;
    #pragma unroll
    for (int u = 0; u < 2; u++) {
        int c = 2 * c2 + u;
        int f = (c < DM / 2) ? c : (c - DM / 2);
        double invf = exp(-((double)(2 * f) / (double)DM) * log(10000.0));
        double val = (double)(TT - 1 - row) * invf;
        float r = (float)((c < DM / 2) ? sin(val) : cos(val));
        if (u == 0) v0 = r; else v1 = r;
    }
    uint32_t hw, lw;
    split2(v0, v1, hw, lw);
    posPh[idx] = hw; posPl[idx] = lw;
}

// ---------------- weight convert ----------------
__global__ void convert_weight(const float* __restrict__ W,
                               uint32_t* __restrict__ Ph, uint32_t* __restrict__ Pl,
                               int K, int N) {
    __shared__ float S[64][33];
    const int l = blockIdx.z;
    const float* Wl = W + (size_t)l * K * N;
    const int Kw = K >> 1;
    uint32_t* PhL = Ph + (size_t)l * N * Kw;
    uint32_t* PlL = Pl + (size_t)l * N * Kw;
    const int n0 = blockIdx.x * 32, k0 = blockIdx.y * 64;
    const int t = threadIdx.x;
    {
        int n = t & 31, kk = t >> 5;
        #pragma unroll
        for (int i = 0; i < 8; i++)
            S[kk + 8 * i][n] = Wl[(size_t)(k0 + kk + 8 * i) * N + n0 + n];
    }
    __syncthreads();
    {
        int nn = t >> 3, kq = t & 7;
        uint32_t oh[4], ol[4];
        #pragma unroll
        for (int i = 0; i < 4; i++) {
            int kp = kq * 4 + i;
            split2(S[2 * kp][nn], S[2 * kp + 1][nn], oh[i], ol[i]);
        }
        size_t base = (size_t)(n0 + nn) * Kw + (k0 >> 1) + kq * 4;
        *reinterpret_cast<uint4*>(PhL + base) = *reinterpret_cast<uint4*>(oh);
        *reinterpret_cast<uint4*>(PlL + base) = *reinterpret_cast<uint4*>(ol);
    }
}

// ---------------- V transpose-convert ----------------
__global__ void convert_vt(const float* __restrict__ heads,
                           uint32_t* __restrict__ Vh, uint32_t* __restrict__ Vl) {
    __shared__ float S[64][65];
    const int jt = blockIdx.x, h = blockIdx.y;
    const int j0 = jt * 64, tid = threadIdx.x;
    for (int t = tid; t < 64 * 16; t += 256) {
        int r = t >> 4, c4 = (t & 15) * 4;
        int gj = j0 + r;
        float4 v = make_float4(0.f, 0.f, 0.f, 0.f);
        if (gj < TT)
            v = *(const float4*)(heads + (size_t)gj * 1536 + 1024 + h * 64 + c4);
        S[r][c4] = v.x; S[r][c4 + 1] = v.y; S[r][c4 + 2] = v.z; S[r][c4 + 3] = v.w;
    }
    __syncthreads();
    const int f = tid >> 2, wq = (tid & 3) * 8;
    size_t base = ((size_t)h * 64 + f) * VTKP + (j0 >> 1) + wq;
    #pragma unroll
    for (int i = 0; i < 8; i++) {
        int kp = wq + i;
        uint32_t hw, lw;
        split2(S[2 * kp][f], S[2 * kp + 1][f], hw, lw);
        Vh[base + i] = hw; Vl[base + i] = lw;
    }
}

// ---------------- GEMM: cp.async 3-stage pipeline ----------------
#define PPA 20
#define PPB 20
#define ASTG (128 * PPA)
#define BSTG (64 * PPB)
#define STG_W (2 * ASTG + 2 * BSTG)
#define NSTG 3
#define GEMM_SMEM (NSTG * STG_W * 4)

__global__ __launch_bounds__(256, 2)
void mma_gemm(const uint32_t* __restrict__ Ahg, const uint32_t* __restrict__ Alg, int ldaw,
              const uint32_t* __restrict__ Bhg, const uint32_t* __restrict__ Blg, int ldbw,
              float* __restrict__ C, float* __restrict__ C2, int ldc,
              uint32_t* __restrict__ OutH, uint32_t* __restrict__ OutL, int ldcw,
              const float* __restrict__ cbias, int doRelu, int outMode,
              int M, int N, int Ksub) {
    extern __shared__ uint32_t gsm[];
    const uint32_t smBase = sm_u32(gsm);

    const int bm = blockIdx.y * 128, bn = blockIdx.x * 64;
    const int kOffW = blockIdx.z * (Ksub >> 1);
    if (blockIdx.z == 1) C = C2;

    const int tid = threadIdx.x;
    const int lane = tid & 31, warp = tid >> 5;
    const int wm = warp & 3, wn = warp >> 2;
    const int g4 = lane >> 2, l4 = lane & 3;

    float acc[2][4][4] = {};

    const int arow = tid >> 2;
    const int akq = tid & 3;

    const int aRow = lane & 15;
    const uint32_t aHiB = ((lane >> 4) & 1) * 16;
    const uint32_t adA = smBase + (uint32_t)((wm * 32 + aRow) * PPA) * 4 + aHiB;
    const int bRowN = ((lane >> 4) & 1) * 8 + (lane & 7);
    const uint32_t bHiB = ((lane >> 3) & 1) * 16;
    const uint32_t adB0 = smBase + (uint32_t)(2 * ASTG + (wn * 32 + bRowN) * PPB) * 4 + bHiB;
    const uint32_t adB1 = adB0 + 16 * PPB * 4;

    const uint32_t dA = (uint32_t)(arow * PPA + akq * 4) * 4;
    const uint32_t dB = (uint32_t)(2 * ASTG + arow * PPB + akq * 4) * 4;

    auto issueStage = [&](int iter, int st) {
        const int kw = kOffW + iter * 16 + akq * 4;
        const uint32_t base = smBase + (uint32_t)st * (STG_W * 4);
        #pragma unroll
        for (int p = 0; p < 2; p++) {
            int row = bm + p * 64 + arow;
            int ok = (row < M) ? 16 : 0;
            int rowc = (row < M) ? row : 0;
            cpa16(base + dA + p * 64 * PPA * 4, Ahg + (size_t)rowc * ldaw + kw, ok);
            cpa16(base + dA + p * 64 * PPA * 4 + ASTG * 4, Alg + (size_t)rowc * ldaw + kw, ok);
        }
        {
            int row = bn + arow;
            cpa16(base + dB, Bhg + (size_t)row * ldbw + kw, 16);
            cpa16(base + dB + BSTG * 4, Blg + (size_t)row * ldbw + kw, 16);
        }
    };

    const int niter = Ksub >> 5;
    issueStage(0, 0);
    asm volatile("cp.async.commit_group;" ::: "memory");
    issueStage(1, 1);
    asm volatile("cp.async.commit_group;" ::: "memory");

    int st = 0;
    for (int i = 0; i < niter; i++) {
        asm volatile("cp.async.wait_group 1;" ::: "memory");
        __syncthreads();
        const uint32_t so = (uint32_t)st * (STG_W * 4);
        #pragma unroll
        for (int ks = 0; ks < 2; ks++) {
            uint32_t ahh[2][4], alo[2][4];
            ldsm4(ahh[0], adA + so + ks * 32);
            ldsm4(ahh[1], adA + so + 16 * PPA * 4 + ks * 32);
            ldsm4(alo[0], adA + so + ASTG * 4 + ks * 32);
            ldsm4(alo[1], adA + so + ASTG * 4 + 16 * PPA * 4 + ks * 32);
            uint32_t bhh[2][4], blo[2][4];
            ldsm4(bhh[0], adB0 + so + ks * 32);
            ldsm4(bhh[1], adB1 + so + ks * 32);
            ldsm4(blo[0], adB0 + so + BSTG * 4 + ks * 32);
            ldsm4(blo[1], adB1 + so + BSTG * 4 + ks * 32);
            #pragma unroll
            for (int am = 0; am < 2; am++)
                #pragma unroll
                for (int an = 0; an < 4; an++) {
                    const int g = an >> 1, x = (an & 1) * 2;
                    mma16(acc[am][an], ahh[am], bhh[g][x], bhh[g][x + 1]);
                    mma16(acc[am][an], ahh[am], blo[g][x], blo[g][x + 1]);
                    mma16(acc[am][an], alo[am], bhh[g][x], bhh[g][x + 1]);
                }
        }
        if (i + 2 < niter) {
            int st2 = st + 2; if (st2 >= NSTG) st2 -= NSTG;
            issueStage(i + 2, st2);
        }
        asm volatile("cp.async.commit_group;" ::: "memory");
        st = (st + 1 == NSTG) ? 0 : st + 1;
    }

    bool wantPlane, wantF32;
    if (outMode == 0)      { wantPlane = false; wantF32 = true; }
    else if (outMode == 1) { wantPlane = true;  wantF32 = false; }
    else if (outMode == 2) { wantPlane = true;  wantF32 = true; }
    else {
        bool isk = (bn >= 512 && bn < 1024);
        wantPlane = isk; wantF32 = !isk;
    }
    const int pShift = (outMode == 3) ? 512 : 0;

    #pragma unroll
    for (int am = 0; am < 2; am++) {
        int row0 = bm + wm * 32 + am * 16 + g4;
        #pragma unroll
        for (int an = 0; an < 4; an++) {
            int col0 = bn + wn * 32 + an * 8 + 2 * l4;
            float v0 = acc[am][an][0], v1 = acc[am][an][1];
            float v2 = acc[am][an][2], v3 = acc[am][an][3];
            if (cbias && blockIdx.z == 0) {
                float b0 = cbias[col0], b1 = cbias[col0 + 1];
                v0 += b0; v1 += b1; v2 += b0; v3 += b1;
            }
            if (doRelu) {
                v0 = fmaxf(v0, 0.f); v1 = fmaxf(v1, 0.f);
                v2 = fmaxf(v2, 0.f); v3 = fmaxf(v3, 0.f);
            }
            if (wantPlane) {
                uint32_t hw, lw;
                int colP = (col0 - pShift) >> 1;
                if (row0 < M) {
                    split2(v0, v1, hw, lw);
                    OutH[(size_t)row0 * ldcw + colP] = hw;
                    OutL[(size_t)row0 * ldcw + colP] = lw;
                }
                if (row0 + 8 < M) {
                    split2(v2, v3, hw, lw);
                    OutH[(size_t)(row0 + 8) * ldcw + colP] = hw;
                    OutL[(size_t)(row0 + 8) * ldcw + colP] = lw;
                }
            }
            if (wantF32) {
                if (row0 < M) {
                    C[(size_t)row0 * ldc + col0]     = v0;
                    C[(size_t)row0 * ldc + col0 + 1] = v1;
                }
                if (row0 + 8 < M) {
                    C[(size_t)(row0 + 8) * ldc + col0]     = v2;
                    C[(size_t)(row0 + 8) * ldc + col0 + 1] = v3;
                }
            }
        }
    }
}

// ---------------- fused flash-style relative attention ----------------
// 512 threads, 16 warps; K/V double-buffered; BD chunk pipelined 1 tile ahead.
// Exactly 2 __syncthreads per tile.
#define RPAD 68
#define RSLOT (64 * RPAD)
#define ATTN_WORDS (16 * BPLANE + 3 * RSLOT + 512)
#define ATTN_SMEM (ATTN_WORDS * 4)

__global__ __launch_bounds__(512, 1)
void fused_attn_kernel(const float* __restrict__ heads,
                       const float* __restrict__ rbuf,
                       const uint32_t* __restrict__ kGh, const uint32_t* __restrict__ kGl,
                       const uint32_t* __restrict__ vGh, const uint32_t* __restrict__ vGl,
                       const uint32_t* __restrict__ rGh, const uint32_t* __restrict__ rGl,
                       const float* __restrict__ rwb,
                       const float* __restrict__ rrb) {
    extern __shared__ uint32_t smu[];
    uint32_t* Qwh = smu;
    uint32_t* Qwl = Qwh + BPLANE;
    uint32_t* Qrh = Qwl + BPLANE;
    uint32_t* Qrl = Qrh + BPLANE;
    uint32_t* Kh  = Qrl + BPLANE;          // 2 buffers
    uint32_t* Kl  = Kh  + 2 * BPLANE;      // 2 buffers
    uint32_t* Rh  = Kl  + 2 * BPLANE;
    uint32_t* Rl  = Rh  + BPLANE;
    uint32_t* Vth = Rl  + BPLANE;          // 2 buffers
    uint32_t* Vtl = Vth + 2 * BPLANE;      // 2 buffers
    uint32_t* Ph  = Vtl + 2 * BPLANE;
    uint32_t* Pl  = Ph  + BPLANE;
    float* Ring = (float*)(Pl + BPLANE);
    float* redm = Ring + 3 * RSLOT;     // [4][64]
    float* reds = redm + 256;           // [4][64]

    const int h = blockIdx.x;
    const int p = blockIdx.y;
    const int tid = threadIdx.x;
    const int lane = tid & 31, warp = tid >> 5;
    const int wm = warp & 3, wn = warp >> 2;
    const int g4 = lane >> 2, l4 = lane & 3;
    const int wr0 = wm * 16 + g4;
    const int colbase = wn * 16;

    const int aRow = lane & 15;
    const uint32_t aHiB = ((lane >> 4) & 1) * 16;
    const uint32_t aOff = (uint32_t)boff(wm * 16 + aRow) * 4 + aHiB;
    const uint32_t adQwh = sm_u32(Qwh) + aOff, adQwl = sm_u32(Qwl) + aOff;
    const uint32_t adQrh = sm_u32(Qrh) + aOff, adQrl = sm_u32(Qrl) + aOff;
    const uint32_t adPh  = sm_u32(Ph)  + aOff, adPl  = sm_u32(Pl)  + aOff;
    const int bRowN = ((lane >> 4) & 1) * 8 + (lane & 7);
    const uint32_t bHiB = ((lane >> 3) & 1) * 16;
    const uint32_t bO0 = (uint32_t)boff(colbase + bRowN) * 4 + bHiB;
    const uint32_t adKh = sm_u32(Kh) + bO0;
    const uint32_t adKl = sm_u32(Kl) + bO0;
    const uint32_t adRh = sm_u32(Rh) + bO0;
    const uint32_t adRl = sm_u32(Rl) + bO0;
    const uint32_t adVh = sm_u32(Vth) + bO0;
    const uint32_t adVl = sm_u32(Vtl) + bO0;

    uint4 pkh, pkl, pvh, pvl;
    const int prow = tid >> 3, pwq = (tid & 7) * 4;
    const size_t vtBase = ((size_t)h * 64 + prow) * VTKP;
    auto prefetchKV = [&](int j0) {
        int gj = j0 + prow;
        if (gj < TT) {
            pkh = *(const uint4*)(kGh + (size_t)gj * 256 + h * 32 + pwq);
            pkl = *(const uint4*)(kGl + (size_t)gj * 256 + h * 32 + pwq);
        } else {
            pkh = make_uint4(0, 0, 0, 0);
            pkl = make_uint4(0, 0, 0, 0);
        }
        pvh = *(const uint4*)(vGh + vtBase + (j0 >> 1) + pwq);
        pvl = *(const uint4*)(vGl + vtBase + (j0 >> 1) + pwq);
    };
    auto storeKV = [&](int buf) {
        int wi = buf * BPLANE + boff(prow) + pwq;
        *(uint4*)(Kh + wi) = pkh;
        *(uint4*)(Kl + wi) = pkl;
        *(uint4*)(Vth + wi) = pvh;
        *(uint4*)(Vtl + wi) = pvl;
    };
    auto loadRchunk = [&](int c) {
        int grow = c * 64 + prow;
        uint4 r0 = make_uint4(0, 0, 0, 0), r1 = r0;
        if (grow < TT) {
            r0 = *(const uint4*)(rGh + (size_t)grow * 256 + h * 32 + pwq);
            r1 = *(const uint4*)(rGl + (size_t)grow * 256 + h * 32 + pwq);
        }
        int wi = boff(prow) + pwq;
        *(uint4*)(Rh + wi) = r0;
        *(uint4*)(Rl + wi) = r1;
    };
    auto bdChunk = [&](int c) {
        float cacc[2][4];
        #pragma unroll
        for (int a = 0; a < 2; a++)
            cacc[a][0] = cacc[a][1] = cacc[a][2] = cacc[a][3] = 0.f;
        #pragma unroll
        for (int kc = 0; kc < 4; kc++) {
            uint32_t ah[4], al[4];
            ldsm4(ah, adQrh + kc * 32);
            ldsm4(al, adQrl + kc * 32);
            uint32_t bh[4], bl[4];
            ldsm4(bh, adRh + kc * 32);
            ldsm4(bl, adRl + kc * 32);
            #pragma unroll
            for (int an = 0; an < 2; an++) {
                const int x = an * 2;
                mma16(cacc[an], ah, bh[x], bh[x + 1]);
                mma16(cacc[an], ah, bl[x], bl[x + 1]);
                mma16(cacc[an], al, bh[x], bh[x + 1]);
            }
        }
        float* slot = Ring + (c % 3) * RSLOT;
        #pragma unroll
        for (int an = 0; an < 2; an++) {
            int col = colbase + an * 8 + 2 * l4;
            slot[wr0 * RPAD + col]           = cacc[an][0];
            slot[wr0 * RPAD + col + 1]       = cacc[an][1];
            slot[(wr0 + 8) * RPAD + col]     = cacc[an][2];
            slot[(wr0 + 8) * RPAD + col + 1] = cacc[an][3];
        }
    };

    int blist[2]; int nblk;
    if (p < 16) { blist[0] = p; blist[1] = 31 - p; nblk = 2; }
    else        { blist[0] = 32; nblk = 1; }

    for (int bi = 0; bi < nblk; bi++) {
        const int b = blist[bi];
        const int i0 = b * 64;
        const int validRows = min(64, TT - i0);
        const int njt = (b < 32) ? (b + 1) : 33;

        __syncthreads();   // protect smem reuse from previous block
        // Q load
        for (int t = tid; t < 64 * 16; t += 512) {
            int r = t >> 4, c4 = (t & 15) * 4;
            int grow = i0 + r;
            float4 q = make_float4(0.f, 0.f, 0.f, 0.f);
            if (grow < TT)
                q = *(const float4*)(heads + (size_t)grow * (3 * DM) + h * DH + c4);
            float4 bw = *(const float4*)(rwb + h * DH + c4);
            float4 br = *(const float4*)(rrb + h * DH + c4);
            int wi = boff(r) + (c4 >> 1);
            uint32_t hw, lw;
            split2(q.x + bw.x, q.y + bw.y, hw, lw); Qwh[wi] = hw;     Qwl[wi] = lw;
            split2(q.z + bw.z, q.w + bw.w, hw, lw); Qwh[wi + 1] = hw; Qwl[wi + 1] = lw;
            split2(q.x + br.x, q.y + br.y, hw, lw); Qrh[wi] = hw;     Qrl[wi] = lw;
            split2(q.z + br.z, q.w + br.w, hw, lw); Qrh[wi + 1] = hw; Qrl[wi + 1] = lw;
        }
        prefetchKV(0);
        storeKV(0);

        int nextChunk = (2016 - i0) / 64;
        if (nextChunk < 0) nextChunk = 0;

        // prologue: chunks needed by tile 0
        const int chi0 = min(TT - 1, TT - 1 - i0 + 63) >> 6;
        while (nextChunk <= chi0) {
            __syncthreads();
            loadRchunk(nextChunk);
            __syncthreads();
            bdChunk(nextChunk);
            nextChunk++;
        }
        __syncthreads();   // ring + K/V buf0 + Q visible

        float o[2][4];
        #pragma unroll
        for (int a = 0; a < 2; a++) { o[a][0] = o[a][1] = o[a][2] = o[a][3] = 0.f; }
        float mrow[2] = {-1e30f, -1e30f};
        float lrow[2] = {0.f, 0.f};

        for (int jt = 0; jt < njt; jt++) {
            const int j0 = jt * 64;
            const uint32_t kb = (uint32_t)(jt & 1) * (BPLANE * 4);

            // ---- AC MMA ----
            float s[2][4];
            #pragma unroll
            for (int a = 0; a < 2; a++)
                s[a][0] = s[a][1] = s[a][2] = s[a][3] = 0.f;
            #pragma unroll
            for (int kc = 0; kc < 4; kc++) {
                uint32_t ah[4], al[4];
                ldsm4(ah, adQwh + kc * 32);
                ldsm4(al, adQwl + kc * 32);
                uint32_t bh[4], bl[4];
                ldsm4(bh, adKh + kb + kc * 32);
                ldsm4(bl, adKl + kb + kc * 32);
                #pragma unroll
                for (int an = 0; an < 2; an++) {
                    const int x = an * 2;
                    mma16(s[an], ah, bh[x], bh[x + 1]);
                    mma16(s[an], ah, bl[x], bl[x + 1]);
                    mma16(s[an], al, bh[x], bh[x + 1]);
                }
            }

            // ---- combine with rel-shifted BD ----
            float tmax[2] = {-1e30f, -1e30f};
            #pragma unroll
            for (int an = 0; an < 2; an++) {
                #pragma unroll
                for (int e = 0; e < 4; e++) {
                    int rh = e >> 1;
                    int di = wr0 + rh * 8;
                    int dj = colbase + an * 8 + 2 * l4 + (e & 1);
                    int i = i0 + di, j = j0 + dj;
                    float v = -1e30f;
                    if (di < validRows && j < TT) {
                        int jmaxr = (i < NMTOK) ? (NMTOK - 1)
                                  : ((i >= TT - NMTOK) ? (TT - 1) : i);
                        if (j <= jmaxr) {
                            float bd;
                            if (j <= i) {
                                int jr = TT - 1 - i + j;
                                bd = Ring[((jr >> 6) % 3) * RSLOT + di * RPAD + (jr & 63)];
                            } else if (j == i + 1) {
                                bd = 0.f;
                            } else {
                                const float* rr = rbuf + (size_t)(j - i - 2) * DM + h * DH;
                                float accd = 0.f;
                                #pragma unroll 8
                                for (int d2 = 0; d2 < 32; d2++) {
                                    uint32_t wh = Qrh[boff(di + 1) + d2];
                                    uint32_t wl = Qrl[boff(di + 1) + d2];
                                    __nv_bfloat162 h2 = *reinterpret_cast<__nv_bfloat162*>(&wh);
                                    __nv_bfloat162 l2 = *reinterpret_cast<__nv_bfloat162*>(&wl);
                                    float q0 = __bfloat162float(h2.x) + __bfloat162float(l2.x);
                                    float q1 = __bfloat162float(h2.y) + __bfloat162float(l2.y);
                                    accd += q0 * rr[2 * d2] + q1 * rr[2 * d2 + 1];
                                }
                                bd = accd;
                            }
                            v = (s[an][e] + bd) * 0.125f;
                        }
                    }
                    s[an][e] = v;
                    tmax[rh] = fmaxf(tmax[rh], v);
                }
            }
            #pragma unroll
            for (int rh = 0; rh < 2; rh++) {
                tmax[rh] = fmaxf(tmax[rh], __shfl_xor_sync(0xffffffffu, tmax[rh], 1));
                tmax[rh] = fmaxf(tmax[rh], __shfl_xor_sync(0xffffffffu, tmax[rh], 2));
            }
            if (l4 == 0) {
                redm[wn * 64 + wm * 16 + g4]     = tmax[0];
                redm[wn * 64 + wm * 16 + g4 + 8] = tmax[1];
            }

            // pipelined loads for next tile
            bool needChunk = false;
            int cN = nextChunk;
            if (jt + 1 < njt) {
                prefetchKV((jt + 1) * 64);
                int chiN = min(TT - 1, TT - 1 - i0 + (jt + 1) * 64 + 63) >> 6;
                if (nextChunk <= chiN) { needChunk = true; loadRchunk(cN); }
            }
            __syncthreads();   // (c): redm + R chunk visible

            float scl[2], lsum[2] = {0.f, 0.f};
            #pragma unroll
            for (int rh = 0; rh < 2; rh++) {
                int row = wm * 16 + g4 + rh * 8;
                float tm = fmaxf(fmaxf(redm[row], redm[64 + row]),
                                 fmaxf(redm[128 + row], redm[192 + row]));
                float mnew = fmaxf(mrow[rh], tm);
                scl[rh] = expf(mrow[rh] - mnew);
                mrow[rh] = mnew;
            }
            #pragma unroll
            for (int an = 0; an < 2; an++) {
                #pragma unroll
                for (int e = 0; e < 4; e++) {
                    int rh = e >> 1;
                    float ev = expf(s[an][e] - mrow[rh]);
                    s[an][e] = ev;
                    lsum[rh] += ev;
                }
            }
            #pragma unroll
            for (int rh = 0; rh < 2; rh++) {
                lsum[rh] += __shfl_xor_sync(0xffffffffu, lsum[rh], 1);
                lsum[rh] += __shfl_xor_sync(0xffffffffu, lsum[rh], 2);
            }
            if (l4 == 0) {
                reds[wn * 64 + wm * 16 + g4]     = lsum[0];
                reds[wn * 64 + wm * 16 + g4 + 8] = lsum[1];
            }
            #pragma unroll
            for (int an = 0; an < 2; an++) {
                int cp = (colbase >> 1) + an * 4 + l4;
                uint32_t hw, lw;
                split2(s[an][0], s[an][1], hw, lw);
                Ph[boff(wr0) + cp] = hw; Pl[boff(wr0) + cp] = lw;
                split2(s[an][2], s[an][3], hw, lw);
                Ph[boff(wr0 + 8) + cp] = hw; Pl[boff(wr0 + 8) + cp] = lw;
            }
            if (jt + 1 < njt) storeKV((jt + 1) & 1);
            if (needChunk) { bdChunk(cN); nextChunk++; }
            __syncthreads();   // (d): reds + P + next K/V + ring visible

            #pragma unroll
            for (int rh = 0; rh < 2; rh++) {
                int row = wm * 16 + g4 + rh * 8;
                lrow[rh] = lrow[rh] * scl[rh] +
                           reds[row] + reds[64 + row] + reds[128 + row] + reds[192 + row];
            }
            #pragma unroll
            for (int an = 0; an < 2; an++) {
                o[an][0] *= scl[0]; o[an][1] *= scl[0];
                o[an][2] *= scl[1]; o[an][3] *= scl[1];
            }

            // ---- PV MMA ----
            #pragma unroll
            for (int kc = 0; kc < 4; kc++) {
                uint32_t ah[4], al[4];
                ldsm4(ah, adPh + kc * 32);
                ldsm4(al, adPl + kc * 32);
                uint32_t bh[4], bl[4];
                ldsm4(bh, adVh + kb + kc * 32);
                ldsm4(bl, adVl + kb + kc * 32);
                #pragma unroll
                for (int an = 0; an < 2; an++) {
                    const int x = an * 2;
                    mma16(o[an], ah, bh[x], bh[x + 1]);
                    mma16(o[an], ah, bl[x], bl[x + 1]);
                    mma16(o[an], al, bh[x], bh[x + 1]);
                }
            }
        } // j-tiles

        float inv0 = 1.f / lrow[0], inv1 = 1.f / lrow[1];
        #pragma unroll
        for (int an = 0; an < 2; an++) {
            int colw = (h * DH + colbase + an * 8 + 2 * l4) >> 1;
            int r0 = i0 + wr0;
            uint32_t hw, lw;
            if (wr0 < validRows) {
                split2(o[an][0] * inv0, o[an][1] * inv0, hw, lw);
                avPh[(size_t)r0 * 256 + colw] = hw;
                avPl[(size_t)r0 * 256 + colw] = lw;
            }
            if (wr0 + 8 < validRows) {
                split2(o[an][2] * inv1, o[an][3] * inv1, hw, lw);
                avPh[(size_t)(r0 + 8) * 256 + colw] = hw;
                avPl[(size_t)(r0 + 8) * 256 + colw] = lw;
            }
        }
    } // blocks
}

// ---------------- residual add + layernorm (1-barrier, emits w planes) ----------------
__global__ void add_ln_kernel(float* __restrict__ w, const float* __restrict__ delta,
                              const float* __restrict__ delta2,
                              const float* __restrict__ gam, const float* __restrict__ bta) {
    int row = blockIdx.x;
    int tid = threadIdx.x;
    int c = 2 * tid;
    __shared__ float s1m[8], s2m[8];
    float x0 = w[row * DM + c]     + delta[row * DM + c];
    float x1 = w[row * DM + c + 1] + delta[row * DM + c + 1];
    if (delta2) {
        x0 += delta2[row * DM + c];
        x1 += delta2[row * DM + c + 1];
    }
    float s1 = x0 + x1;
    float s2 = x0 * x0 + x1 * x1;
    #pragma unroll
    for (int o = 16; o > 0; o >>= 1) {
        s1 += __shfl_xor_sync(0xffffffffu, s1, o);
        s2 += __shfl_xor_sync(0xffffffffu, s2, o);
    }
    if ((tid & 31) == 0) { s1m[tid >> 5] = s1; s2m[tid >> 5] = s2; }
    __syncthreads();
    float t1 = 0.f, t2 = 0.f;
    #pragma unroll
    for (int i = 0; i < 8; i++) { t1 += s1m[i]; t2 += s2m[i]; }
    float mean = t1 * (1.f / DM);
    float var = t2 * (1.f / DM) - mean * mean;
    float inv = 1.f / sqrtf(var + 1e-5f);
    float y0 = (x0 - mean) * inv * gam[c]     + bta[c];
    float y1 = (x1 - mean) * inv * gam[c + 1] + bta[c + 1];
    w[row * DM + c]     = y0;
    w[row * DM + c + 1] = y1;
    uint32_t hw, lw;
    split2(y0, y1, hw, lw);
    wPh[row * 256 + tid] = hw;
    wPl[row * 256 + tid] = lw;
}

__global__ void copy_out_kernel(float* __restrict__ out) {
    int idx = blockIdx.x * blockDim.x + threadIdx.x;
    if (idx < TT * DM) out[idx] = g_w[idx];
}

// ---------------- launcher ----------------
extern "C" void kernel_launch(void* const* d_in, const int* in_sizes, int n_in,
                              void* d_out, int out_size) {
    (void)in_sizes; (void)n_in; (void)out_size;
    const float* word_emb = (const float*)d_in[0];
    const float* mem_tok  = (const float*)d_in[1];
    const float* Wqkv     = (const float*)d_in[2];
    const float* Wr       = (const float*)d_in[3];
    const float* Wo       = (const float*)d_in[4];
    const float* ln1s     = (const float*)d_in[5];
    const float* ln1b     = (const float*)d_in[6];
    const float* W1       = (const float*)d_in[7];
    const float* b1       = (const float*)d_in[8];
    const float* W2       = (const float*)d_in[9];
    const float* b2       = (const float*)d_in[10];
    const float* ln2s     = (const float*)d_in[11];
    const float* ln2b     = (const float*)d_in[12];
    const float* rwb      = (const float*)d_in[13];
    const float* rrb      = (const float*)d_in[14];

    float *g_w_p, *g_hd_p, *g_r_p, *g_tmp_p, *g_tmp2_p;
    cudaGetSymbolAddress((void**)&g_w_p,    g_w);
    cudaGetSymbolAddress((void**)&g_hd_p,   g_heads);
    cudaGetSymbolAddress((void**)&g_r_p,    g_r);
    cudaGetSymbolAddress((void**)&g_tmp_p,  g_tmp);
    cudaGetSymbolAddress((void**)&g_tmp2_p, g_tmp2);
    uint32_t *wPh_p, *wPl_p, *posPh_p, *posPl_p, *avPh_p, *avPl_p, *ff1Ph_p, *ff1Pl_p;
    uint32_t *kPh_p, *kPl_p, *rPh_p, *rPl_p, *vtPh_p, *vtPl_p;
    cudaGetSymbolAddress((void**)&wPh_p,   wPh);
    cudaGetSymbolAddress((void**)&wPl_p,   wPl);
    cudaGetSymbolAddress((void**)&posPh_p, posPh);
    cudaGetSymbolAddress((void**)&posPl_p, posPl);
    cudaGetSymbolAddress((void**)&avPh_p,  avPh);
    cudaGetSymbolAddress((void**)&avPl_p,  avPl);
    cudaGetSymbolAddress((void**)&ff1Ph_p, ff1Ph);
    cudaGetSymbolAddress((void**)&ff1Pl_p, ff1Pl);
    cudaGetSymbolAddress((void**)&kPh_p,   kPh);
    cudaGetSymbolAddress((void**)&kPl_p,   kPl);
    cudaGetSymbolAddress((void**)&rPh_p,   rPh);
    cudaGetSymbolAddress((void**)&rPl_p,   rPl);
    cudaGetSymbolAddress((void**)&vtPh_p,  vtPh);
    cudaGetSymbolAddress((void**)&vtPl_p,  vtPl);
    uint32_t *qkvPh_p, *qkvPl_p, *wrPh_p, *wrPl_p, *woPh_p, *woPl_p, *w1Ph_p, *w1Pl_p, *w2Ph_p, *w2Pl_p;
    cudaGetSymbolAddress((void**)&qkvPh_p, qkvPh);
    cudaGetSymbolAddress((void**)&qkvPl_p, qkvPl);
    cudaGetSymbolAddress((void**)&wrPh_p,  wrPh);
    cudaGetSymbolAddress((void**)&wrPl_p,  wrPl);
    cudaGetSymbolAddress((void**)&woPh_p,  woPh);
    cudaGetSymbolAddress((void**)&woPl_p,  woPl);
    cudaGetSymbolAddress((void**)&w1Ph_p,  w1Ph);
    cudaGetSymbolAddress((void**)&w1Pl_p,  w1Pl);
    cudaGetSymbolAddress((void**)&w2Ph_p,  w2Ph);
    cudaGetSymbolAddress((void**)&w2Pl_p,  w2Pl);

    cudaFuncSetAttribute(fused_attn_kernel,
                         cudaFuncAttributeMaxDynamicSharedMemorySize, ATTN_SMEM);
    cudaFuncSetAttribute(mma_gemm,
                         cudaFuncAttributeMaxDynamicSharedMemorySize, GEMM_SMEM);

    convert_weight<<<dim3(1536 / 32, 512 / 64, NLAY), 256>>>(Wqkv, qkvPh_p, qkvPl_p, 512, 1536);
    convert_weight<<<dim3(512 / 32, 512 / 64, NLAY), 256>>>(Wr, wrPh_p, wrPl_p, 512, 512);
    convert_weight<<<dim3(512 / 32, 512 / 64, NLAY), 256>>>(Wo, woPh_p, woPl_p, 512, 512);
    convert_weight<<<dim3(2048 / 32, 512 / 64, NLAY), 256>>>(W1, w1Ph_p, w1Pl_p, 512, 2048);
    convert_weight<<<dim3(512 / 32, 2048 / 64, NLAY), 256>>>(W2, w2Ph_p, w2Pl_p, 2048, 512);

    build_w_kernel<<<(TT * 256 + 255) / 256, 256>>>(word_emb, mem_tok);
    build_pos_kernel<<<(TT * 256 + 255) / 256, 256>>>();

    const int MB = (TT + 127) / 128;   // 17

    for (int l = 0; l < NLAY; l++) {
        mma_gemm<<<dim3(24, MB, 1), 256, GEMM_SMEM>>>(
            wPh_p, wPl_p, 256,
            qkvPh_p + (size_t)l * 1536 * 256, qkvPl_p + (size_t)l * 1536 * 256, 256,
            g_hd_p, g_hd_p, 3 * DM,
            kPh_p, kPl_p, 256,
            nullptr, 0, 3, TT, 3 * DM, DM);
        mma_gemm<<<dim3(8, MB, 1), 256, GEMM_SMEM>>>(
            posPh_p, posPl_p, 256,
            wrPh_p + (size_t)l * 512 * 256, wrPl_p + (size_t)l * 512 * 256, 256,
            g_r_p, g_r_p, DM,
            rPh_p, rPl_p, 256,
            nullptr, 0, 2, TT, DM, DM);
        convert_vt<<<dim3(33, NH), 256>>>(g_hd_p, vtPh_p, vtPl_p);

        fused_attn_kernel<<<dim3(NH, 17), 512, ATTN_SMEM>>>(
            g_hd_p, g_r_p, kPh_p, kPl_p, vtPh_p, vtPl_p, rPh_p, rPl_p, rwb, rrb);

        mma_gemm<<<dim3(8, MB, 2), 256, GEMM_SMEM>>>(
            avPh_p, avPl_p, 256,
            woPh_p + (size_t)l * 512 * 256, woPl_p + (size_t)l * 512 * 256, 256,
            g_tmp_p, g_tmp2_p, DM,
            nullptr, nullptr, 0,
            nullptr, 0, 0, TT, DM, DM / 2);
        add_ln_kernel<<<TT, 256>>>(g_w_p, g_tmp_p, g_tmp2_p, ln1s + l * DM, ln1b + l * DM);
        mma_gemm<<<dim3(32, MB, 1), 256, GEMM_SMEM>>>(
            wPh_p, wPl_p, 256,
            w1Ph_p + (size_t)l * 2048 * 256, w1Pl_p + (size_t)l * 2048 * 256, 256,
            nullptr, nullptr, 0,
            ff1Ph_p, ff1Pl_p, DI / 2,
            b1 + (size_t)l * DI, 1, 1, TT, DI, DM);
        mma_gemm<<<dim3(8, MB, 2), 256, GEMM_SMEM>>>(
            ff1Ph_p, ff1Pl_p, 1024,
            w2Ph_p + (size_t)l * 512 * 1024, w2Pl_p + (size_t)l * 512 * 1024, 1024,
            g_tmp_p, g_tmp2_p, DM,
            nullptr, nullptr, 0,
            b2 + (size_t)l * DM, 0, 0, TT, DM, DI / 2);
        add_ln_kernel<<<TT, 256>>>(g_w_p, g_tmp_p, g_tmp2_p, ln2s + l * DM, ln2b + l * DM);
    }

    copy_out_kernel<<<(TT * DM + 255) / 256, 256>>>((float*)d_out);
}

// round 15
// speedup vs baseline: 1.2306x; 1.0378x over previous
#include <cuda_runtime.h>
#include <cuda_bf16.h>
#include <math.h>
#include <stdint.h>

// ---------------- problem constants ----------------
#define TT    2080
#define DM    512
#define NH    8
#define DH    64
#define DI    2048
#define NLAY  4
#define NMTOK 16
#define QL    2048
#define VTKP  1056

// ---------------- fp32 scratch ----------------
__device__ float g_w[TT * DM];
__device__ float g_heads[TT * 3 * DM];
__device__ float g_r4[NLAY * TT * DM];
__device__ float g_tmp[TT * DM];
__device__ float g_tmp2[TT * DM];

// ---------------- bf16 hi/lo pair-plane scratch ----------------
__device__ uint32_t wPh[TT * 256],   wPl[TT * 256];
__device__ uint32_t posPh[TT * 256], posPl[TT * 256];
__device__ uint32_t avPh[TT * 256],  avPl[TT * 256];
__device__ uint32_t ff1Ph[TT * 1024], ff1Pl[TT * 1024];
__device__ uint32_t kPh[TT * 256],   kPl[TT * 256];
__device__ uint32_t rPh4[NLAY * TT * 256], rPl4[NLAY * TT * 256];
__device__ uint32_t vtPh[NH * 64 * VTKP], vtPl[NH * 64 * VTKP];
__device__ uint32_t qkvPh[NLAY * 1536 * 256], qkvPl[NLAY * 1536 * 256];
__device__ uint32_t wrPh[NLAY * 512 * 256],   wrPl[NLAY * 512 * 256];
__device__ uint32_t woPh[NLAY * 512 * 256],   woPl[NLAY * 512 * 256];
__device__ uint32_t w1Ph[NLAY * 2048 * 256],  w1Pl[NLAY * 2048 * 256];
__device__ uint32_t w2Ph[NLAY * 512 * 1024],  w2Pl[NLAY * 512 * 1024];

// ---------------- bf16x3 helpers ----------------
__device__ __forceinline__ void split2(float x0, float x1, uint32_t& hw, uint32_t& lw) {
    __nv_bfloat162 h, l;
    h.x = __float2bfloat16(x0);
    h.y = __float2bfloat16(x1);
    l.x = __float2bfloat16(x0 - __bfloat162float(h.x));
    l.y = __float2bfloat16(x1 - __bfloat162float(h.y));
    hw = *reinterpret_cast<uint32_t*>(&h);
    lw = *reinterpret_cast<uint32_t*>(&l);
}

__device__ __forceinline__ void mma16(float (&c)[4], const uint32_t (&a)[4],
                                      uint32_t b0, uint32_t b1) {
    asm volatile(
        "mma.sync.aligned.m16n8k16.row.col.f32.bf16.bf16.f32 "
        "{%0,%1,%2,%3}, {%4,%5,%6,%7}, {%8,%9}, {%0,%1,%2,%3};"
        : "+f"(c[0]), "+f"(c[1]), "+f"(c[2]), "+f"(c[3])
        : "r"(a[0]), "r"(a[1]), "r"(a[2]), "r"(a[3]), "r"(b0), "r"(b1));
}

__device__ __forceinline__ uint32_t sm_u32(const void* p) {
    return (uint32_t)__cvta_generic_to_shared(p);
}

__device__ __forceinline__ void ldsm4(uint32_t (&r)[4], uint32_t a) {
    asm volatile("ldmatrix.sync.aligned.m8n8.x4.shared.b16 {%0,%1,%2,%3}, [%4];"
                 : "=r"(r[0]), "=r"(r[1]), "=r"(r[2]), "=r"(r[3]) : "r"(a));
}

__device__ __forceinline__ void cpa16(uint32_t dst, const void* src, int szok) {
    asm volatile("cp.async.cg.shared.global [%0], [%1], 16, %2;"
                 :: "r"(dst), "l"(src), "r"(szok));
}

__device__ __forceinline__ int boff(int n) { return n * 36 + ((n >> 3) << 2); }
#define BPLANE (64 * 36 + 32)

// ---------------- prep kernels ----------------
__global__ void build_w_kernel(const float* __restrict__ word_emb,
                               const float* __restrict__ mem) {
    int idx = blockIdx.x * blockDim.x + threadIdx.x;
    if (idx >= TT * 256) return;
    int row = idx >> 8, c2 = idx & 255;
    int c = 2 * c2;
    float v0, v1;
    if (row < NMTOK) {
        v0 = mem[row * DM + c]; v1 = mem[row * DM + c + 1];
    } else if (row < NMTOK + QL) {
        v0 = word_emb[(row - NMTOK) * DM + c]; v1 = word_emb[(row - NMTOK) * DM + c + 1];
    } else {
        v0 = mem[(row - NMTOK - QL) * DM + c]; v1 = mem[(row - NMTOK - QL) * DM + c + 1];
    }
    g_w[row * DM + c] = v0;
    g_w[row * DM + c + 1] = v1;
    uint32_t hw, lw;
    split2(v0, v1, hw, lw);
    wPh[idx] = hw; wPl[idx] = lw;
}

__global__ void build_pos_kernel() {
    int idx = blockIdx.x * blockDim.x + threadIdx.x;
    if (idx >= TT * 256) return;
    int row = idx >> 8, c2 = idx & 255;
    float v0, v1;
    #pragma unroll
    for (int u = 0; u < 2; u++) {
        int c = 2 * c2 + u;
        int f = (c < DM / 2) ? c : (c - DM / 2);
        double invf = exp(-((double)(2 * f) / (double)DM) * log(10000.0));
        double val = (double)(TT - 1 - row) * invf;
        float r = (float)((c < DM / 2) ? sin(val) : cos(val));
        if (u == 0) v0 = r; else v1 = r;
    }
    uint32_t hw, lw;
    split2(v0, v1, hw, lw);
    posPh[idx] = hw; posPl[idx] = lw;
}

// ---------------- weight convert ----------------
__global__ void convert_weight(const float* __restrict__ W,
                               uint32_t* __restrict__ Ph, uint32_t* __restrict__ Pl,
                               int K, int N) {
    __shared__ float S[64][33];
    const int l = blockIdx.z;
    const float* Wl = W + (size_t)l * K * N;
    const int Kw = K >> 1;
    uint32_t* PhL = Ph + (size_t)l * N * Kw;
    uint32_t* PlL = Pl + (size_t)l * N * Kw;
    const int n0 = blockIdx.x * 32, k0 = blockIdx.y * 64;
    const int t = threadIdx.x;
    {
        int n = t & 31, kk = t >> 5;
        #pragma unroll
        for (int i = 0; i < 8; i++)
            S[kk + 8 * i][n] = Wl[(size_t)(k0 + kk + 8 * i) * N + n0 + n];
    }
    __syncthreads();
    {
        int nn = t >> 3, kq = t & 7;
        uint32_t oh[4], ol[4];
        #pragma unroll
        for (int i = 0; i < 4; i++) {
            int kp = kq * 4 + i;
            split2(S[2 * kp][nn], S[2 * kp + 1][nn], oh[i], ol[i]);
        }
        size_t base = (size_t)(n0 + nn) * Kw + (k0 >> 1) + kq * 4;
        *reinterpret_cast<uint4*>(PhL + base) = *reinterpret_cast<uint4*>(oh);
        *reinterpret_cast<uint4*>(PlL + base) = *reinterpret_cast<uint4*>(ol);
    }
}

// ---------------- V transpose-convert ----------------
__global__ void convert_vt(const float* __restrict__ heads,
                           uint32_t* __restrict__ Vh, uint32_t* __restrict__ Vl) {
    __shared__ float S[64][65];
    const int jt = blockIdx.x, h = blockIdx.y;
    const int j0 = jt * 64, tid = threadIdx.x;
    for (int t = tid; t < 64 * 16; t += 256) {
        int r = t >> 4, c4 = (t & 15) * 4;
        int gj = j0 + r;
        float4 v = make_float4(0.f, 0.f, 0.f, 0.f);
        if (gj < TT)
            v = *(const float4*)(heads + (size_t)gj * 1536 + 1024 + h * 64 + c4);
        S[r][c4] = v.x; S[r][c4 + 1] = v.y; S[r][c4 + 2] = v.z; S[r][c4 + 3] = v.w;
    }
    __syncthreads();
    const int f = tid >> 2, wq = (tid & 3) * 8;
    size_t base = ((size_t)h * 64 + f) * VTKP + (j0 >> 1) + wq;
    #pragma unroll
    for (int i = 0; i < 8; i++) {
        int kp = wq + i;
        uint32_t hw, lw;
        split2(S[2 * kp][f], S[2 * kp + 1][f], hw, lw);
        Vh[base + i] = hw; Vl[base + i] = lw;
    }
}

// ---------------- GEMM: cp.async 3-stage pipeline ----------------
#define PPA 20
#define PPB 20
#define ASTG (128 * PPA)
#define BSTG (64 * PPB)
#define STG_W (2 * ASTG + 2 * BSTG)
#define NSTG 3
#define GEMM_SMEM (NSTG * STG_W * 4)

// outMode: 0=fp32, 1=planes, 2=both, 3=QKV special.
// zMode: 0 = k-split over z (2), 1 = layer batch over z (strides zStrB/zStrC/zStrP)
__global__ __launch_bounds__(256, 2)
void mma_gemm(const uint32_t* __restrict__ Ahg, const uint32_t* __restrict__ Alg, int ldaw,
              const uint32_t* __restrict__ Bhg, const uint32_t* __restrict__ Blg, int ldbw,
              float* __restrict__ C, float* __restrict__ C2, int ldc,
              uint32_t* __restrict__ OutH, uint32_t* __restrict__ OutL, int ldcw,
              const float* __restrict__ cbias, int doRelu, int outMode,
              int M, int N, int Ksub,
              int zMode, size_t zStrB, size_t zStrC, size_t zStrP) {
    extern __shared__ uint32_t gsm[];
    const uint32_t smBase = sm_u32(gsm);

    const int bm = blockIdx.y * 128, bn = blockIdx.x * 64;
    const int bz = blockIdx.z;
    int kOffW;
    if (zMode == 0) {
        kOffW = bz * (Ksub >> 1);
        if (bz == 1) C = C2;
    } else {
        kOffW = 0;
        Bhg += (size_t)bz * zStrB; Blg += (size_t)bz * zStrB;
        if (C)    C    += (size_t)bz * zStrC;
        if (OutH) { OutH += (size_t)bz * zStrP; OutL += (size_t)bz * zStrP; }
    }

    const int tid = threadIdx.x;
    const int lane = tid & 31, warp = tid >> 5;
    const int wm = warp & 3, wn = warp >> 2;
    const int g4 = lane >> 2, l4 = lane & 3;

    float acc[2][4][4] = {};

    const int arow = tid >> 2;
    const int akq = tid & 3;

    const int aRow = lane & 15;
    const uint32_t aHiB = ((lane >> 4) & 1) * 16;
    const uint32_t adA = smBase + (uint32_t)((wm * 32 + aRow) * PPA) * 4 + aHiB;
    const int bRowN = ((lane >> 4) & 1) * 8 + (lane & 7);
    const uint32_t bHiB = ((lane >> 3) & 1) * 16;
    const uint32_t adB0 = smBase + (uint32_t)(2 * ASTG + (wn * 32 + bRowN) * PPB) * 4 + bHiB;
    const uint32_t adB1 = adB0 + 16 * PPB * 4;

    const uint32_t dA = (uint32_t)(arow * PPA + akq * 4) * 4;
    const uint32_t dB = (uint32_t)(2 * ASTG + arow * PPB + akq * 4) * 4;

    auto issueStage = [&](int iter, int st) {
        const int kw = kOffW + iter * 16 + akq * 4;
        const uint32_t base = smBase + (uint32_t)st * (STG_W * 4);
        #pragma unroll
        for (int p = 0; p < 2; p++) {
            int row = bm + p * 64 + arow;
            int ok = (row < M) ? 16 : 0;
            int rowc = (row < M) ? row : 0;
            cpa16(base + dA + p * 64 * PPA * 4, Ahg + (size_t)rowc * ldaw + kw, ok);
            cpa16(base + dA + p * 64 * PPA * 4 + ASTG * 4, Alg + (size_t)rowc * ldaw + kw, ok);
        }
        {
            int row = bn + arow;
            cpa16(base + dB, Bhg + (size_t)row * ldbw + kw, 16);
            cpa16(base + dB + BSTG * 4, Blg + (size_t)row * ldbw + kw, 16);
        }
    };

    const int niter = Ksub >> 5;
    issueStage(0, 0);
    asm volatile("cp.async.commit_group;" ::: "memory");
    issueStage(1, 1);
    asm volatile("cp.async.commit_group;" ::: "memory");

    int st = 0;
    for (int i = 0; i < niter; i++) {
        asm volatile("cp.async.wait_group 1;" ::: "memory");
        __syncthreads();
        const uint32_t so = (uint32_t)st * (STG_W * 4);
        #pragma unroll
        for (int ks = 0; ks < 2; ks++) {
            uint32_t ahh[2][4], alo[2][4];
            ldsm4(ahh[0], adA + so + ks * 32);
            ldsm4(ahh[1], adA + so + 16 * PPA * 4 + ks * 32);
            ldsm4(alo[0], adA + so + ASTG * 4 + ks * 32);
            ldsm4(alo[1], adA + so + ASTG * 4 + 16 * PPA * 4 + ks * 32);
            uint32_t bhh[2][4], blo[2][4];
            ldsm4(bhh[0], adB0 + so + ks * 32);
            ldsm4(bhh[1], adB1 + so + ks * 32);
            ldsm4(blo[0], adB0 + so + BSTG * 4 + ks * 32);
            ldsm4(blo[1], adB1 + so + BSTG * 4 + ks * 32);
            #pragma unroll
            for (int am = 0; am < 2; am++)
                #pragma unroll
                for (int an = 0; an < 4; an++) {
                    const int g = an >> 1, x = (an & 1) * 2;
                    mma16(acc[am][an], ahh[am], bhh[g][x], bhh[g][x + 1]);
                    mma16(acc[am][an], ahh[am], blo[g][x], blo[g][x + 1]);
                    mma16(acc[am][an], alo[am], bhh[g][x], bhh[g][x + 1]);
                }
        }
        if (i + 2 < niter) {
            int st2 = st + 2; if (st2 >= NSTG) st2 -= NSTG;
            issueStage(i + 2, st2);
        }
        asm volatile("cp.async.commit_group;" ::: "memory");
        st = (st + 1 == NSTG) ? 0 : st + 1;
    }

    bool wantPlane, wantF32;
    if (outMode == 0)      { wantPlane = false; wantF32 = true; }
    else if (outMode == 1) { wantPlane = true;  wantF32 = false; }
    else if (outMode == 2) { wantPlane = true;  wantF32 = true; }
    else {
        bool isk = (bn >= 512 && bn < 1024);
        wantPlane = isk; wantF32 = !isk;
    }
    const int pShift = (outMode == 3) ? 512 : 0;

    #pragma unroll
    for (int am = 0; am < 2; am++) {
        int row0 = bm + wm * 32 + am * 16 + g4;
        #pragma unroll
        for (int an = 0; an < 4; an++) {
            int col0 = bn + wn * 32 + an * 8 + 2 * l4;
            float v0 = acc[am][an][0], v1 = acc[am][an][1];
            float v2 = acc[am][an][2], v3 = acc[am][an][3];
            if (cbias && blockIdx.z == 0) {
                float b0 = cbias[col0], b1 = cbias[col0 + 1];
                v0 += b0; v1 += b1; v2 += b0; v3 += b1;
            }
            if (doRelu) {
                v0 = fmaxf(v0, 0.f); v1 = fmaxf(v1, 0.f);
                v2 = fmaxf(v2, 0.f); v3 = fmaxf(v3, 0.f);
            }
            if (wantPlane) {
                uint32_t hw, lw;
                int colP = (col0 - pShift) >> 1;
                if (row0 < M) {
                    split2(v0, v1, hw, lw);
                    OutH[(size_t)row0 * ldcw + colP] = hw;
                    OutL[(size_t)row0 * ldcw + colP] = lw;
                }
                if (row0 + 8 < M) {
                    split2(v2, v3, hw, lw);
                    OutH[(size_t)(row0 + 8) * ldcw + colP] = hw;
                    OutL[(size_t)(row0 + 8) * ldcw + colP] = lw;
                }
            }
            if (wantF32) {
                if (row0 < M) {
                    C[(size_t)row0 * ldc + col0]     = v0;
                    C[(size_t)row0 * ldc + col0 + 1] = v1;
                }
                if (row0 + 8 < M) {
                    C[(size_t)(row0 + 8) * ldc + col0]     = v2;
                    C[(size_t)(row0 + 8) * ldc + col0 + 1] = v3;
                }
            }
        }
    }
}

// ---------------- fused flash-style relative attention ----------------
#define RPAD 68
#define RSLOT (64 * RPAD)
#define ATTN_WORDS (16 * BPLANE + 3 * RSLOT + 512)
#define ATTN_SMEM (ATTN_WORDS * 4)

__global__ __launch_bounds__(512, 1)
void fused_attn_kernel(const float* __restrict__ heads,
                       const float* __restrict__ rbuf,
                       const uint32_t* __restrict__ kGh, const uint32_t* __restrict__ kGl,
                       const uint32_t* __restrict__ vGh, const uint32_t* __restrict__ vGl,
                       const uint32_t* __restrict__ rGh, const uint32_t* __restrict__ rGl,
                       const float* __restrict__ rwb,
                       const float* __restrict__ rrb) {
    extern __shared__ uint32_t smu[];
    uint32_t* Qwh = smu;
    uint32_t* Qwl = Qwh + BPLANE;
    uint32_t* Qrh = Qwl + BPLANE;
    uint32_t* Qrl = Qrh + BPLANE;
    uint32_t* Kh  = Qrl + BPLANE;
    uint32_t* Kl  = Kh  + 2 * BPLANE;
    uint32_t* Rh  = Kl  + 2 * BPLANE;
    uint32_t* Rl  = Rh  + BPLANE;
    uint32_t* Vth = Rl  + BPLANE;
    uint32_t* Vtl = Vth + 2 * BPLANE;
    uint32_t* Ph  = Vtl + 2 * BPLANE;
    uint32_t* Pl  = Ph  + BPLANE;
    float* Ring = (float*)(Pl + BPLANE);
    float* redm = Ring + 3 * RSLOT;
    float* reds = redm + 256;

    const int h = blockIdx.x;
    const int p = blockIdx.y;
    const int tid = threadIdx.x;
    const int lane = tid & 31, warp = tid >> 5;
    const int wm = warp & 3, wn = warp >> 2;
    const int g4 = lane >> 2, l4 = lane & 3;
    const int wr0 = wm * 16 + g4;
    const int colbase = wn * 16;

    const int aRow = lane & 15;
    const uint32_t aHiB = ((lane >> 4) & 1) * 16;
    const uint32_t aOff = (uint32_t)boff(wm * 16 + aRow) * 4 + aHiB;
    const uint32_t adQwh = sm_u32(Qwh) + aOff, adQwl = sm_u32(Qwl) + aOff;
    const uint32_t adQrh = sm_u32(Qrh) + aOff, adQrl = sm_u32(Qrl) + aOff;
    const uint32_t adPh  = sm_u32(Ph)  + aOff, adPl  = sm_u32(Pl)  + aOff;
    const int bRowN = ((lane >> 4) & 1) * 8 + (lane & 7);
    const uint32_t bHiB = ((lane >> 3) & 1) * 16;
    const uint32_t bO0 = (uint32_t)boff(colbase + bRowN) * 4 + bHiB;
    const uint32_t adKh = sm_u32(Kh) + bO0;
    const uint32_t adKl = sm_u32(Kl) + bO0;
    const uint32_t adRh = sm_u32(Rh) + bO0;
    const uint32_t adRl = sm_u32(Rl) + bO0;
    const uint32_t adVh = sm_u32(Vth) + bO0;
    const uint32_t adVl = sm_u32(Vtl) + bO0;

    uint4 pkh, pkl, pvh, pvl;
    const int prow = tid >> 3, pwq = (tid & 7) * 4;
    const size_t vtBase = ((size_t)h * 64 + prow) * VTKP;
    auto prefetchKV = [&](int j0) {
        int gj = j0 + prow;
        if (gj < TT) {
            pkh = *(const uint4*)(kGh + (size_t)gj * 256 + h * 32 + pwq);
            pkl = *(const uint4*)(kGl + (size_t)gj * 256 + h * 32 + pwq);
        } else {
            pkh = make_uint4(0, 0, 0, 0);
            pkl = make_uint4(0, 0, 0, 0);
        }
        pvh = *(const uint4*)(vGh + vtBase + (j0 >> 1) + pwq);
        pvl = *(const uint4*)(vGl + vtBase + (j0 >> 1) + pwq);
    };
    auto storeKV = [&](int buf) {
        int wi = buf * BPLANE + boff(prow) + pwq;
        *(uint4*)(Kh + wi) = pkh;
        *(uint4*)(Kl + wi) = pkl;
        *(uint4*)(Vth + wi) = pvh;
        *(uint4*)(Vtl + wi) = pvl;
    };
    auto loadRchunk = [&](int c) {
        int grow = c * 64 + prow;
        uint4 r0 = make_uint4(0, 0, 0, 0), r1 = r0;
        if (grow < TT) {
            r0 = *(const uint4*)(rGh + (size_t)grow * 256 + h * 32 + pwq);
            r1 = *(const uint4*)(rGl + (size_t)grow * 256 + h * 32 + pwq);
        }
        int wi = boff(prow) + pwq;
        *(uint4*)(Rh + wi) = r0;
        *(uint4*)(Rl + wi) = r1;
    };
    auto bdChunk = [&](int c) {
        float cacc[2][4];
        #pragma unroll
        for (int a = 0; a < 2; a++)
            cacc[a][0] = cacc[a][1] = cacc[a][2] = cacc[a][3] = 0.f;
        #pragma unroll
        for (int kc = 0; kc < 4; kc++) {
            uint32_t ah[4], al[4];
            ldsm4(ah, adQrh + kc * 32);
            ldsm4(al, adQrl + kc * 32);
            uint32_t bh[4], bl[4];
            ldsm4(bh, adRh + kc * 32);
            ldsm4(bl, adRl + kc * 32);
            #pragma unroll
            for (int an = 0; an < 2; an++) {
                const int x = an * 2;
                mma16(cacc[an], ah, bh[x], bh[x + 1]);
                mma16(cacc[an], ah, bl[x], bl[x + 1]);
                mma16(cacc[an], al, bh[x], bh[x + 1]);
            }
        }
        float* slot = Ring + (c % 3) * RSLOT;
        #pragma unroll
        for (int an = 0; an < 2; an++) {
            int col = colbase + an * 8 + 2 * l4;
            slot[wr0 * RPAD + col]           = cacc[an][0];
            slot[wr0 * RPAD + col + 1]       = cacc[an][1];
            slot[(wr0 + 8) * RPAD + col]     = cacc[an][2];
            slot[(wr0 + 8) * RPAD + col + 1] = cacc[an][3];
        }
    };

    int blist[2]; int nblk;
    if (p < 16) { blist[0] = p; blist[1] = 31 - p; nblk = 2; }
    else        { blist[0] = 32; nblk = 1; }

    for (int bi = 0; bi < nblk; bi++) {
        const int b = blist[bi];
        const int i0 = b * 64;
        const int validRows = min(64, TT - i0);
        const int njt = (b < 32) ? (b + 1) : 33;

        __syncthreads();
        for (int t = tid; t < 64 * 16; t += 512) {
            int r = t >> 4, c4 = (t & 15) * 4;
            int grow = i0 + r;
            float4 q = make_float4(0.f, 0.f, 0.f, 0.f);
            if (grow < TT)
                q = *(const float4*)(heads + (size_t)grow * (3 * DM) + h * DH + c4);
            float4 bw = *(const float4*)(rwb + h * DH + c4);
            float4 br = *(const float4*)(rrb + h * DH + c4);
            int wi = boff(r) + (c4 >> 1);
            uint32_t hw, lw;
            split2(q.x + bw.x, q.y + bw.y, hw, lw); Qwh[wi] = hw;     Qwl[wi] = lw;
            split2(q.z + bw.z, q.w + bw.w, hw, lw); Qwh[wi + 1] = hw; Qwl[wi + 1] = lw;
            split2(q.x + br.x, q.y + br.y, hw, lw); Qrh[wi] = hw;     Qrl[wi] = lw;
            split2(q.z + br.z, q.w + br.w, hw, lw); Qrh[wi + 1] = hw; Qrl[wi + 1] = lw;
        }
        prefetchKV(0);
        storeKV(0);

        int nextChunk = (2016 - i0) / 64;
        if (nextChunk < 0) nextChunk = 0;

        const int chi0 = min(TT - 1, TT - 1 - i0 + 63) >> 6;
        while (nextChunk <= chi0) {
            __syncthreads();
            loadRchunk(nextChunk);
            __syncthreads();
            bdChunk(nextChunk);
            nextChunk++;
        }
        __syncthreads();

        float o[2][4];
        #pragma unroll
        for (int a = 0; a < 2; a++) { o[a][0] = o[a][1] = o[a][2] = o[a][3] = 0.f; }
        float mrow[2] = {-1e30f, -1e30f};
        float lrow[2] = {0.f, 0.f};

        for (int jt = 0; jt < njt; jt++) {
            const int j0 = jt * 64;
            const uint32_t kb = (uint32_t)(jt & 1) * (BPLANE * 4);

            // ---- AC MMA ----
            float s[2][4];
            #pragma unroll
            for (int a = 0; a < 2; a++)
                s[a][0] = s[a][1] = s[a][2] = s[a][3] = 0.f;
            #pragma unroll
            for (int kc = 0; kc < 4; kc++) {
                uint32_t ah[4], al[4];
                ldsm4(ah, adQwh + kc * 32);
                ldsm4(al, adQwl + kc * 32);
                uint32_t bh[4], bl[4];
                ldsm4(bh, adKh + kb + kc * 32);
                ldsm4(bl, adKl + kb + kc * 32);
                #pragma unroll
                for (int an = 0; an < 2; an++) {
                    const int x = an * 2;
                    mma16(s[an], ah, bh[x], bh[x + 1]);
                    mma16(s[an], ah, bl[x], bl[x + 1]);
                    mma16(s[an], al, bh[x], bh[x + 1]);
                }
            }

            // ---- combine with rel-shifted BD ----
            float tmax[2] = {-1e30f, -1e30f};
            if (jt < b) {
                // fast path: strictly-below-diagonal tile, no masking, bd from ring
                const int jrB = TT - 1 - i0 + j0 + colbase + 2 * l4;
                #pragma unroll
                for (int an = 0; an < 2; an++) {
                    #pragma unroll
                    for (int e = 0; e < 4; e++) {
                        int rh = e >> 1;
                        int di = wr0 + rh * 8;
                        int jr = jrB - di + an * 8 + (e & 1);
                        float bd = Ring[((jr >> 6) % 3) * RSLOT + di * RPAD + (jr & 63)];
                        float v = (s[an][e] + bd) * 0.125f;
                        s[an][e] = v;
                        tmax[rh] = fmaxf(tmax[rh], v);
                    }
                }
            } else {
                #pragma unroll
                for (int an = 0; an < 2; an++) {
                    #pragma unroll
                    for (int e = 0; e < 4; e++) {
                        int rh = e >> 1;
                        int di = wr0 + rh * 8;
                        int dj = colbase + an * 8 + 2 * l4 + (e & 1);
                        int i = i0 + di, j = j0 + dj;
                        float v = -1e30f;
                        if (di < validRows && j < TT) {
                            int jmaxr = (i < NMTOK) ? (NMTOK - 1)
                                      : ((i >= TT - NMTOK) ? (TT - 1) : i);
                            if (j <= jmaxr) {
                                float bd;
                                if (j <= i) {
                                    int jr = TT - 1 - i + j;
                                    bd = Ring[((jr >> 6) % 3) * RSLOT + di * RPAD + (jr & 63)];
                                } else if (j == i + 1) {
                                    bd = 0.f;
                                } else {
                                    const float* rr = rbuf + (size_t)(j - i - 2) * DM + h * DH;
                                    float accd = 0.f;
                                    #pragma unroll 8
                                    for (int d2 = 0; d2 < 32; d2++) {
                                        uint32_t wh = Qrh[boff(di + 1) + d2];
                                        uint32_t wl = Qrl[boff(di + 1) + d2];
                                        __nv_bfloat162 h2 = *reinterpret_cast<__nv_bfloat162*>(&wh);
                                        __nv_bfloat162 l2 = *reinterpret_cast<__nv_bfloat162*>(&wl);
                                        float q0 = __bfloat162float(h2.x) + __bfloat162float(l2.x);
                                        float q1 = __bfloat162float(h2.y) + __bfloat162float(l2.y);
                                        accd += q0 * rr[2 * d2] + q1 * rr[2 * d2 + 1];
                                    }
                                    bd = accd;
                                }
                                v = (s[an][e] + bd) * 0.125f;
                            }
                        }
                        s[an][e] = v;
                        tmax[rh] = fmaxf(tmax[rh], v);
                    }
                }
            }
            #pragma unroll
            for (int rh = 0; rh < 2; rh++) {
                tmax[rh] = fmaxf(tmax[rh], __shfl_xor_sync(0xffffffffu, tmax[rh], 1));
                tmax[rh] = fmaxf(tmax[rh], __shfl_xor_sync(0xffffffffu, tmax[rh], 2));
            }
            if (l4 == 0) {
                redm[wn * 64 + wm * 16 + g4]     = tmax[0];
                redm[wn * 64 + wm * 16 + g4 + 8] = tmax[1];
            }

            bool needChunk = false;
            int cN = nextChunk;
            if (jt + 1 < njt) {
                prefetchKV((jt + 1) * 64);
                int chiN = min(TT - 1, TT - 1 - i0 + (jt + 1) * 64 + 63) >> 6;
                if (nextChunk <= chiN) { needChunk = true; loadRchunk(cN); }
            }
            __syncthreads();   // (c)

            float scl[2], lsum[2] = {0.f, 0.f};
            #pragma unroll
            for (int rh = 0; rh < 2; rh++) {
                int row = wm * 16 + g4 + rh * 8;
                float tm = fmaxf(fmaxf(redm[row], redm[64 + row]),
                                 fmaxf(redm[128 + row], redm[192 + row]));
                float mnew = fmaxf(mrow[rh], tm);
                scl[rh] = __expf(mrow[rh] - mnew);
                mrow[rh] = mnew;
            }
            #pragma unroll
            for (int an = 0; an < 2; an++) {
                #pragma unroll
                for (int e = 0; e < 4; e++) {
                    int rh = e >> 1;
                    float ev = __expf(s[an][e] - mrow[rh]);
                    s[an][e] = ev;
                    lsum[rh] += ev;
                }
            }
            #pragma unroll
            for (int rh = 0; rh < 2; rh++) {
                lsum[rh] += __shfl_xor_sync(0xffffffffu, lsum[rh], 1);
                lsum[rh] += __shfl_xor_sync(0xffffffffu, lsum[rh], 2);
            }
            if (l4 == 0) {
                reds[wn * 64 + wm * 16 + g4]     = lsum[0];
                reds[wn * 64 + wm * 16 + g4 + 8] = lsum[1];
            }
            #pragma unroll
            for (int an = 0; an < 2; an++) {
                int cp = (colbase >> 1) + an * 4 + l4;
                uint32_t hw, lw;
                split2(s[an][0], s[an][1], hw, lw);
                Ph[boff(wr0) + cp] = hw; Pl[boff(wr0) + cp] = lw;
                split2(s[an][2], s[an][3], hw, lw);
                Ph[boff(wr0 + 8) + cp] = hw; Pl[boff(wr0 + 8) + cp] = lw;
            }
            if (jt + 1 < njt) storeKV((jt + 1) & 1);
            if (needChunk) { bdChunk(cN); nextChunk++; }
            __syncthreads();   // (d)

            #pragma unroll
            for (int rh = 0; rh < 2; rh++) {
                int row = wm * 16 + g4 + rh * 8;
                lrow[rh] = lrow[rh] * scl[rh] +
                           reds[row] + reds[64 + row] + reds[128 + row] + reds[192 + row];
            }
            #pragma unroll
            for (int an = 0; an < 2; an++) {
                o[an][0] *= scl[0]; o[an][1] *= scl[0];
                o[an][2] *= scl[1]; o[an][3] *= scl[1];
            }

            // ---- PV MMA ----
            #pragma unroll
            for (int kc = 0; kc < 4; kc++) {
                uint32_t ah[4], al[4];
                ldsm4(ah, adPh + kc * 32);
                ldsm4(al, adPl + kc * 32);
                uint32_t bh[4], bl[4];
                ldsm4(bh, adVh + kb + kc * 32);
                ldsm4(bl, adVl + kb + kc * 32);
                #pragma unroll
                for (int an = 0; an < 2; an++) {
                    const int x = an * 2;
                    mma16(o[an], ah, bh[x], bh[x + 1]);
                    mma16(o[an], ah, bl[x], bl[x + 1]);
                    mma16(o[an], al, bh[x], bh[x + 1]);
                }
            }
        } // j-tiles

        float inv0 = 1.f / lrow[0], inv1 = 1.f / lrow[1];
        #pragma unroll
        for (int an = 0; an < 2; an++) {
            int colw = (h * DH + colbase + an * 8 + 2 * l4) >> 1;
            int r0 = i0 + wr0;
            uint32_t hw, lw;
            if (wr0 < validRows) {
                split2(o[an][0] * inv0, o[an][1] * inv0, hw, lw);
                avPh[(size_t)r0 * 256 + colw] = hw;
                avPl[(size_t)r0 * 256 + colw] = lw;
            }
            if (wr0 + 8 < validRows) {
                split2(o[an][2] * inv1, o[an][3] * inv1, hw, lw);
                avPh[(size_t)(r0 + 8) * 256 + colw] = hw;
                avPl[(size_t)(r0 + 8) * 256 + colw] = lw;
            }
        }
    } // blocks
}

// ---------------- residual add + layernorm (1-barrier, emits w planes) ----------------
__global__ void add_ln_kernel(float* __restrict__ w, const float* __restrict__ delta,
                              const float* __restrict__ delta2,
                              const float* __restrict__ gam, const float* __restrict__ bta) {
    int row = blockIdx.x;
    int tid = threadIdx.x;
    int c = 2 * tid;
    __shared__ float s1m[8], s2m[8];
    float x0 = w[row * DM + c]     + delta[row * DM + c];
    float x1 = w[row * DM + c + 1] + delta[row * DM + c + 1];
    if (delta2) {
        x0 += delta2[row * DM + c];
        x1 += delta2[row * DM + c + 1];
    }
    float s1 = x0 + x1;
    float s2 = x0 * x0 + x1 * x1;
    #pragma unroll
    for (int o = 16; o > 0; o >>= 1) {
        s1 += __shfl_xor_sync(0xffffffffu, s1, o);
        s2 += __shfl_xor_sync(0xffffffffu, s2, o);
    }
    if ((tid & 31) == 0) { s1m[tid >> 5] = s1; s2m[tid >> 5] = s2; }
    __syncthreads();
    float t1 = 0.f, t2 = 0.f;
    #pragma unroll
    for (int i = 0; i < 8; i++) { t1 += s1m[i]; t2 += s2m[i]; }
    float mean = t1 * (1.f / DM);
    float var = t2 * (1.f / DM) - mean * mean;
    float inv = 1.f / sqrtf(var + 1e-5f);
    float y0 = (x0 - mean) * inv * gam[c]     + bta[c];
    float y1 = (x1 - mean) * inv * gam[c + 1] + bta[c + 1];
    w[row * DM + c]     = y0;
    w[row * DM + c + 1] = y1;
    uint32_t hw, lw;
    split2(y0, y1, hw, lw);
    wPh[row * 256 + tid] = hw;
    wPl[row * 256 + tid] = lw;
}

__global__ void copy_out_kernel(float* __restrict__ out) {
    int idx = blockIdx.x * blockDim.x + threadIdx.x;
    if (idx < TT * DM) out[idx] = g_w[idx];
}

// ---------------- launcher ----------------
extern "C" void kernel_launch(void* const* d_in, const int* in_sizes, int n_in,
                              void* d_out, int out_size) {
    (void)in_sizes; (void)n_in; (void)out_size;
    const float* word_emb = (const float*)d_in[0];
    const float* mem_tok  = (const float*)d_in[1];
    const float* Wqkv     = (const float*)d_in[2];
    const float* Wr       = (const float*)d_in[3];
    const float* Wo       = (const float*)d_in[4];
    const float* ln1s     = (const float*)d_in[5];
    const float* ln1b     = (const float*)d_in[6];
    const float* W1       = (const float*)d_in[7];
    const float* b1       = (const float*)d_in[8];
    const float* W2       = (const float*)d_in[9];
    const float* b2       = (const float*)d_in[10];
    const float* ln2s     = (const float*)d_in[11];
    const float* ln2b     = (const float*)d_in[12];
    const float* rwb      = (const float*)d_in[13];
    const float* rrb      = (const float*)d_in[14];

    float *g_w_p, *g_hd_p, *g_r4_p, *g_tmp_p, *g_tmp2_p;
    cudaGetSymbolAddress((void**)&g_w_p,    g_w);
    cudaGetSymbolAddress((void**)&g_hd_p,   g_heads);
    cudaGetSymbolAddress((void**)&g_r4_p,   g_r4);
    cudaGetSymbolAddress((void**)&g_tmp_p,  g_tmp);
    cudaGetSymbolAddress((void**)&g_tmp2_p, g_tmp2);
    uint32_t *wPh_p, *wPl_p, *posPh_p, *posPl_p, *avPh_p, *avPl_p, *ff1Ph_p, *ff1Pl_p;
    uint32_t *kPh_p, *kPl_p, *rPh4_p, *rPl4_p, *vtPh_p, *vtPl_p;
    cudaGetSymbolAddress((void**)&wPh_p,   wPh);
    cudaGetSymbolAddress((void**)&wPl_p,   wPl);
    cudaGetSymbolAddress((void**)&posPh_p, posPh);
    cudaGetSymbolAddress((void**)&posPl_p, posPl);
    cudaGetSymbolAddress((void**)&avPh_p,  avPh);
    cudaGetSymbolAddress((void**)&avPl_p,  avPl);
    cudaGetSymbolAddress((void**)&ff1Ph_p, ff1Ph);
    cudaGetSymbolAddress((void**)&ff1Pl_p, ff1Pl);
    cudaGetSymbolAddress((void**)&kPh_p,   kPh);
    cudaGetSymbolAddress((void**)&kPl_p,   kPl);
    cudaGetSymbolAddress((void**)&rPh4_p,  rPh4);
    cudaGetSymbolAddress((void**)&rPl4_p,  rPl4);
    cudaGetSymbolAddress((void**)&vtPh_p,  vtPh);
    cudaGetSymbolAddress((void**)&vtPl_p,  vtPl);
    uint32_t *qkvPh_p, *qkvPl_p, *wrPh_p, *wrPl_p, *woPh_p, *woPl_p, *w1Ph_p, *w1Pl_p, *w2Ph_p, *w2Pl_p;
    cudaGetSymbolAddress((void**)&qkvPh_p, qkvPh);
    cudaGetSymbolAddress((void**)&qkvPl_p, qkvPl);
    cudaGetSymbolAddress((void**)&wrPh_p,  wrPh);
    cudaGetSymbolAddress((void**)&wrPl_p,  wrPl);
    cudaGetSymbolAddress((void**)&woPh_p,  woPh);
    cudaGetSymbolAddress((void**)&woPl_p,  woPl);
    cudaGetSymbolAddress((void**)&w1Ph_p,  w1Ph);
    cudaGetSymbolAddress((void**)&w1Pl_p,  w1Pl);
    cudaGetSymbolAddress((void**)&w2Ph_p,  w2Ph);
    cudaGetSymbolAddress((void**)&w2Pl_p,  w2Pl);

    cudaFuncSetAttribute(fused_attn_kernel,
                         cudaFuncAttributeMaxDynamicSharedMemorySize, ATTN_SMEM);
    cudaFuncSetAttribute(mma_gemm,
                         cudaFuncAttributeMaxDynamicSharedMemorySize, GEMM_SMEM);

    convert_weight<<<dim3(1536 / 32, 512 / 64, NLAY), 256>>>(Wqkv, qkvPh_p, qkvPl_p, 512, 1536);
    convert_weight<<<dim3(512 / 32, 512 / 64, NLAY), 256>>>(Wr, wrPh_p, wrPl_p, 512, 512);
    convert_weight<<<dim3(512 / 32, 512 / 64, NLAY), 256>>>(Wo, woPh_p, woPl_p, 512, 512);
    convert_weight<<<dim3(2048 / 32, 512 / 64, NLAY), 256>>>(W1, w1Ph_p, w1Pl_p, 512, 2048);
    convert_weight<<<dim3(512 / 32, 2048 / 64, NLAY), 256>>>(W2, w2Ph_p, w2Pl_p, 2048, 512);

    build_w_kernel<<<(TT * 256 + 255) / 256, 256>>>(word_emb, mem_tok);
    build_pos_kernel<<<(TT * 256 + 255) / 256, 256>>>();

    const int MB = (TT + 127) / 128;   // 17

    // All 4 layers' r-projections in one batched launch (layer over z)
    mma_gemm<<<dim3(8, MB, NLAY), 256, GEMM_SMEM>>>(
        posPh_p, posPl_p, 256,
        wrPh_p, wrPl_p, 256,
        g_r4_p, nullptr, DM,
        rPh4_p, rPl4_p, 256,
        nullptr, 0, 2, TT, DM, DM,
        1, (size_t)512 * 256, (size_t)TT * DM, (size_t)TT * 256);

    for (int l = 0; l < NLAY; l++) {
        mma_gemm<<<dim3(24, MB, 1), 256, GEMM_SMEM>>>(
            wPh_p, wPl_p, 256,
            qkvPh_p + (size_t)l * 1536 * 256, qkvPl_p + (size_t)l * 1536 * 256, 256,
            g_hd_p, g_hd_p, 3 * DM,
            kPh_p, kPl_p, 256,
            nullptr, 0, 3, TT, 3 * DM, DM,
            0, 0, 0, 0);
        convert_vt<<<dim3(33, NH), 256>>>(g_hd_p, vtPh_p, vtPl_p);

        fused_attn_kernel<<<dim3(NH, 17), 512, ATTN_SMEM>>>(
            g_hd_p, g_r4_p + (size_t)l * TT * DM,
            kPh_p, kPl_p, vtPh_p, vtPl_p,
            rPh4_p + (size_t)l * TT * 256, rPl4_p + (size_t)l * TT * 256,
            rwb, rrb);

        mma_gemm<<<dim3(8, MB, 2), 256, GEMM_SMEM>>>(
            avPh_p, avPl_p, 256,
            woPh_p + (size_t)l * 512 * 256, woPl_p + (size_t)l * 512 * 256, 256,
            g_tmp_p, g_tmp2_p, DM,
            nullptr, nullptr, 0,
            nullptr, 0, 0, TT, DM, DM / 2,
            0, 0, 0, 0);
        add_ln_kernel<<<TT, 256>>>(g_w_p, g_tmp_p, g_tmp2_p, ln1s + l * DM, ln1b + l * DM);
        mma_gemm<<<dim3(32, MB, 1), 256, GEMM_SMEM>>>(
            wPh_p, wPl_p, 256,
            w1Ph_p + (size_t)l * 2048 * 256, w1Pl_p + (size_t)l * 2048 * 256, 256,
            nullptr, nullptr, 0,
            ff1Ph_p, ff1Pl_p, DI / 2,
            b1 + (size_t)l * DI, 1, 1, TT, DI, DM,
            0, 0, 0, 0);
        mma_gemm<<<dim3(8, MB, 2), 256, GEMM_SMEM>>>(
            ff1Ph_p, ff1Pl_p, 1024,
            w2Ph_p + (size_t)l * 512 * 1024, w2Pl_p + (size_t)l * 512 * 1024, 1024,
            g_tmp_p, g_tmp2_p, DM,
            nullptr, nullptr, 0,
            b2 + (size_t)l * DM, 0, 0, TT, DM, DI / 2,
            0, 0, 0, 0);
        add_ln_kernel<<<TT, 256>>>(g_w_p, g_tmp_p, g_tmp2_p, ln2s + l * DM, ln2b + l * DM);
    }

    copy_out_kernel<<<(TT * DM + 255) / 256, 256>>>((float*)d_out);
}

// round 16
// speedup vs baseline: 1.2345x; 1.0031x over previous
#include <cuda_runtime.h>
#include <cuda_bf16.h>
#include <math.h>
#include <stdint.h>

// ---------------- problem constants ----------------
#define TT    2080
#define DM    512
#define NH    8
#define DH    64
#define DI    2048
#define NLAY  4
#define NMTOK 16
#define QL    2048
#define VTKP  1056

// ---------------- fp32 scratch ----------------
__device__ float g_w[TT * DM];
__device__ float g_heads[TT * 3 * DM];   // only v region (cols 1024..1535) live now
__device__ float g_r4[NLAY * TT * DM];
__device__ float g_tmp[TT * DM];
__device__ float g_tmp2[TT * DM];

// ---------------- bf16 hi/lo pair-plane scratch ----------------
__device__ uint32_t wPh[TT * 256],   wPl[TT * 256];
__device__ uint32_t posPh[TT * 256], posPl[TT * 256];
__device__ uint32_t avPh[TT * 256],  avPl[TT * 256];
__device__ uint32_t ff1Ph[TT * 1024], ff1Pl[TT * 1024];
__device__ uint32_t kPh[TT * 256],   kPl[TT * 256];
__device__ uint32_t qwPh[TT * 256],  qwPl[TT * 256];   // q + r_w_bias planes
__device__ uint32_t qrPh[TT * 256],  qrPl[TT * 256];   // q + r_r_bias planes
__device__ uint32_t rPh4[NLAY * TT * 256], rPl4[NLAY * TT * 256];
__device__ uint32_t vtPh[NH * 64 * VTKP], vtPl[NH * 64 * VTKP];
__device__ uint32_t qkvPh[NLAY * 1536 * 256], qkvPl[NLAY * 1536 * 256];
__device__ uint32_t wrPh[NLAY * 512 * 256],   wrPl[NLAY * 512 * 256];
__device__ uint32_t woPh[NLAY * 512 * 256],   woPl[NLAY * 512 * 256];
__device__ uint32_t w1Ph[NLAY * 2048 * 256],  w1Pl[NLAY * 2048 * 256];
__device__ uint32_t w2Ph[NLAY * 512 * 1024],  w2Pl[NLAY * 512 * 1024];

// ---------------- bf16x3 helpers ----------------
__device__ __forceinline__ void split2(float x0, float x1, uint32_t& hw, uint32_t& lw) {
    __nv_bfloat162 h, l;
    h.x = __float2bfloat16(x0);
    h.y = __float2bfloat16(x1);
    l.x = __float2bfloat16(x0 - __bfloat162float(h.x));
    l.y = __float2bfloat16(x1 - __bfloat162float(h.y));
    hw = *reinterpret_cast<uint32_t*>(&h);
    lw = *reinterpret_cast<uint32_t*>(&l);
}

__device__ __forceinline__ void mma16(float (&c)[4], const uint32_t (&a)[4],
                                      uint32_t b0, uint32_t b1) {
    asm volatile(
        "mma.sync.aligned.m16n8k16.row.col.f32.bf16.bf16.f32 "
        "{%0,%1,%2,%3}, {%4,%5,%6,%7}, {%8,%9}, {%0,%1,%2,%3};"
        : "+f"(c[0]), "+f"(c[1]), "+f"(c[2]), "+f"(c[3])
        : "r"(a[0]), "r"(a[1]), "r"(a[2]), "r"(a[3]), "r"(b0), "r"(b1));
}

__device__ __forceinline__ uint32_t sm_u32(const void* p) {
    return (uint32_t)__cvta_generic_to_shared(p);
}

__device__ __forceinline__ void ldsm4(uint32_t (&r)[4], uint32_t a) {
    asm volatile("ldmatrix.sync.aligned.m8n8.x4.shared.b16 {%0,%1,%2,%3}, [%4];"
                 : "=r"(r[0]), "=r"(r[1]), "=r"(r[2]), "=r"(r[3]) : "r"(a));
}

__device__ __forceinline__ void cpa16(uint32_t dst, const void* src, int szok) {
    asm volatile("cp.async.cg.shared.global [%0], [%1], 16, %2;"
                 :: "r"(dst), "l"(src), "r"(szok));
}

__device__ __forceinline__ int boff(int n) { return n * 36 + ((n >> 3) << 2); }
#define BPLANE (64 * 36 + 32)

// ---------------- prep kernels ----------------
__global__ void build_w_kernel(const float* __restrict__ word_emb,
                               const float* __restrict__ mem) {
    int idx = blockIdx.x * blockDim.x + threadIdx.x;
    if (idx >= TT * 256) return;
    int row = idx >> 8, c2 = idx & 255;
    int c = 2 * c2;
    float v0, v1;
    if (row < NMTOK) {
        v0 = mem[row * DM + c]; v1 = mem[row * DM + c + 1];
    } else if (row < NMTOK + QL) {
        v0 = word_emb[(row - NMTOK) * DM + c]; v1 = word_emb[(row - NMTOK) * DM + c + 1];
    } else {
        v0 = mem[(row - NMTOK - QL) * DM + c]; v1 = mem[(row - NMTOK - QL) * DM + c + 1];
    }
    g_w[row * DM + c] = v0;
    g_w[row * DM + c + 1] = v1;
    uint32_t hw, lw;
    split2(v0, v1, hw, lw);
    wPh[idx] = hw; wPl[idx] = lw;
}

__global__ void build_pos_kernel() {
    int idx = blockIdx.x * blockDim.x + threadIdx.x;
    if (idx >= TT * 256) return;
    int row = idx >> 8, c2 = idx & 255;
    float v0, v1;
    #pragma unroll
    for (int u = 0; u < 2; u++) {
        int c = 2 * c2 + u;
        int f = (c < DM / 2) ? c : (c - DM / 2);
        double invf = exp(-((double)(2 * f) / (double)DM) * log(10000.0));
        double val = (double)(TT - 1 - row) * invf;
        float r = (float)((c < DM / 2) ? sin(val) : cos(val));
        if (u == 0) v0 = r; else v1 = r;
    }
    uint32_t hw, lw;
    split2(v0, v1, hw, lw);
    posPh[idx] = hw; posPl[idx] = lw;
}

// ---------------- fused weight convert (all 5 weights, one launch) ----------------
__device__ void convert_tile(const float* __restrict__ Wl,
                             uint32_t* __restrict__ PhL, uint32_t* __restrict__ PlL,
                             int N, int Kw, int n0, int k0) {
    __shared__ float S[64][33];
    const int t = threadIdx.x;
    {
        int n = t & 31, kk = t >> 5;
        #pragma unroll
        for (int i = 0; i < 8; i++)
            S[kk + 8 * i][n] = Wl[(size_t)(k0 + kk + 8 * i) * N + n0 + n];
    }
    __syncthreads();
    {
        int nn = t >> 3, kq = t & 7;
        uint32_t oh[4], ol[4];
        #pragma unroll
        for (int i = 0; i < 4; i++) {
            int kp = kq * 4 + i;
            split2(S[2 * kp][nn], S[2 * kp + 1][nn], oh[i], ol[i]);
        }
        size_t base = (size_t)(n0 + nn) * Kw + (k0 >> 1) + kq * 4;
        *reinterpret_cast<uint4*>(PhL + base) = *reinterpret_cast<uint4*>(oh);
        *reinterpret_cast<uint4*>(PlL + base) = *reinterpret_cast<uint4*>(ol);
    }
}

__global__ void convert_all(const float* Wqkv, uint32_t* qPh, uint32_t* qPl,
                            const float* Wr, uint32_t* rPh, uint32_t* rPl,
                            const float* Wo, uint32_t* oPh, uint32_t* oPl,
                            const float* W1, uint32_t* aPh, uint32_t* aPl,
                            const float* W2, uint32_t* bPh, uint32_t* bPl) {
    int b = blockIdx.x;
    const float* W; uint32_t *Ph, *Pl; int K, N;
    if (b < 1536)            { W = Wqkv; Ph = qPh; Pl = qPl; K = 512;  N = 1536; }
    else if (b < 2048)       { W = Wr;   Ph = rPh; Pl = rPl; K = 512;  N = 512;  b -= 1536; }
    else if (b < 2560)       { W = Wo;   Ph = oPh; Pl = oPl; K = 512;  N = 512;  b -= 2048; }
    else if (b < 4608)       { W = W1;   Ph = aPh; Pl = aPl; K = 512;  N = 2048; b -= 2560; }
    else                     { W = W2;   Ph = bPh; Pl = bPl; K = 2048; N = 512;  b -= 4608; }
    const int nbl = N / 32, kbl = K / 64;
    const int perL = nbl * kbl;
    const int l = b / perL;
    const int rem = b % perL;
    const int kb = rem / nbl, nb = rem % nbl;
    const int Kw = K >> 1;
    convert_tile(W + (size_t)l * K * N,
                 Ph + (size_t)l * N * Kw, Pl + (size_t)l * N * Kw,
                 N, Kw, nb * 32, kb * 64);
}

// ---------------- V transpose-convert ----------------
__global__ void convert_vt(const float* __restrict__ heads,
                           uint32_t* __restrict__ Vh, uint32_t* __restrict__ Vl) {
    __shared__ float S[64][65];
    const int jt = blockIdx.x, h = blockIdx.y;
    const int j0 = jt * 64, tid = threadIdx.x;
    for (int t = tid; t < 64 * 16; t += 256) {
        int r = t >> 4, c4 = (t & 15) * 4;
        int gj = j0 + r;
        float4 v = make_float4(0.f, 0.f, 0.f, 0.f);
        if (gj < TT)
            v = *(const float4*)(heads + (size_t)gj * 1536 + 1024 + h * 64 + c4);
        S[r][c4] = v.x; S[r][c4 + 1] = v.y; S[r][c4 + 2] = v.z; S[r][c4 + 3] = v.w;
    }
    __syncthreads();
    const int f = tid >> 2, wq = (tid & 3) * 8;
    size_t base = ((size_t)h * 64 + f) * VTKP + (j0 >> 1) + wq;
    #pragma unroll
    for (int i = 0; i < 8; i++) {
        int kp = wq + i;
        uint32_t hw, lw;
        split2(S[2 * kp][f], S[2 * kp + 1][f], hw, lw);
        Vh[base + i] = hw; Vl[base + i] = lw;
    }
}

// ---------------- GEMM: cp.async 3-stage pipeline ----------------
#define PPA 20
#define PPB 20
#define ASTG (128 * PPA)
#define BSTG (64 * PPB)
#define STG_W (2 * ASTG + 2 * BSTG)
#define NSTG 3
#define GEMM_SMEM (NSTG * STG_W * 4)

// outMode: 0=fp32, 1=planes, 2=both, 4=QKV (q->biased qw/qr planes, k->planes, v->fp32)
// zMode: 0 = k-split over z (2), 1 = layer batch over z
__global__ __launch_bounds__(256, 2)
void mma_gemm(const uint32_t* __restrict__ Ahg, const uint32_t* __restrict__ Alg, int ldaw,
              const uint32_t* __restrict__ Bhg, const uint32_t* __restrict__ Blg, int ldbw,
              float* __restrict__ C, float* __restrict__ C2, int ldc,
              uint32_t* __restrict__ OutH, uint32_t* __restrict__ OutL, int ldcw,
              const float* __restrict__ cbias, int doRelu, int outMode,
              int M, int N, int Ksub,
              int zMode, size_t zStrB, size_t zStrC, size_t zStrP,
              const float* __restrict__ qwb, const float* __restrict__ qrb,
              uint32_t* __restrict__ QwH, uint32_t* __restrict__ QwL,
              uint32_t* __restrict__ QrH, uint32_t* __restrict__ QrL) {
    extern __shared__ uint32_t gsm[];
    const uint32_t smBase = sm_u32(gsm);

    const int bm = blockIdx.y * 128, bn = blockIdx.x * 64;
    const int bz = blockIdx.z;
    int kOffW;
    if (zMode == 0) {
        kOffW = bz * (Ksub >> 1);
        if (bz == 1) C = C2;
    } else {
        kOffW = 0;
        Bhg += (size_t)bz * zStrB; Blg += (size_t)bz * zStrB;
        if (C)    C    += (size_t)bz * zStrC;
        if (OutH) { OutH += (size_t)bz * zStrP; OutL += (size_t)bz * zStrP; }
    }

    const int tid = threadIdx.x;
    const int lane = tid & 31, warp = tid >> 5;
    const int wm = warp & 3, wn = warp >> 2;
    const int g4 = lane >> 2, l4 = lane & 3;

    float acc[2][4][4] = {};

    const int arow = tid >> 2;
    const int akq = tid & 3;

    const int aRow = lane & 15;
    const uint32_t aHiB = ((lane >> 4) & 1) * 16;
    const uint32_t adA = smBase + (uint32_t)((wm * 32 + aRow) * PPA) * 4 + aHiB;
    const int bRowN = ((lane >> 4) & 1) * 8 + (lane & 7);
    const uint32_t bHiB = ((lane >> 3) & 1) * 16;
    const uint32_t adB0 = smBase + (uint32_t)(2 * ASTG + (wn * 32 + bRowN) * PPB) * 4 + bHiB;
    const uint32_t adB1 = adB0 + 16 * PPB * 4;

    const uint32_t dA = (uint32_t)(arow * PPA + akq * 4) * 4;
    const uint32_t dB = (uint32_t)(2 * ASTG + arow * PPB + akq * 4) * 4;

    auto issueStage = [&](int iter, int st) {
        const int kw = kOffW + iter * 16 + akq * 4;
        const uint32_t base = smBase + (uint32_t)st * (STG_W * 4);
        #pragma unroll
        for (int p = 0; p < 2; p++) {
            int row = bm + p * 64 + arow;
            int ok = (row < M) ? 16 : 0;
            int rowc = (row < M) ? row : 0;
            cpa16(base + dA + p * 64 * PPA * 4, Ahg + (size_t)rowc * ldaw + kw, ok);
            cpa16(base + dA + p * 64 * PPA * 4 + ASTG * 4, Alg + (size_t)rowc * ldaw + kw, ok);
        }
        {
            int row = bn + arow;
            cpa16(base + dB, Bhg + (size_t)row * ldbw + kw, 16);
            cpa16(base + dB + BSTG * 4, Blg + (size_t)row * ldbw + kw, 16);
        }
    };

    const int niter = Ksub >> 5;
    issueStage(0, 0);
    asm volatile("cp.async.commit_group;" ::: "memory");
    issueStage(1, 1);
    asm volatile("cp.async.commit_group;" ::: "memory");

    int st = 0;
    for (int i = 0; i < niter; i++) {
        asm volatile("cp.async.wait_group 1;" ::: "memory");
        __syncthreads();
        const uint32_t so = (uint32_t)st * (STG_W * 4);
        #pragma unroll
        for (int ks = 0; ks < 2; ks++) {
            uint32_t ahh[2][4], alo[2][4];
            ldsm4(ahh[0], adA + so + ks * 32);
            ldsm4(ahh[1], adA + so + 16 * PPA * 4 + ks * 32);
            ldsm4(alo[0], adA + so + ASTG * 4 + ks * 32);
            ldsm4(alo[1], adA + so + ASTG * 4 + 16 * PPA * 4 + ks * 32);
            uint32_t bhh[2][4], blo[2][4];
            ldsm4(bhh[0], adB0 + so + ks * 32);
            ldsm4(bhh[1], adB1 + so + ks * 32);
            ldsm4(blo[0], adB0 + so + BSTG * 4 + ks * 32);
            ldsm4(blo[1], adB1 + so + BSTG * 4 + ks * 32);
            #pragma unroll
            for (int am = 0; am < 2; am++)
                #pragma unroll
                for (int an = 0; an < 4; an++) {
                    const int g = an >> 1, x = (an & 1) * 2;
                    mma16(acc[am][an], ahh[am], bhh[g][x], bhh[g][x + 1]);
                    mma16(acc[am][an], ahh[am], blo[g][x], blo[g][x + 1]);
                    mma16(acc[am][an], alo[am], bhh[g][x], bhh[g][x + 1]);
                }
        }
        if (i + 2 < niter) {
            int st2 = st + 2; if (st2 >= NSTG) st2 -= NSTG;
            issueStage(i + 2, st2);
        }
        asm volatile("cp.async.commit_group;" ::: "memory");
        st = (st + 1 == NSTG) ? 0 : st + 1;
    }

    int mode;   // 0=f32, 1=plane, 2=both, 3=qplanes
    if (outMode == 0)      mode = 0;
    else if (outMode == 1) mode = 1;
    else if (outMode == 2) mode = 2;
    else mode = (bn < 512) ? 3 : ((bn < 1024) ? 1 : 0);
    const int pShift = (outMode == 4 && mode == 1) ? 512 : 0;

    #pragma unroll
    for (int am = 0; am < 2; am++) {
        int row0 = bm + wm * 32 + am * 16 + g4;
        #pragma unroll
        for (int an = 0; an < 4; an++) {
            int col0 = bn + wn * 32 + an * 8 + 2 * l4;
            float v0 = acc[am][an][0], v1 = acc[am][an][1];
            float v2 = acc[am][an][2], v3 = acc[am][an][3];
            if (cbias && blockIdx.z == 0) {
                float b0 = cbias[col0], b1 = cbias[col0 + 1];
                v0 += b0; v1 += b1; v2 += b0; v3 += b1;
            }
            if (doRelu) {
                v0 = fmaxf(v0, 0.f); v1 = fmaxf(v1, 0.f);
                v2 = fmaxf(v2, 0.f); v3 = fmaxf(v3, 0.f);
            }
            if (mode == 3) {
                float bw0 = qwb[col0], bw1 = qwb[col0 + 1];
                float br0 = qrb[col0], br1 = qrb[col0 + 1];
                int colP = col0 >> 1;
                uint32_t hw, lw;
                if (row0 < M) {
                    split2(v0 + bw0, v1 + bw1, hw, lw);
                    QwH[(size_t)row0 * 256 + colP] = hw;
                    QwL[(size_t)row0 * 256 + colP] = lw;
                    split2(v0 + br0, v1 + br1, hw, lw);
                    QrH[(size_t)row0 * 256 + colP] = hw;
                    QrL[(size_t)row0 * 256 + colP] = lw;
                }
                if (row0 + 8 < M) {
                    split2(v2 + bw0, v3 + bw1, hw, lw);
                    QwH[(size_t)(row0 + 8) * 256 + colP] = hw;
                    QwL[(size_t)(row0 + 8) * 256 + colP] = lw;
                    split2(v2 + br0, v3 + br1, hw, lw);
                    QrH[(size_t)(row0 + 8) * 256 + colP] = hw;
                    QrL[(size_t)(row0 + 8) * 256 + colP] = lw;
                }
            } else {
                if (mode == 1 || mode == 2) {
                    uint32_t hw, lw;
                    int colP = (col0 - pShift) >> 1;
                    if (row0 < M) {
                        split2(v0, v1, hw, lw);
                        OutH[(size_t)row0 * ldcw + colP] = hw;
                        OutL[(size_t)row0 * ldcw + colP] = lw;
                    }
                    if (row0 + 8 < M) {
                        split2(v2, v3, hw, lw);
                        OutH[(size_t)(row0 + 8) * ldcw + colP] = hw;
                        OutL[(size_t)(row0 + 8) * ldcw + colP] = lw;
                    }
                }
                if (mode == 0 || mode == 2) {
                    if (row0 < M) {
                        C[(size_t)row0 * ldc + col0]     = v0;
                        C[(size_t)row0 * ldc + col0 + 1] = v1;
                    }
                    if (row0 + 8 < M) {
                        C[(size_t)(row0 + 8) * ldc + col0]     = v2;
                        C[(size_t)(row0 + 8) * ldc + col0 + 1] = v3;
                    }
                }
            }
        }
    }
}

// ---------------- fused flash-style relative attention ----------------
#define RPAD 68
#define RSLOT (64 * RPAD)
#define ATTN_WORDS (16 * BPLANE + 3 * RSLOT + 512)
#define ATTN_SMEM (ATTN_WORDS * 4)

__global__ __launch_bounds__(512, 1)
void fused_attn_kernel(const float* __restrict__ rbuf,
                       const uint32_t* __restrict__ qwGh, const uint32_t* __restrict__ qwGl,
                       const uint32_t* __restrict__ qrGh, const uint32_t* __restrict__ qrGl,
                       const uint32_t* __restrict__ kGh, const uint32_t* __restrict__ kGl,
                       const uint32_t* __restrict__ vGh, const uint32_t* __restrict__ vGl,
                       const uint32_t* __restrict__ rGh, const uint32_t* __restrict__ rGl) {
    extern __shared__ uint32_t smu[];
    uint32_t* Qwh = smu;
    uint32_t* Qwl = Qwh + BPLANE;
    uint32_t* Qrh = Qwl + BPLANE;
    uint32_t* Qrl = Qrh + BPLANE;
    uint32_t* Kh  = Qrl + BPLANE;
    uint32_t* Kl  = Kh  + 2 * BPLANE;
    uint32_t* Rh  = Kl  + 2 * BPLANE;
    uint32_t* Rl  = Rh  + BPLANE;
    uint32_t* Vth = Rl  + BPLANE;
    uint32_t* Vtl = Vth + 2 * BPLANE;
    uint32_t* Ph  = Vtl + 2 * BPLANE;
    uint32_t* Pl  = Ph  + BPLANE;
    float* Ring = (float*)(Pl + BPLANE);
    float* redm = Ring + 3 * RSLOT;
    float* reds = redm + 256;

    const int h = blockIdx.x;
    const int p = blockIdx.y;
    const int tid = threadIdx.x;
    const int lane = tid & 31, warp = tid >> 5;
    const int wm = warp & 3, wn = warp >> 2;
    const int g4 = lane >> 2, l4 = lane & 3;
    const int wr0 = wm * 16 + g4;
    const int colbase = wn * 16;

    const int aRow = lane & 15;
    const uint32_t aHiB = ((lane >> 4) & 1) * 16;
    const uint32_t aOff = (uint32_t)boff(wm * 16 + aRow) * 4 + aHiB;
    const uint32_t adQwh = sm_u32(Qwh) + aOff, adQwl = sm_u32(Qwl) + aOff;
    const uint32_t adQrh = sm_u32(Qrh) + aOff, adQrl = sm_u32(Qrl) + aOff;
    const uint32_t adPh  = sm_u32(Ph)  + aOff, adPl  = sm_u32(Pl)  + aOff;
    const int bRowN = ((lane >> 4) & 1) * 8 + (lane & 7);
    const uint32_t bHiB = ((lane >> 3) & 1) * 16;
    const uint32_t bO0 = (uint32_t)boff(colbase + bRowN) * 4 + bHiB;
    const uint32_t adKh = sm_u32(Kh) + bO0;
    const uint32_t adKl = sm_u32(Kl) + bO0;
    const uint32_t adRh = sm_u32(Rh) + bO0;
    const uint32_t adRl = sm_u32(Rl) + bO0;
    const uint32_t adVh = sm_u32(Vth) + bO0;
    const uint32_t adVl = sm_u32(Vtl) + bO0;

    uint4 pkh, pkl, pvh, pvl;
    const int prow = tid >> 3, pwq = (tid & 7) * 4;
    const size_t vtBase = ((size_t)h * 64 + prow) * VTKP;
    auto prefetchKV = [&](int j0) {
        int gj = j0 + prow;
        if (gj < TT) {
            pkh = *(const uint4*)(kGh + (size_t)gj * 256 + h * 32 + pwq);
            pkl = *(const uint4*)(kGl + (size_t)gj * 256 + h * 32 + pwq);
        } else {
            pkh = make_uint4(0, 0, 0, 0);
            pkl = make_uint4(0, 0, 0, 0);
        }
        pvh = *(const uint4*)(vGh + vtBase + (j0 >> 1) + pwq);
        pvl = *(const uint4*)(vGl + vtBase + (j0 >> 1) + pwq);
    };
    auto storeKV = [&](int buf) {
        int wi = buf * BPLANE + boff(prow) + pwq;
        *(uint4*)(Kh + wi) = pkh;
        *(uint4*)(Kl + wi) = pkl;
        *(uint4*)(Vth + wi) = pvh;
        *(uint4*)(Vtl + wi) = pvl;
    };
    auto loadRchunk = [&](int c) {
        int grow = c * 64 + prow;
        uint4 r0 = make_uint4(0, 0, 0, 0), r1 = r0;
        if (grow < TT) {
            r0 = *(const uint4*)(rGh + (size_t)grow * 256 + h * 32 + pwq);
            r1 = *(const uint4*)(rGl + (size_t)grow * 256 + h * 32 + pwq);
        }
        int wi = boff(prow) + pwq;
        *(uint4*)(Rh + wi) = r0;
        *(uint4*)(Rl + wi) = r1;
    };
    auto bdChunk = [&](int c) {
        float cacc[2][4];
        #pragma unroll
        for (int a = 0; a < 2; a++)
            cacc[a][0] = cacc[a][1] = cacc[a][2] = cacc[a][3] = 0.f;
        #pragma unroll
        for (int kc = 0; kc < 4; kc++) {
            uint32_t ah[4], al[4];
            ldsm4(ah, adQrh + kc * 32);
            ldsm4(al, adQrl + kc * 32);
            uint32_t bh[4], bl[4];
            ldsm4(bh, adRh + kc * 32);
            ldsm4(bl, adRl + kc * 32);
            #pragma unroll
            for (int an = 0; an < 2; an++) {
                const int x = an * 2;
                mma16(cacc[an], ah, bh[x], bh[x + 1]);
                mma16(cacc[an], ah, bl[x], bl[x + 1]);
                mma16(cacc[an], al, bh[x], bh[x + 1]);
            }
        }
        float* slot = Ring + (c % 3) * RSLOT;
        #pragma unroll
        for (int an = 0; an < 2; an++) {
            int col = colbase + an * 8 + 2 * l4;
            slot[wr0 * RPAD + col]           = cacc[an][0];
            slot[wr0 * RPAD + col + 1]       = cacc[an][1];
            slot[(wr0 + 8) * RPAD + col]     = cacc[an][2];
            slot[(wr0 + 8) * RPAD + col + 1] = cacc[an][3];
        }
    };

    int blist[2]; int nblk;
    if (p < 16) { blist[0] = p; blist[1] = 31 - p; nblk = 2; }
    else        { blist[0] = 32; nblk = 1; }

    for (int bi = 0; bi < nblk; bi++) {
        const int b = blist[bi];
        const int i0 = b * 64;
        const int validRows = min(64, TT - i0);
        const int njt = (b < 32) ? (b + 1) : 33;

        __syncthreads();
        // Q load from pre-biased planes: one uint4 per plane per thread
        {
            int gr = i0 + prow;
            uint4 a0 = make_uint4(0, 0, 0, 0), a1 = a0, a2 = a0, a3 = a0;
            if (gr < TT) {
                size_t base = (size_t)gr * 256 + h * 32 + pwq;
                a0 = *(const uint4*)(qwGh + base);
                a1 = *(const uint4*)(qwGl + base);
                a2 = *(const uint4*)(qrGh + base);
                a3 = *(const uint4*)(qrGl + base);
            }
            int wi = boff(prow) + pwq;
            *(uint4*)(Qwh + wi) = a0;
            *(uint4*)(Qwl + wi) = a1;
            *(uint4*)(Qrh + wi) = a2;
            *(uint4*)(Qrl + wi) = a3;
        }
        prefetchKV(0);
        storeKV(0);

        int nextChunk = (2016 - i0) / 64;
        if (nextChunk < 0) nextChunk = 0;

        const int chi0 = min(TT - 1, TT - 1 - i0 + 63) >> 6;
        while (nextChunk <= chi0) {
            __syncthreads();
            loadRchunk(nextChunk);
            __syncthreads();
            bdChunk(nextChunk);
            nextChunk++;
        }
        __syncthreads();

        float o[2][4];
        #pragma unroll
        for (int a = 0; a < 2; a++) { o[a][0] = o[a][1] = o[a][2] = o[a][3] = 0.f; }
        float mrow[2] = {-1e30f, -1e30f};
        float lrow[2] = {0.f, 0.f};

        for (int jt = 0; jt < njt; jt++) {
            const int j0 = jt * 64;
            const uint32_t kb = (uint32_t)(jt & 1) * (BPLANE * 4);

            // ---- AC MMA ----
            float s[2][4];
            #pragma unroll
            for (int a = 0; a < 2; a++)
                s[a][0] = s[a][1] = s[a][2] = s[a][3] = 0.f;
            #pragma unroll
            for (int kc = 0; kc < 4; kc++) {
                uint32_t ah[4], al[4];
                ldsm4(ah, adQwh + kc * 32);
                ldsm4(al, adQwl + kc * 32);
                uint32_t bh[4], bl[4];
                ldsm4(bh, adKh + kb + kc * 32);
                ldsm4(bl, adKl + kb + kc * 32);
                #pragma unroll
                for (int an = 0; an < 2; an++) {
                    const int x = an * 2;
                    mma16(s[an], ah, bh[x], bh[x + 1]);
                    mma16(s[an], ah, bl[x], bl[x + 1]);
                    mma16(s[an], al, bh[x], bh[x + 1]);
                }
            }

            // ---- combine with rel-shifted BD ----
            float tmax[2] = {-1e30f, -1e30f};
            if (jt < b) {
                const int jrB = TT - 1 - i0 + j0 + colbase + 2 * l4;
                #pragma unroll
                for (int an = 0; an < 2; an++) {
                    #pragma unroll
                    for (int e = 0; e < 4; e++) {
                        int rh = e >> 1;
                        int di = wr0 + rh * 8;
                        int jr = jrB - di + an * 8 + (e & 1);
                        float bd = Ring[((jr >> 6) % 3) * RSLOT + di * RPAD + (jr & 63)];
                        float v = (s[an][e] + bd) * 0.125f;
                        s[an][e] = v;
                        tmax[rh] = fmaxf(tmax[rh], v);
                    }
                }
            } else {
                #pragma unroll
                for (int an = 0; an < 2; an++) {
                    #pragma unroll
                    for (int e = 0; e < 4; e++) {
                        int rh = e >> 1;
                        int di = wr0 + rh * 8;
                        int dj = colbase + an * 8 + 2 * l4 + (e & 1);
                        int i = i0 + di, j = j0 + dj;
                        float v = -1e30f;
                        if (di < validRows && j < TT) {
                            int jmaxr = (i < NMTOK) ? (NMTOK - 1)
                                      : ((i >= TT - NMTOK) ? (TT - 1) : i);
                            if (j <= jmaxr) {
                                float bd;
                                if (j <= i) {
                                    int jr = TT - 1 - i + j;
                                    bd = Ring[((jr >> 6) % 3) * RSLOT + di * RPAD + (jr & 63)];
                                } else if (j == i + 1) {
                                    bd = 0.f;
                                } else {
                                    const float* rr = rbuf + (size_t)(j - i - 2) * DM + h * DH;
                                    float accd = 0.f;
                                    #pragma unroll 8
                                    for (int d2 = 0; d2 < 32; d2++) {
                                        uint32_t wh = Qrh[boff(di + 1) + d2];
                                        uint32_t wl = Qrl[boff(di + 1) + d2];
                                        __nv_bfloat162 h2 = *reinterpret_cast<__nv_bfloat162*>(&wh);
                                        __nv_bfloat162 l2 = *reinterpret_cast<__nv_bfloat162*>(&wl);
                                        float q0 = __bfloat162float(h2.x) + __bfloat162float(l2.x);
                                        float q1 = __bfloat162float(h2.y) + __bfloat162float(l2.y);
                                        accd += q0 * rr[2 * d2] + q1 * rr[2 * d2 + 1];
                                    }
                                    bd = accd;
                                }
                                v = (s[an][e] + bd) * 0.125f;
                            }
                        }
                        s[an][e] = v;
                        tmax[rh] = fmaxf(tmax[rh], v);
                    }
                }
            }
            #pragma unroll
            for (int rh = 0; rh < 2; rh++) {
                tmax[rh] = fmaxf(tmax[rh], __shfl_xor_sync(0xffffffffu, tmax[rh], 1));
                tmax[rh] = fmaxf(tmax[rh], __shfl_xor_sync(0xffffffffu, tmax[rh], 2));
            }
            if (l4 == 0) {
                redm[wn * 64 + wm * 16 + g4]     = tmax[0];
                redm[wn * 64 + wm * 16 + g4 + 8] = tmax[1];
            }

            bool needChunk = false;
            int cN = nextChunk;
            if (jt + 1 < njt) {
                prefetchKV((jt + 1) * 64);
                int chiN = min(TT - 1, TT - 1 - i0 + (jt + 1) * 64 + 63) >> 6;
                if (nextChunk <= chiN) { needChunk = true; loadRchunk(cN); }
            }
            __syncthreads();   // (c)

            float scl[2], lsum[2] = {0.f, 0.f};
            #pragma unroll
            for (int rh = 0; rh < 2; rh++) {
                int row = wm * 16 + g4 + rh * 8;
                float tm = fmaxf(fmaxf(redm[row], redm[64 + row]),
                                 fmaxf(redm[128 + row], redm[192 + row]));
                float mnew = fmaxf(mrow[rh], tm);
                scl[rh] = __expf(mrow[rh] - mnew);
                mrow[rh] = mnew;
            }
            #pragma unroll
            for (int an = 0; an < 2; an++) {
                #pragma unroll
                for (int e = 0; e < 4; e++) {
                    int rh = e >> 1;
                    float ev = __expf(s[an][e] - mrow[rh]);
                    s[an][e] = ev;
                    lsum[rh] += ev;
                }
            }
            #pragma unroll
            for (int rh = 0; rh < 2; rh++) {
                lsum[rh] += __shfl_xor_sync(0xffffffffu, lsum[rh], 1);
                lsum[rh] += __shfl_xor_sync(0xffffffffu, lsum[rh], 2);
            }
            if (l4 == 0) {
                reds[wn * 64 + wm * 16 + g4]     = lsum[0];
                reds[wn * 64 + wm * 16 + g4 + 8] = lsum[1];
            }
            #pragma unroll
            for (int an = 0; an < 2; an++) {
                int cp = (colbase >> 1) + an * 4 + l4;
                uint32_t hw, lw;
                split2(s[an][0], s[an][1], hw, lw);
                Ph[boff(wr0) + cp] = hw; Pl[boff(wr0) + cp] = lw;
                split2(s[an][2], s[an][3], hw, lw);
                Ph[boff(wr0 + 8) + cp] = hw; Pl[boff(wr0 + 8) + cp] = lw;
            }
            if (jt + 1 < njt) storeKV((jt + 1) & 1);
            if (needChunk) { bdChunk(cN); nextChunk++; }
            __syncthreads();   // (d)

            #pragma unroll
            for (int rh = 0; rh < 2; rh++) {
                int row = wm * 16 + g4 + rh * 8;
                lrow[rh] = lrow[rh] * scl[rh] +
                           reds[row] + reds[64 + row] + reds[128 + row] + reds[192 + row];
            }
            #pragma unroll
            for (int an = 0; an < 2; an++) {
                o[an][0] *= scl[0]; o[an][1] *= scl[0];
                o[an][2] *= scl[1]; o[an][3] *= scl[1];
            }

            // ---- PV MMA ----
            #pragma unroll
            for (int kc = 0; kc < 4; kc++) {
                uint32_t ah[4], al[4];
                ldsm4(ah, adPh + kc * 32);
                ldsm4(al, adPl + kc * 32);
                uint32_t bh[4], bl[4];
                ldsm4(bh, adVh + kb + kc * 32);
                ldsm4(bl, adVl + kb + kc * 32);
                #pragma unroll
                for (int an = 0; an < 2; an++) {
                    const int x = an * 2;
                    mma16(o[an], ah, bh[x], bh[x + 1]);
                    mma16(o[an], ah, bl[x], bl[x + 1]);
                    mma16(o[an], al, bh[x], bh[x + 1]);
                }
            }
        } // j-tiles

        float inv0 = 1.f / lrow[0], inv1 = 1.f / lrow[1];
        #pragma unroll
        for (int an = 0; an < 2; an++) {
            int colw = (h * DH + colbase + an * 8 + 2 * l4) >> 1;
            int r0 = i0 + wr0;
            uint32_t hw, lw;
            if (wr0 < validRows) {
                split2(o[an][0] * inv0, o[an][1] * inv0, hw, lw);
                avPh[(size_t)r0 * 256 + colw] = hw;
                avPl[(size_t)r0 * 256 + colw] = lw;
            }
            if (wr0 + 8 < validRows) {
                split2(o[an][2] * inv1, o[an][3] * inv1, hw, lw);
                avPh[(size_t)(r0 + 8) * 256 + colw] = hw;
                avPl[(size_t)(r0 + 8) * 256 + colw] = lw;
            }
        }
    } // blocks
}

// ---------------- residual add + layernorm (1-barrier, emits w planes) ----------------
__global__ void add_ln_kernel(float* __restrict__ w, const float* __restrict__ delta,
                              const float* __restrict__ delta2,
                              const float* __restrict__ gam, const float* __restrict__ bta) {
    int row = blockIdx.x;
    int tid = threadIdx.x;
    int c = 2 * tid;
    __shared__ float s1m[8], s2m[8];
    float x0 = w[row * DM + c]     + delta[row * DM + c];
    float x1 = w[row * DM + c + 1] + delta[row * DM + c + 1];
    if (delta2) {
        x0 += delta2[row * DM + c];
        x1 += delta2[row * DM + c + 1];
    }
    float s1 = x0 + x1;
    float s2 = x0 * x0 + x1 * x1;
    #pragma unroll
    for (int o = 16; o > 0; o >>= 1) {
        s1 += __shfl_xor_sync(0xffffffffu, s1, o);
        s2 += __shfl_xor_sync(0xffffffffu, s2, o);
    }
    if ((tid & 31) == 0) { s1m[tid >> 5] = s1; s2m[tid >> 5] = s2; }
    __syncthreads();
    float t1 = 0.f, t2 = 0.f;
    #pragma unroll
    for (int i = 0; i < 8; i++) { t1 += s1m[i]; t2 += s2m[i]; }
    float mean = t1 * (1.f / DM);
    float var = t2 * (1.f / DM) - mean * mean;
    float inv = 1.f / sqrtf(var + 1e-5f);
    float y0 = (x0 - mean) * inv * gam[c]     + bta[c];
    float y1 = (x1 - mean) * inv * gam[c + 1] + bta[c + 1];
    w[row * DM + c]     = y0;
    w[row * DM + c + 1] = y1;
    uint32_t hw, lw;
    split2(y0, y1, hw, lw);
    wPh[row * 256 + tid] = hw;
    wPl[row * 256 + tid] = lw;
}

__global__ void copy_out_kernel(float* __restrict__ out) {
    int idx = blockIdx.x * blockDim.x + threadIdx.x;
    if (idx < TT * DM) out[idx] = g_w[idx];
}

// ---------------- launcher ----------------
extern "C" void kernel_launch(void* const* d_in, const int* in_sizes, int n_in,
                              void* d_out, int out_size) {
    (void)in_sizes; (void)n_in; (void)out_size;
    const float* word_emb = (const float*)d_in[0];
    const float* mem_tok  = (const float*)d_in[1];
    const float* Wqkv     = (const float*)d_in[2];
    const float* Wr       = (const float*)d_in[3];
    const float* Wo       = (const float*)d_in[4];
    const float* ln1s     = (const float*)d_in[5];
    const float* ln1b     = (const float*)d_in[6];
    const float* W1       = (const float*)d_in[7];
    const float* b1       = (const float*)d_in[8];
    const float* W2       = (const float*)d_in[9];
    const float* b2       = (const float*)d_in[10];
    const float* ln2s     = (const float*)d_in[11];
    const float* ln2b     = (const float*)d_in[12];
    const float* rwb      = (const float*)d_in[13];
    const float* rrb      = (const float*)d_in[14];

    float *g_w_p, *g_hd_p, *g_r4_p, *g_tmp_p, *g_tmp2_p;
    cudaGetSymbolAddress((void**)&g_w_p,    g_w);
    cudaGetSymbolAddress((void**)&g_hd_p,   g_heads);
    cudaGetSymbolAddress((void**)&g_r4_p,   g_r4);
    cudaGetSymbolAddress((void**)&g_tmp_p,  g_tmp);
    cudaGetSymbolAddress((void**)&g_tmp2_p, g_tmp2);
    uint32_t *wPh_p, *wPl_p, *posPh_p, *posPl_p, *avPh_p, *avPl_p, *ff1Ph_p, *ff1Pl_p;
    uint32_t *kPh_p, *kPl_p, *qwPh_p, *qwPl_p, *qrPh_p, *qrPl_p, *rPh4_p, *rPl4_p, *vtPh_p, *vtPl_p;
    cudaGetSymbolAddress((void**)&wPh_p,   wPh);
    cudaGetSymbolAddress((void**)&wPl_p,   wPl);
    cudaGetSymbolAddress((void**)&posPh_p, posPh);
    cudaGetSymbolAddress((void**)&posPl_p, posPl);
    cudaGetSymbolAddress((void**)&avPh_p,  avPh);
    cudaGetSymbolAddress((void**)&avPl_p,  avPl);
    cudaGetSymbolAddress((void**)&ff1Ph_p, ff1Ph);
    cudaGetSymbolAddress((void**)&ff1Pl_p, ff1Pl);
    cudaGetSymbolAddress((void**)&kPh_p,   kPh);
    cudaGetSymbolAddress((void**)&kPl_p,   kPl);
    cudaGetSymbolAddress((void**)&qwPh_p,  qwPh);
    cudaGetSymbolAddress((void**)&qwPl_p,  qwPl);
    cudaGetSymbolAddress((void**)&qrPh_p,  qrPh);
    cudaGetSymbolAddress((void**)&qrPl_p,  qrPl);
    cudaGetSymbolAddress((void**)&rPh4_p,  rPh4);
    cudaGetSymbolAddress((void**)&rPl4_p,  rPl4);
    cudaGetSymbolAddress((void**)&vtPh_p,  vtPh);
    cudaGetSymbolAddress((void**)&vtPl_p,  vtPl);
    uint32_t *qkvPh_p, *qkvPl_p, *wrPh_p, *wrPl_p, *woPh_p, *woPl_p, *w1Ph_p, *w1Pl_p, *w2Ph_p, *w2Pl_p;
    cudaGetSymbolAddress((void**)&qkvPh_p, qkvPh);
    cudaGetSymbolAddress((void**)&qkvPl_p, qkvPl);
    cudaGetSymbolAddress((void**)&wrPh_p,  wrPh);
    cudaGetSymbolAddress((void**)&wrPl_p,  wrPl);
    cudaGetSymbolAddress((void**)&woPh_p,  woPh);
    cudaGetSymbolAddress((void**)&woPl_p,  woPl);
    cudaGetSymbolAddress((void**)&w1Ph_p,  w1Ph);
    cudaGetSymbolAddress((void**)&w1Pl_p,  w1Pl);
    cudaGetSymbolAddress((void**)&w2Ph_p,  w2Ph);
    cudaGetSymbolAddress((void**)&w2Pl_p,  w2Pl);

    cudaFuncSetAttribute(fused_attn_kernel,
                         cudaFuncAttributeMaxDynamicSharedMemorySize, ATTN_SMEM);
    cudaFuncSetAttribute(mma_gemm,
                         cudaFuncAttributeMaxDynamicSharedMemorySize, GEMM_SMEM);

    // fused weight conversion (single launch)
    convert_all<<<6656, 256>>>(Wqkv, qkvPh_p, qkvPl_p,
                               Wr, wrPh_p, wrPl_p,
                               Wo, woPh_p, woPl_p,
                               W1, w1Ph_p, w1Pl_p,
                               W2, w2Ph_p, w2Pl_p);

    build_w_kernel<<<(TT * 256 + 255) / 256, 256>>>(word_emb, mem_tok);
    build_pos_kernel<<<(TT * 256 + 255) / 256, 256>>>();

    const int MB = (TT + 127) / 128;   // 17

    // All 4 layers' r-projections in one batched launch
    mma_gemm<<<dim3(8, MB, NLAY), 256, GEMM_SMEM>>>(
        posPh_p, posPl_p, 256,
        wrPh_p, wrPl_p, 256,
        g_r4_p, nullptr, DM,
        rPh4_p, rPl4_p, 256,
        nullptr, 0, 2, TT, DM, DM,
        1, (size_t)512 * 256, (size_t)TT * DM, (size_t)TT * 256,
        nullptr, nullptr, nullptr, nullptr, nullptr, nullptr);

    for (int l = 0; l < NLAY; l++) {
        // QKV: q -> biased qw/qr planes, k -> planes, v -> fp32
        mma_gemm<<<dim3(24, MB, 1), 256, GEMM_SMEM>>>(
            wPh_p, wPl_p, 256,
            qkvPh_p + (size_t)l * 1536 * 256, qkvPl_p + (size_t)l * 1536 * 256, 256,
            g_hd_p, g_hd_p, 3 * DM,
            kPh_p, kPl_p, 256,
            nullptr, 0, 4, TT, 3 * DM, DM,
            0, 0, 0, 0,
            rwb, rrb, qwPh_p, qwPl_p, qrPh_p, qrPl_p);
        convert_vt<<<dim3(33, NH), 256>>>(g_hd_p, vtPh_p, vtPl_p);

        fused_attn_kernel<<<dim3(NH, 17), 512, ATTN_SMEM>>>(
            g_r4_p + (size_t)l * TT * DM,
            qwPh_p, qwPl_p, qrPh_p, qrPl_p,
            kPh_p, kPl_p, vtPh_p, vtPl_p,
            rPh4_p + (size_t)l * TT * 256, rPl4_p + (size_t)l * TT * 256);

        mma_gemm<<<dim3(8, MB, 2), 256, GEMM_SMEM>>>(
            avPh_p, avPl_p, 256,
            woPh_p + (size_t)l * 512 * 256, woPl_p + (size_t)l * 512 * 256, 256,
            g_tmp_p, g_tmp2_p, DM,
            nullptr, nullptr, 0,
            nullptr, 0, 0, TT, DM, DM / 2,
            0, 0, 0, 0,
            nullptr, nullptr, nullptr, nullptr, nullptr, nullptr);
        add_ln_kernel<<<TT, 256>>>(g_w_p, g_tmp_p, g_tmp2_p, ln1s + l * DM, ln1b + l * DM);
        mma_gemm<<<dim3(32, MB, 1), 256, GEMM_SMEM>>>(
            wPh_p, wPl_p, 256,
            w1Ph_p + (size_t)l * 2048 * 256, w1Pl_p + (size_t)l * 2048 * 256, 256,
            nullptr, nullptr, 0,
            ff1Ph_p, ff1Pl_p, DI / 2,
            b1 + (size_t)l * DI, 1, 1, TT, DI, DM,
            0, 0, 0, 0,
            nullptr, nullptr, nullptr, nullptr, nullptr, nullptr);
        mma_gemm<<<dim3(8, MB, 2), 256, GEMM_SMEM>>>(
            ff1Ph_p, ff1Pl_p, 1024,
            w2Ph_p + (size_t)l * 512 * 1024, w2Pl_p + (size_t)l * 512 * 1024, 1024,
            g_tmp_p, g_tmp2_p, DM,
            nullptr, nullptr, 0,
            b2 + (size_t)l * DM, 0, 0, TT, DM, DI / 2,
            0, 0, 0, 0,
            nullptr, nullptr, nullptr, nullptr, nullptr, nullptr);
        add_ln_kernel<<<TT, 256>>>(g_w_p, g_tmp_p, g_tmp2_p, ln2s + l * DM, ln2b + l * DM);
    }

    copy_out_kernel<<<(TT * DM + 255) / 256, 256>>>((float*)d_out);
}